// round 1
// baseline (speedup 1.0000x reference)
#include <cuda_runtime.h>
#include <cuda_bf16.h>
#include <math.h>

// Problem constants
#define BB 2
#define SS 2048
#define DD 1024
#define HH 16
#define DH 64
#define MM (BB * SS)   // 4096 rows

// -------------------- scratch (allocation-free rule: __device__ globals) ----
__device__ float g_Q[MM * DD];   // stored head-split: [B*H][S][DH]
__device__ float g_K[MM * DD];
__device__ float g_V[MM * DD];
__device__ float g_O[MM * DD];   // attention output, head-split

// ============================================================================
// GEMM 1: projection.  Out[b,h,s,dh] = (X @ W + bias) head-split store.
// X: [4096,1024] natural.  W: [1024,1024] (k-major rows).  128x128x16 tiles.
// ============================================================================
__global__ __launch_bounds__(256)
void gemm_proj(const float* __restrict__ X, const float* __restrict__ W,
               const float* __restrict__ bias, float* __restrict__ Out)
{
    __shared__ float As[16][132];   // transposed A: As[k][m], pad keeps 16B align
    __shared__ float Bs[16][128];

    const int t    = threadIdx.x;
    const int trow = t >> 4;    // 0..15 -> 8 rows
    const int tcol = t & 15;    // 0..15 -> 8 cols
    const int m0   = blockIdx.y * 128;
    const int n0   = blockIdx.x * 128;

    float acc[8][8];
#pragma unroll
    for (int i = 0; i < 8; i++)
#pragma unroll
        for (int j = 0; j < 8; j++) acc[i][j] = 0.f;

    for (int k0 = 0; k0 < DD; k0 += 16) {
        // A tile 128x16 -> transposed smem
#pragma unroll
        for (int i = 0; i < 2; i++) {
            int f   = t + i * 256;        // 0..511 float4s
            int row = f >> 2;
            int kc  = (f & 3) * 4;
            float4 v = *(const float4*)&X[(size_t)(m0 + row) * DD + k0 + kc];
            As[kc + 0][row] = v.x; As[kc + 1][row] = v.y;
            As[kc + 2][row] = v.z; As[kc + 3][row] = v.w;
        }
        // B tile 16x128
#pragma unroll
        for (int i = 0; i < 2; i++) {
            int f  = t + i * 256;
            int kr = f >> 5;
            int nc = (f & 31) * 4;
            *(float4*)&Bs[kr][nc] =
                *(const float4*)&W[(size_t)(k0 + kr) * DD + n0 + nc];
        }
        __syncthreads();
#pragma unroll
        for (int kk = 0; kk < 16; kk++) {
            float a[8], b[8];
            *(float4*)&a[0] = *(const float4*)&As[kk][trow * 8];
            *(float4*)&a[4] = *(const float4*)&As[kk][trow * 8 + 4];
            *(float4*)&b[0] = *(const float4*)&Bs[kk][tcol * 8];
            *(float4*)&b[4] = *(const float4*)&Bs[kk][tcol * 8 + 4];
#pragma unroll
            for (int i = 0; i < 8; i++)
#pragma unroll
                for (int j = 0; j < 8; j++) acc[i][j] += a[i] * b[j];
        }
        __syncthreads();
    }

    // store head-split: row m -> (b, s); col n -> (h, dh)
#pragma unroll
    for (int i = 0; i < 8; i++) {
        int m = m0 + trow * 8 + i;
        int b = m >> 11, s = m & 2047;
#pragma unroll
        for (int j = 0; j < 8; j++) {
            int n = n0 + tcol * 8 + j;
            int h = n >> 6, dh = n & 63;
            Out[((size_t)((b * HH + h) * SS + s)) * DH + dh] = acc[i][j] + bias[n];
        }
    }
}

// ============================================================================
// GEMM 2: output projection.  A gathered from head-split g_O, natural store.
// ============================================================================
__global__ __launch_bounds__(256)
void gemm_out(const float* __restrict__ Ain, const float* __restrict__ W,
              const float* __restrict__ bias, float* __restrict__ Out)
{
    __shared__ float As[16][132];
    __shared__ float Bs[16][128];

    const int t    = threadIdx.x;
    const int trow = t >> 4;
    const int tcol = t & 15;
    const int m0   = blockIdx.y * 128;
    const int n0   = blockIdx.x * 128;

    float acc[8][8];
#pragma unroll
    for (int i = 0; i < 8; i++)
#pragma unroll
        for (int j = 0; j < 8; j++) acc[i][j] = 0.f;

    for (int k0 = 0; k0 < DD; k0 += 16) {
#pragma unroll
        for (int i = 0; i < 2; i++) {
            int f   = t + i * 256;
            int row = f >> 2;
            int kc  = (f & 3) * 4;
            int m   = m0 + row;
            int b   = m >> 11, s = m & 2047;
            int k   = k0 + kc;
            int h   = k >> 6, dh = k & 63;   // 16-chunk stays inside one head
            float4 v = *(const float4*)
                &Ain[((size_t)((b * HH + h) * SS + s)) * DH + dh];
            As[kc + 0][row] = v.x; As[kc + 1][row] = v.y;
            As[kc + 2][row] = v.z; As[kc + 3][row] = v.w;
        }
#pragma unroll
        for (int i = 0; i < 2; i++) {
            int f  = t + i * 256;
            int kr = f >> 5;
            int nc = (f & 31) * 4;
            *(float4*)&Bs[kr][nc] =
                *(const float4*)&W[(size_t)(k0 + kr) * DD + n0 + nc];
        }
        __syncthreads();
#pragma unroll
        for (int kk = 0; kk < 16; kk++) {
            float a[8], b[8];
            *(float4*)&a[0] = *(const float4*)&As[kk][trow * 8];
            *(float4*)&a[4] = *(const float4*)&As[kk][trow * 8 + 4];
            *(float4*)&b[0] = *(const float4*)&Bs[kk][tcol * 8];
            *(float4*)&b[4] = *(const float4*)&Bs[kk][tcol * 8 + 4];
#pragma unroll
            for (int i = 0; i < 8; i++)
#pragma unroll
                for (int j = 0; j < 8; j++) acc[i][j] += a[i] * b[j];
        }
        __syncthreads();
    }

#pragma unroll
    for (int i = 0; i < 8; i++) {
        int m = m0 + trow * 8 + i;
#pragma unroll
        for (int j = 0; j < 8; j++) {
            int n = n0 + tcol * 8 + j;
            Out[(size_t)m * DD + n] = acc[i][j] + bias[n];
        }
    }
}

// ============================================================================
// Flash attention, fp32.  64-query x 64-key tiles, Dh = 64.
// grid = (S/64, B*H); 256 threads; thread (ty,tx) owns 4 rows x 4 out-dims.
// smem: Qs^T[64][68] + Ks^T[64][68] + Vs[64][64] + Ps[64][64] = 67584 B
// ============================================================================
#define QK_PAD 68

__global__ __launch_bounds__(256)
void attn_kernel(const float* __restrict__ Qg, const float* __restrict__ Kg,
                 const float* __restrict__ Vg, float* __restrict__ Og)
{
    extern __shared__ float sm[];
    float* Qs = sm;                         // [64][QK_PAD] transposed (k-major)
    float* Ks = Qs + 64 * QK_PAD;           // [64][QK_PAD] transposed
    float* Vs = Ks + 64 * QK_PAD;           // [64][64] natural
    float* Ps = Vs + 64 * 64;               // [64][64]

    const int t  = threadIdx.x;
    const int ty = t >> 4;     // 0..15 -> 4 query rows
    const int tx = t & 15;     // 0..15 -> 4 cols / out-dims
    const int bh = blockIdx.y;
    const int q0 = blockIdx.x * 64;

    const float* Qb = Qg + (size_t)bh * SS * DH;
    const float* Kb = Kg + (size_t)bh * SS * DH;
    const float* Vb = Vg + (size_t)bh * SS * DH;

    // load Q tile transposed, pre-scaled by 1/sqrt(Dh)
#pragma unroll
    for (int i = 0; i < 4; i++) {
        int f  = t + i * 256;        // 0..1023 float4s
        int r  = f >> 4;             // 64 floats = 16 float4 per row
        int kc = (f & 15) * 4;
        float4 v = *(const float4*)&Qb[(size_t)(q0 + r) * DH + kc];
        Qs[(kc + 0) * QK_PAD + r] = v.x * 0.125f;
        Qs[(kc + 1) * QK_PAD + r] = v.y * 0.125f;
        Qs[(kc + 2) * QK_PAD + r] = v.z * 0.125f;
        Qs[(kc + 3) * QK_PAD + r] = v.w * 0.125f;
    }

    float m_i[4], l_i[4], acc[4][4];
#pragma unroll
    for (int i = 0; i < 4; i++) {
        m_i[i] = -INFINITY; l_i[i] = 0.f;
#pragma unroll
        for (int j = 0; j < 4; j++) acc[i][j] = 0.f;
    }

    for (int kt = 0; kt < SS; kt += 64) {
        __syncthreads();   // prev PV done reading Ks/Vs (also covers Q load)
        // load K tile transposed + V tile natural
#pragma unroll
        for (int i = 0; i < 4; i++) {
            int f  = t + i * 256;
            int r  = f >> 4;
            int kc = (f & 15) * 4;
            float4 kv = *(const float4*)&Kb[(size_t)(kt + r) * DH + kc];
            Ks[(kc + 0) * QK_PAD + r] = kv.x;
            Ks[(kc + 1) * QK_PAD + r] = kv.y;
            Ks[(kc + 2) * QK_PAD + r] = kv.z;
            Ks[(kc + 3) * QK_PAD + r] = kv.w;
            *(float4*)&Vs[r * 64 + kc] =
                *(const float4*)&Vb[(size_t)(kt + r) * DH + kc];
        }
        __syncthreads();

        // scores: s[i][j] = sum_k Q^T[k][ty*4+i] * K^T[k][tx*4+j]
        float s[4][4];
#pragma unroll
        for (int i = 0; i < 4; i++)
#pragma unroll
            for (int j = 0; j < 4; j++) s[i][j] = 0.f;

        for (int k = 0; k < 64; k++) {
            float4 qa = *(const float4*)&Qs[k * QK_PAD + ty * 4];
            float4 kb = *(const float4*)&Ks[k * QK_PAD + tx * 4];
            float qv[4] = {qa.x, qa.y, qa.z, qa.w};
            float kv[4] = {kb.x, kb.y, kb.z, kb.w};
#pragma unroll
            for (int i = 0; i < 4; i++)
#pragma unroll
                for (int j = 0; j < 4; j++) s[i][j] += qv[i] * kv[j];
        }

        // online softmax per row (reduce across the 16 tx lanes, width 16)
#pragma unroll
        for (int i = 0; i < 4; i++) {
            float mx = fmaxf(fmaxf(s[i][0], s[i][1]), fmaxf(s[i][2], s[i][3]));
#pragma unroll
            for (int o = 8; o >= 1; o >>= 1)
                mx = fmaxf(mx, __shfl_xor_sync(0xffffffffu, mx, o));
            float mn   = fmaxf(m_i[i], mx);
            float corr = __expf(m_i[i] - mn);
            m_i[i] = mn;
            float rs = 0.f;
#pragma unroll
            for (int j = 0; j < 4; j++) {
                s[i][j] = __expf(s[i][j] - mn);
                rs += s[i][j];
            }
#pragma unroll
            for (int o = 8; o >= 1; o >>= 1)
                rs += __shfl_xor_sync(0xffffffffu, rs, o);
            l_i[i] = l_i[i] * corr + rs;
#pragma unroll
            for (int j = 0; j < 4; j++) acc[i][j] *= corr;
            *(float4*)&Ps[(ty * 4 + i) * 64 + tx * 4] =
                make_float4(s[i][0], s[i][1], s[i][2], s[i][3]);
        }
        __syncthreads();

        // PV: acc[i][:] += sum_c Ps[r][c] * Vs[c][tx*4..]
        for (int c = 0; c < 64; c++) {
            float4 v4 = *(const float4*)&Vs[c * 64 + tx * 4];
#pragma unroll
            for (int i = 0; i < 4; i++) {
                float p = Ps[(ty * 4 + i) * 64 + c];
                acc[i][0] += p * v4.x; acc[i][1] += p * v4.y;
                acc[i][2] += p * v4.z; acc[i][3] += p * v4.w;
            }
        }
    }

    // epilogue
    float* Ob = Og + (size_t)bh * SS * DH;
#pragma unroll
    for (int i = 0; i < 4; i++) {
        float inv = 1.f / l_i[i];
        *(float4*)&Ob[(size_t)(q0 + ty * 4 + i) * DH + tx * 4] =
            make_float4(acc[i][0] * inv, acc[i][1] * inv,
                        acc[i][2] * inv, acc[i][3] * inv);
    }
}

// ============================================================================
// launch
// ============================================================================
extern "C" void kernel_launch(void* const* d_in, const int* in_sizes, int n_in,
                              void* d_out, int out_size)
{
    const float* q   = (const float*)d_in[0];
    const float* k   = (const float*)d_in[1];
    const float* v   = (const float*)d_in[2];
    const float* w_q = (const float*)d_in[3];
    const float* b_q = (const float*)d_in[4];
    const float* w_k = (const float*)d_in[5];
    const float* b_k = (const float*)d_in[6];
    const float* w_v = (const float*)d_in[7];
    const float* b_v = (const float*)d_in[8];
    const float* w_o = (const float*)d_in[9];
    const float* b_o = (const float*)d_in[10];
    float* out = (float*)d_out;

    float *pQ, *pK, *pV, *pO;
    cudaGetSymbolAddress((void**)&pQ, g_Q);
    cudaGetSymbolAddress((void**)&pK, g_K);
    cudaGetSymbolAddress((void**)&pV, g_V);
    cudaGetSymbolAddress((void**)&pO, g_O);

    static int smem_set = 0;
    const int attn_smem = (64 * QK_PAD * 2 + 64 * 64 * 2) * sizeof(float);
    if (!smem_set) {
        cudaFuncSetAttribute(attn_kernel,
                             cudaFuncAttributeMaxDynamicSharedMemorySize,
                             attn_smem);
        smem_set = 1;
    }

    dim3 gg(DD / 128, MM / 128);   // (8, 32)
    gemm_proj<<<gg, 256>>>(q, w_q, b_q, pQ);
    gemm_proj<<<gg, 256>>>(k, w_k, b_k, pK);
    gemm_proj<<<gg, 256>>>(v, w_v, b_v, pV);

    dim3 ga(SS / 64, BB * HH);     // (32, 32)
    attn_kernel<<<ga, 256, attn_smem>>>(pQ, pK, pV, pO);

    gemm_out<<<gg, 256>>>(pO, w_o, b_o, out);
}

// round 3
// speedup vs baseline: 1.3369x; 1.3369x over previous
#include <cuda_runtime.h>
#include <cuda_bf16.h>
#include <math.h>
#include <stdint.h>

// Problem constants
#define BB 2
#define SS 2048
#define DD 1024
#define HH 16
#define DH 64
#define MM (BB * SS)   // 4096 rows

// -------------------- scratch (allocation-free rule: __device__ globals) ----
__device__ float g_Q[MM * DD];   // head-split: [B*H][S][DH]
__device__ float g_K[MM * DD];
__device__ float g_V[MM * DD];
__device__ float g_O[MM * DD];   // attention output, head-split
__device__ __nv_bfloat16 g_Ah[MM * DD];   // A operand hi  [M][K]
__device__ __nv_bfloat16 g_Al[MM * DD];   // A operand lo
__device__ __nv_bfloat16 g_Bh[DD * DD];   // B operand hi  [N][K] (W transposed)
__device__ __nv_bfloat16 g_Bl[DD * DD];   // B operand lo

// ============================================================================
// helpers
// ============================================================================
__device__ __forceinline__ uint32_t smem_u32(const void* p) {
    uint32_t a;
    asm("{ .reg .u64 t; cvta.to.shared.u64 t, %1; cvt.u32.u64 %0, t; }"
        : "=r"(a) : "l"(p));
    return a;
}

#define LDSM4(r0, r1, r2, r3, addr)                                            \
    asm volatile("ldmatrix.sync.aligned.m8n8.x4.shared.b16 {%0,%1,%2,%3}, [%4];" \
                 : "=r"(r0), "=r"(r1), "=r"(r2), "=r"(r3) : "r"(addr))

#define MMA16816(d, a, b0, b1)                                                 \
    asm volatile("mma.sync.aligned.m16n8k16.row.col.f32.bf16.bf16.f32 "        \
                 "{%0,%1,%2,%3}, {%4,%5,%6,%7}, {%8,%9}, {%0,%1,%2,%3};"       \
                 : "+f"((d)[0]), "+f"((d)[1]), "+f"((d)[2]), "+f"((d)[3])      \
                 : "r"((a)[0]), "r"((a)[1]), "r"((a)[2]), "r"((a)[3]),         \
                   "r"(b0), "r"(b1))

#define CP_ASYNC16(dst, src)                                                   \
    asm volatile("cp.async.cg.shared.global [%0], [%1], 16;" :: "r"(dst), "l"(src))
#define CP_COMMIT()  asm volatile("cp.async.commit_group;" ::: "memory")
#define CP_WAIT1()   asm volatile("cp.async.wait_group 1;" ::: "memory")
#define CP_WAIT0()   asm volatile("cp.async.wait_group 0;" ::: "memory")

// ============================================================================
// bf16 split conversion kernels
// ============================================================================
__global__ __launch_bounds__(256)
void conv_split(const float4* __restrict__ src, __nv_bfloat16* __restrict__ hi,
                __nv_bfloat16* __restrict__ lo, int n4)
{
    int i = blockIdx.x * 256 + threadIdx.x;
    if (i >= n4) return;
    float4 v = src[i];
    float vs[4] = {v.x, v.y, v.z, v.w};
    __nv_bfloat162* h2 = (__nv_bfloat162*)hi;
    __nv_bfloat162* l2 = (__nv_bfloat162*)lo;
    __nv_bfloat16 h[4], l[4];
#pragma unroll
    for (int j = 0; j < 4; j++) {
        h[j] = __float2bfloat16_rn(vs[j]);
        l[j] = __float2bfloat16_rn(vs[j] - __bfloat162float(h[j]));
    }
    h2[i * 2 + 0] = __nv_bfloat162(h[0], h[1]);
    h2[i * 2 + 1] = __nv_bfloat162(h[2], h[3]);
    l2[i * 2 + 0] = __nv_bfloat162(l[0], l[1]);
    l2[i * 2 + 1] = __nv_bfloat162(l[2], l[3]);
}

// W [K][N] row-major -> Bt[n][k] hi/lo (transpose + split)
__global__ __launch_bounds__(256)
void conv_wT(const float* __restrict__ W, __nv_bfloat16* __restrict__ hi,
             __nv_bfloat16* __restrict__ lo)
{
    __shared__ float t[32][33];
    int n0 = blockIdx.x * 32, k0 = blockIdx.y * 32;
    int tx = threadIdx.x, ty = threadIdx.y;   // block (32,8)
#pragma unroll
    for (int i = 0; i < 32; i += 8)
        t[ty + i][tx] = W[(size_t)(k0 + ty + i) * DD + n0 + tx];
    __syncthreads();
#pragma unroll
    for (int i = 0; i < 32; i += 8) {
        float v = t[tx][ty + i];               // W[k0+tx][n0+ty+i]
        __nv_bfloat16 h = __float2bfloat16_rn(v);
        size_t o = (size_t)(n0 + ty + i) * DD + k0 + tx;
        hi[o] = h;
        lo[o] = __float2bfloat16_rn(v - __bfloat162float(h));
    }
}

// gather head-split O -> row-major [M][K] bf16 hi/lo
__global__ __launch_bounds__(256)
void conv_gather(const float* __restrict__ O, __nv_bfloat16* __restrict__ hi,
                 __nv_bfloat16* __restrict__ lo)
{
    int i = blockIdx.x * 256 + threadIdx.x;   // over MM*DD/4
    int e = i * 4;
    int m = e >> 10, k = e & 1023;
    int b = m >> 11, s = m & 2047, h = k >> 6, dh = k & 63;
    float4 v = *(const float4*)&O[(((size_t)(b * HH + h) * SS) + s) * DH + dh];
    float vs[4] = {v.x, v.y, v.z, v.w};
    __nv_bfloat162* h2 = (__nv_bfloat162*)hi;
    __nv_bfloat162* l2 = (__nv_bfloat162*)lo;
    __nv_bfloat16 hh[4], ll[4];
#pragma unroll
    for (int j = 0; j < 4; j++) {
        hh[j] = __float2bfloat16_rn(vs[j]);
        ll[j] = __float2bfloat16_rn(vs[j] - __bfloat162float(hh[j]));
    }
    h2[i * 2 + 0] = __nv_bfloat162(hh[0], hh[1]);
    h2[i * 2 + 1] = __nv_bfloat162(hh[2], hh[3]);
    l2[i * 2 + 0] = __nv_bfloat162(ll[0], ll[1]);
    l2[i * 2 + 1] = __nv_bfloat162(ll[2], ll[3]);
}

// ============================================================================
// mma.sync GEMM: C[M,N] = A[M,K] * B[N,K]^T + bias, 3-term bf16 split.
// CTA tile 128x128, BK=32, 3-stage cp.async pipeline, 8 warps (2m x 4n),
// warp tile 64x32. Row pad 40 halves (80B) -> conflict-free ldmatrix.
// ============================================================================
#define PADK 40
#define TILE_H (128 * PADK)        // halves per tile
#define STAGE_H (4 * TILE_H)       // Ah | Al | Bh | Bl
#define NSTG 3
#define KSTAGES (DD / 32)          // 32
#define GEMM_SMEM (NSTG * STAGE_H * 2)   // 122880 B

__global__ __launch_bounds__(256)
void gemm_mma(const __nv_bfloat16* __restrict__ Ah, const __nv_bfloat16* __restrict__ Al,
              const __nv_bfloat16* __restrict__ Bh, const __nv_bfloat16* __restrict__ Bl,
              const float* __restrict__ bias, float* __restrict__ Out, int headsplit)
{
    extern __shared__ __nv_bfloat16 smb[];
    const uint32_t sb = smem_u32(smb);
    const int t = threadIdx.x, wid = t >> 5, lane = t & 31;
    const int m0 = blockIdx.y * 128, n0 = blockIdx.x * 128;
    const int wm = (wid >> 2) * 64, wn = (wid & 3) * 32;

    const __nv_bfloat16* srcs[4] = {
        Ah + (size_t)m0 * DD, Al + (size_t)m0 * DD,
        Bh + (size_t)n0 * DD, Bl + (size_t)n0 * DD };

    // per-thread load coords: 8 x 16B chunks per stage
    int l_tile[8], l_row[8], l_c16[8];
#pragma unroll
    for (int p = 0; p < 8; p++) {
        int j = t + p * 256;            // 0..2047
        l_tile[p] = j >> 9;
        int c = j & 511;
        l_row[p] = c >> 2;
        l_c16[p] = c & 3;
    }

    auto issue_stage = [&](int s, int buf) {
        uint32_t base = sb + buf * STAGE_H * 2;
#pragma unroll
        for (int p = 0; p < 8; p++) {
            const __nv_bfloat16* g =
                srcs[l_tile[p]] + (size_t)l_row[p] * DD + s * 32 + l_c16[p] * 8;
            uint32_t d = base +
                (l_tile[p] * TILE_H + l_row[p] * PADK + l_c16[p] * 8) * 2;
            CP_ASYNC16(d, g);
        }
        CP_COMMIT();
    };

    float acc[4][4][4];
#pragma unroll
    for (int i = 0; i < 4; i++)
#pragma unroll
        for (int j = 0; j < 4; j++)
#pragma unroll
            for (int r = 0; r < 4; r++) acc[i][j][r] = 0.f;

    issue_stage(0, 0);
    issue_stage(1, 1);

    for (int s = 0; s < KSTAGES; s++) {
        CP_WAIT1();
        __syncthreads();
        if (s + 2 < KSTAGES) issue_stage(s + 2, (s + 2) % NSTG);

        const uint32_t base = sb + (s % NSTG) * STAGE_H * 2;
#pragma unroll
        for (int kk = 0; kk < 2; kk++) {
            uint32_t ah[4][4], al[4][4], bh[2][4], bl[2][4];
#pragma unroll
            for (int i = 0; i < 4; i++) {
                int row = wm + i * 16 + (lane & 15);
                int col = kk * 16 + (lane >> 4) * 8;
                uint32_t ad = base + (row * PADK + col) * 2;
                LDSM4(ah[i][0], ah[i][1], ah[i][2], ah[i][3], ad);
                LDSM4(al[i][0], al[i][1], al[i][2], al[i][3], ad + TILE_H * 2);
            }
#pragma unroll
            for (int g = 0; g < 2; g++) {
                int row = wn + g * 16 + ((lane >> 4) & 1) * 8 + (lane & 7);
                int col = kk * 16 + ((lane >> 3) & 1) * 8;
                uint32_t bd = base + (2 * TILE_H + row * PADK + col) * 2;
                LDSM4(bh[g][0], bh[g][1], bh[g][2], bh[g][3], bd);
                LDSM4(bl[g][0], bl[g][1], bl[g][2], bl[g][3], bd + TILE_H * 2);
            }
#pragma unroll
            for (int i = 0; i < 4; i++)
#pragma unroll
                for (int j = 0; j < 4; j++) {
                    int g = j >> 1, o = (j & 1) * 2;
                    MMA16816(acc[i][j], ah[i], bh[g][o], bh[g][o + 1]);
                    MMA16816(acc[i][j], ah[i], bl[g][o], bl[g][o + 1]);
                    MMA16816(acc[i][j], al[i], bh[g][o], bh[g][o + 1]);
                }
        }
        __syncthreads();
    }
    CP_WAIT0();

    // epilogue: c0/c1 at (row, col..col+1), c2/c3 at (row+8, ...)
#pragma unroll
    for (int i = 0; i < 4; i++) {
        int grow = m0 + wm + i * 16 + (lane >> 2);
#pragma unroll
        for (int j = 0; j < 4; j++) {
            int gcol = n0 + wn + j * 8 + (lane & 3) * 2;
            float bx = __ldg(&bias[gcol]), by = __ldg(&bias[gcol + 1]);
            float2 v0 = make_float2(acc[i][j][0] + bx, acc[i][j][1] + by);
            float2 v1 = make_float2(acc[i][j][2] + bx, acc[i][j][3] + by);
            if (headsplit) {
                int h = gcol >> 6, dh = gcol & 63;
                int b0r = grow >> 11, s0 = grow & 2047;
                *(float2*)&Out[(((size_t)(b0r * HH + h) * SS) + s0) * DH + dh] = v0;
                int g1 = grow + 8;
                int b1r = g1 >> 11, s1 = g1 & 2047;
                *(float2*)&Out[(((size_t)(b1r * HH + h) * SS) + s1) * DH + dh] = v1;
            } else {
                *(float2*)&Out[(size_t)grow * DD + gcol] = v0;
                *(float2*)&Out[(size_t)(grow + 8) * DD + gcol] = v1;
            }
        }
    }
}

// ============================================================================
// Flash attention, fp32 (R1 known-good)
// ============================================================================
#define QK_PAD 68

__global__ __launch_bounds__(256)
void attn_kernel(const float* __restrict__ Qg, const float* __restrict__ Kg,
                 const float* __restrict__ Vg, float* __restrict__ Og)
{
    extern __shared__ float sm[];
    float* Qs = sm;
    float* Ks = Qs + 64 * QK_PAD;
    float* Vs = Ks + 64 * QK_PAD;
    float* Ps = Vs + 64 * 64;

    const int t  = threadIdx.x;
    const int ty = t >> 4;
    const int tx = t & 15;
    const int bh = blockIdx.y;
    const int q0 = blockIdx.x * 64;

    const float* Qb = Qg + (size_t)bh * SS * DH;
    const float* Kb = Kg + (size_t)bh * SS * DH;
    const float* Vb = Vg + (size_t)bh * SS * DH;

#pragma unroll
    for (int i = 0; i < 4; i++) {
        int f  = t + i * 256;
        int r  = f >> 4;
        int kc = (f & 15) * 4;
        float4 v = *(const float4*)&Qb[(size_t)(q0 + r) * DH + kc];
        Qs[(kc + 0) * QK_PAD + r] = v.x * 0.125f;
        Qs[(kc + 1) * QK_PAD + r] = v.y * 0.125f;
        Qs[(kc + 2) * QK_PAD + r] = v.z * 0.125f;
        Qs[(kc + 3) * QK_PAD + r] = v.w * 0.125f;
    }

    float m_i[4], l_i[4], acc[4][4];
#pragma unroll
    for (int i = 0; i < 4; i++) {
        m_i[i] = -INFINITY; l_i[i] = 0.f;
#pragma unroll
        for (int j = 0; j < 4; j++) acc[i][j] = 0.f;
    }

    for (int kt = 0; kt < SS; kt += 64) {
        __syncthreads();
#pragma unroll
        for (int i = 0; i < 4; i++) {
            int f  = t + i * 256;
            int r  = f >> 4;
            int kc = (f & 15) * 4;
            float4 kv = *(const float4*)&Kb[(size_t)(kt + r) * DH + kc];
            Ks[(kc + 0) * QK_PAD + r] = kv.x;
            Ks[(kc + 1) * QK_PAD + r] = kv.y;
            Ks[(kc + 2) * QK_PAD + r] = kv.z;
            Ks[(kc + 3) * QK_PAD + r] = kv.w;
            *(float4*)&Vs[r * 64 + kc] =
                *(const float4*)&Vb[(size_t)(kt + r) * DH + kc];
        }
        __syncthreads();

        float s[4][4];
#pragma unroll
        for (int i = 0; i < 4; i++)
#pragma unroll
            for (int j = 0; j < 4; j++) s[i][j] = 0.f;

        for (int k = 0; k < 64; k++) {
            float4 qa = *(const float4*)&Qs[k * QK_PAD + ty * 4];
            float4 kb = *(const float4*)&Ks[k * QK_PAD + tx * 4];
            float qv[4] = {qa.x, qa.y, qa.z, qa.w};
            float kv[4] = {kb.x, kb.y, kb.z, kb.w};
#pragma unroll
            for (int i = 0; i < 4; i++)
#pragma unroll
                for (int j = 0; j < 4; j++) s[i][j] += qv[i] * kv[j];
        }

#pragma unroll
        for (int i = 0; i < 4; i++) {
            float mx = fmaxf(fmaxf(s[i][0], s[i][1]), fmaxf(s[i][2], s[i][3]));
#pragma unroll
            for (int o = 8; o >= 1; o >>= 1)
                mx = fmaxf(mx, __shfl_xor_sync(0xffffffffu, mx, o));
            float mn   = fmaxf(m_i[i], mx);
            float corr = __expf(m_i[i] - mn);
            m_i[i] = mn;
            float rs = 0.f;
#pragma unroll
            for (int j = 0; j < 4; j++) {
                s[i][j] = __expf(s[i][j] - mn);
                rs += s[i][j];
            }
#pragma unroll
            for (int o = 8; o >= 1; o >>= 1)
                rs += __shfl_xor_sync(0xffffffffu, rs, o);
            l_i[i] = l_i[i] * corr + rs;
#pragma unroll
            for (int j = 0; j < 4; j++) acc[i][j] *= corr;
            *(float4*)&Ps[(ty * 4 + i) * 64 + tx * 4] =
                make_float4(s[i][0], s[i][1], s[i][2], s[i][3]);
        }
        __syncthreads();

        for (int c = 0; c < 64; c++) {
            float4 v4 = *(const float4*)&Vs[c * 64 + tx * 4];
#pragma unroll
            for (int i = 0; i < 4; i++) {
                float p = Ps[(ty * 4 + i) * 64 + c];
                acc[i][0] += p * v4.x; acc[i][1] += p * v4.y;
                acc[i][2] += p * v4.z; acc[i][3] += p * v4.w;
            }
        }
    }

    float* Ob = Og + (size_t)bh * SS * DH;
#pragma unroll
    for (int i = 0; i < 4; i++) {
        float inv = 1.f / l_i[i];
        *(float4*)&Ob[(size_t)(q0 + ty * 4 + i) * DH + tx * 4] =
            make_float4(acc[i][0] * inv, acc[i][1] * inv,
                        acc[i][2] * inv, acc[i][3] * inv);
    }
}

// ============================================================================
// launch
// ============================================================================
extern "C" void kernel_launch(void* const* d_in, const int* in_sizes, int n_in,
                              void* d_out, int out_size)
{
    const float* q   = (const float*)d_in[0];
    const float* k   = (const float*)d_in[1];
    const float* v   = (const float*)d_in[2];
    const float* w_q = (const float*)d_in[3];
    const float* b_q = (const float*)d_in[4];
    const float* w_k = (const float*)d_in[5];
    const float* b_k = (const float*)d_in[6];
    const float* w_v = (const float*)d_in[7];
    const float* b_v = (const float*)d_in[8];
    const float* w_o = (const float*)d_in[9];
    const float* b_o = (const float*)d_in[10];
    float* out = (float*)d_out;

    float *pQ, *pK, *pV, *pO;
    __nv_bfloat16 *pAh, *pAl, *pBh, *pBl;
    cudaGetSymbolAddress((void**)&pQ, g_Q);
    cudaGetSymbolAddress((void**)&pK, g_K);
    cudaGetSymbolAddress((void**)&pV, g_V);
    cudaGetSymbolAddress((void**)&pO, g_O);
    cudaGetSymbolAddress((void**)&pAh, g_Ah);
    cudaGetSymbolAddress((void**)&pAl, g_Al);
    cudaGetSymbolAddress((void**)&pBh, g_Bh);
    cudaGetSymbolAddress((void**)&pBl, g_Bl);

    static int attr_set = 0;
    const int attn_smem = (64 * QK_PAD * 2 + 64 * 64 * 2) * sizeof(float);
    if (!attr_set) {
        cudaFuncSetAttribute(attn_kernel,
                             cudaFuncAttributeMaxDynamicSharedMemorySize, attn_smem);
        cudaFuncSetAttribute(gemm_mma,
                             cudaFuncAttributeMaxDynamicSharedMemorySize, GEMM_SMEM);
        attr_set = 1;
    }

    const int n4A = MM * DD / 4;      // 1048576
    const dim3 gw(DD / 32, DD / 32);  // (32,32)
    const dim3 bw(32, 8);
    const dim3 gg(DD / 128, MM / 128);  // (8,32)

    // Q projection
    conv_split<<<n4A / 256, 256>>>((const float4*)q, pAh, pAl, n4A);
    conv_wT<<<gw, bw>>>(w_q, pBh, pBl);
    gemm_mma<<<gg, 256, GEMM_SMEM>>>(pAh, pAl, pBh, pBl, b_q, pQ, 1);
    // K projection
    conv_split<<<n4A / 256, 256>>>((const float4*)k, pAh, pAl, n4A);
    conv_wT<<<gw, bw>>>(w_k, pBh, pBl);
    gemm_mma<<<gg, 256, GEMM_SMEM>>>(pAh, pAl, pBh, pBl, b_k, pK, 1);
    // V projection
    conv_split<<<n4A / 256, 256>>>((const float4*)v, pAh, pAl, n4A);
    conv_wT<<<gw, bw>>>(w_v, pBh, pBl);
    gemm_mma<<<gg, 256, GEMM_SMEM>>>(pAh, pAl, pBh, pBl, b_v, pV, 1);

    // attention (fp32, unchanged)
    dim3 ga(SS / 64, BB * HH);
    attn_kernel<<<ga, 256, attn_smem>>>(pQ, pK, pV, pO);

    // output projection
    conv_gather<<<n4A / 256, 256>>>(pO, pAh, pAl);
    conv_wT<<<gw, bw>>>(w_o, pBh, pBl);
    gemm_mma<<<gg, 256, GEMM_SMEM>>>(pAh, pAl, pBh, pBl, b_o, out, 0);
}

// round 4
// speedup vs baseline: 2.4862x; 1.8597x over previous
#include <cuda_runtime.h>
#include <cuda_bf16.h>
#include <math.h>
#include <stdint.h>

// Problem constants
#define BB 2
#define SS 2048
#define DD 1024
#define HH 16
#define DH 64
#define MM (BB * SS)   // 4096 rows

// -------------------- scratch (allocation-free rule: __device__ globals) ----
__device__ __nv_bfloat16 g_Ah[MM * DD];   // GEMM A hi  [M][K]
__device__ __nv_bfloat16 g_Al[MM * DD];   // GEMM A lo
__device__ __nv_bfloat16 g_Bh[DD * DD];   // GEMM B hi  [N][K]
__device__ __nv_bfloat16 g_Bl[DD * DD];   // GEMM B lo
__device__ __nv_bfloat16 g_Qh[MM * DD];   // head-split [B*H][S][DH]
__device__ __nv_bfloat16 g_Ql[MM * DD];
__device__ __nv_bfloat16 g_Kh[MM * DD];
__device__ __nv_bfloat16 g_Kl[MM * DD];
__device__ __nv_bfloat16 g_Vh[MM * DD];
__device__ __nv_bfloat16 g_Vl[MM * DD];

// ============================================================================
// helpers
// ============================================================================
__device__ __forceinline__ uint32_t smem_u32(const void* p) {
    uint32_t a;
    asm("{ .reg .u64 t; cvta.to.shared.u64 t, %1; cvt.u32.u64 %0, t; }"
        : "=r"(a) : "l"(p));
    return a;
}

#define LDSM4(r0, r1, r2, r3, addr)                                            \
    asm volatile("ldmatrix.sync.aligned.m8n8.x4.shared.b16 {%0,%1,%2,%3}, [%4];" \
                 : "=r"(r0), "=r"(r1), "=r"(r2), "=r"(r3) : "r"(addr))
#define LDSM4T(r0, r1, r2, r3, addr)                                           \
    asm volatile("ldmatrix.sync.aligned.m8n8.x4.trans.shared.b16 {%0,%1,%2,%3}, [%4];" \
                 : "=r"(r0), "=r"(r1), "=r"(r2), "=r"(r3) : "r"(addr))

#define MMA16816(d, a, b0, b1)                                                 \
    asm volatile("mma.sync.aligned.m16n8k16.row.col.f32.bf16.bf16.f32 "        \
                 "{%0,%1,%2,%3}, {%4,%5,%6,%7}, {%8,%9}, {%0,%1,%2,%3};"       \
                 : "+f"((d)[0]), "+f"((d)[1]), "+f"((d)[2]), "+f"((d)[3])      \
                 : "r"((a)[0]), "r"((a)[1]), "r"((a)[2]), "r"((a)[3]),         \
                   "r"(b0), "r"(b1))

#define CP_ASYNC16(dst, src)                                                   \
    asm volatile("cp.async.cg.shared.global [%0], [%1], 16;" :: "r"(dst), "l"(src))
#define CP_COMMIT()  asm volatile("cp.async.commit_group;" ::: "memory")
#define CP_WAIT1()   asm volatile("cp.async.wait_group 1;" ::: "memory")
#define CP_WAIT0()   asm volatile("cp.async.wait_group 0;" ::: "memory")

__device__ __forceinline__ uint32_t pack_hi(float x, float y) {
    __nv_bfloat162 h = __floats2bfloat162_rn(x, y);
    return *(uint32_t*)&h;
}
__device__ __forceinline__ uint32_t pack_lo(float x, float y, uint32_t hbits) {
    __nv_bfloat162 h = *(__nv_bfloat162*)&hbits;
    __nv_bfloat162 l = __floats2bfloat162_rn(x - __bfloat162float(h.x),
                                             y - __bfloat162float(h.y));
    return *(uint32_t*)&l;
}

// ============================================================================
// bf16 split conversion kernels
// ============================================================================
__global__ __launch_bounds__(256)
void conv_split(const float4* __restrict__ src, __nv_bfloat16* __restrict__ hi,
                __nv_bfloat16* __restrict__ lo, int n4)
{
    int i = blockIdx.x * 256 + threadIdx.x;
    if (i >= n4) return;
    float4 v = src[i];
    uint32_t h0 = pack_hi(v.x, v.y), h1 = pack_hi(v.z, v.w);
    uint32_t l0 = pack_lo(v.x, v.y, h0), l1 = pack_lo(v.z, v.w, h1);
    ((uint32_t*)hi)[i * 2 + 0] = h0;
    ((uint32_t*)hi)[i * 2 + 1] = h1;
    ((uint32_t*)lo)[i * 2 + 0] = l0;
    ((uint32_t*)lo)[i * 2 + 1] = l1;
}

// W [K][N] row-major -> Bt[n][k] hi/lo (transpose + split)
__global__ __launch_bounds__(256)
void conv_wT(const float* __restrict__ W, __nv_bfloat16* __restrict__ hi,
             __nv_bfloat16* __restrict__ lo)
{
    __shared__ float t[32][33];
    int n0 = blockIdx.x * 32, k0 = blockIdx.y * 32;
    int tx = threadIdx.x, ty = threadIdx.y;   // block (32,8)
#pragma unroll
    for (int i = 0; i < 32; i += 8)
        t[ty + i][tx] = W[(size_t)(k0 + ty + i) * DD + n0 + tx];
    __syncthreads();
#pragma unroll
    for (int i = 0; i < 32; i += 8) {
        float v = t[tx][ty + i];
        __nv_bfloat16 h = __float2bfloat16_rn(v);
        size_t o = (size_t)(n0 + ty + i) * DD + k0 + tx;
        hi[o] = h;
        lo[o] = __float2bfloat16_rn(v - __bfloat162float(h));
    }
}

// ============================================================================
// mma.sync GEMM (R3-proven core).  mode 0: fp32 natural out.
// mode 1: bf16 hi/lo head-split out ([B*H][S][DH]).
// ============================================================================
#define PADK 40
#define TILE_H (128 * PADK)
#define STAGE_H (4 * TILE_H)
#define NSTG 3
#define KSTAGES (DD / 32)
#define GEMM_SMEM (NSTG * STAGE_H * 2)

__global__ __launch_bounds__(256)
void gemm_mma(const __nv_bfloat16* __restrict__ Ah, const __nv_bfloat16* __restrict__ Al,
              const __nv_bfloat16* __restrict__ Bh, const __nv_bfloat16* __restrict__ Bl,
              const float* __restrict__ bias, float* __restrict__ OutF,
              __nv_bfloat16* __restrict__ OutH, __nv_bfloat16* __restrict__ OutL,
              int mode)
{
    extern __shared__ __nv_bfloat16 smb[];
    const uint32_t sb = smem_u32(smb);
    const int t = threadIdx.x, wid = t >> 5, lane = t & 31;
    const int m0 = blockIdx.y * 128, n0 = blockIdx.x * 128;
    const int wm = (wid >> 2) * 64, wn = (wid & 3) * 32;

    const __nv_bfloat16* srcs[4] = {
        Ah + (size_t)m0 * DD, Al + (size_t)m0 * DD,
        Bh + (size_t)n0 * DD, Bl + (size_t)n0 * DD };

    int l_tile[8], l_row[8], l_c16[8];
#pragma unroll
    for (int p = 0; p < 8; p++) {
        int j = t + p * 256;
        l_tile[p] = j >> 9;
        int c = j & 511;
        l_row[p] = c >> 2;
        l_c16[p] = c & 3;
    }

    auto issue_stage = [&](int s, int buf) {
        uint32_t base = sb + buf * STAGE_H * 2;
#pragma unroll
        for (int p = 0; p < 8; p++) {
            const __nv_bfloat16* g =
                srcs[l_tile[p]] + (size_t)l_row[p] * DD + s * 32 + l_c16[p] * 8;
            uint32_t d = base +
                (l_tile[p] * TILE_H + l_row[p] * PADK + l_c16[p] * 8) * 2;
            CP_ASYNC16(d, g);
        }
        CP_COMMIT();
    };

    float acc[4][4][4];
#pragma unroll
    for (int i = 0; i < 4; i++)
#pragma unroll
        for (int j = 0; j < 4; j++)
#pragma unroll
            for (int r = 0; r < 4; r++) acc[i][j][r] = 0.f;

    issue_stage(0, 0);
    issue_stage(1, 1);

    for (int s = 0; s < KSTAGES; s++) {
        CP_WAIT1();
        __syncthreads();
        if (s + 2 < KSTAGES) issue_stage(s + 2, (s + 2) % NSTG);

        const uint32_t base = sb + (s % NSTG) * STAGE_H * 2;
#pragma unroll
        for (int kk = 0; kk < 2; kk++) {
            uint32_t ah[4][4], al[4][4], bh[2][4], bl[2][4];
#pragma unroll
            for (int i = 0; i < 4; i++) {
                int row = wm + i * 16 + (lane & 15);
                int col = kk * 16 + (lane >> 4) * 8;
                uint32_t ad = base + (row * PADK + col) * 2;
                LDSM4(ah[i][0], ah[i][1], ah[i][2], ah[i][3], ad);
                LDSM4(al[i][0], al[i][1], al[i][2], al[i][3], ad + TILE_H * 2);
            }
#pragma unroll
            for (int g = 0; g < 2; g++) {
                int row = wn + g * 16 + ((lane >> 4) & 1) * 8 + (lane & 7);
                int col = kk * 16 + ((lane >> 3) & 1) * 8;
                uint32_t bd = base + (2 * TILE_H + row * PADK + col) * 2;
                LDSM4(bh[g][0], bh[g][1], bh[g][2], bh[g][3], bd);
                LDSM4(bl[g][0], bl[g][1], bl[g][2], bl[g][3], bd + TILE_H * 2);
            }
#pragma unroll
            for (int i = 0; i < 4; i++)
#pragma unroll
                for (int j = 0; j < 4; j++) {
                    int g = j >> 1, o = (j & 1) * 2;
                    MMA16816(acc[i][j], ah[i], bh[g][o], bh[g][o + 1]);
                    MMA16816(acc[i][j], ah[i], bl[g][o], bl[g][o + 1]);
                    MMA16816(acc[i][j], al[i], bh[g][o], bh[g][o + 1]);
                }
        }
        __syncthreads();
    }
    CP_WAIT0();

#pragma unroll
    for (int i = 0; i < 4; i++) {
        int grow = m0 + wm + i * 16 + (lane >> 2);
#pragma unroll
        for (int j = 0; j < 4; j++) {
            int gcol = n0 + wn + j * 8 + (lane & 3) * 2;
            float bx = __ldg(&bias[gcol]), by = __ldg(&bias[gcol + 1]);
            float x0 = acc[i][j][0] + bx, y0 = acc[i][j][1] + by;
            float x1 = acc[i][j][2] + bx, y1 = acc[i][j][3] + by;
            if (mode == 1) {
                int h = gcol >> 6, dh = gcol & 63;
                int b0r = grow >> 11, s0 = grow & 2047;
                size_t o0 = (((size_t)(b0r * HH + h) * SS) + s0) * DH + dh;
                int g1 = grow + 8;
                int b1r = g1 >> 11, s1 = g1 & 2047;
                size_t o1 = (((size_t)(b1r * HH + h) * SS) + s1) * DH + dh;
                uint32_t h0 = pack_hi(x0, y0), h1 = pack_hi(x1, y1);
                *(uint32_t*)&OutH[o0] = h0;
                *(uint32_t*)&OutL[o0] = pack_lo(x0, y0, h0);
                *(uint32_t*)&OutH[o1] = h1;
                *(uint32_t*)&OutL[o1] = pack_lo(x1, y1, h1);
            } else {
                *(float2*)&OutF[(size_t)grow * DD + gcol] = make_float2(x0, y0);
                *(float2*)&OutF[(size_t)(grow + 8) * DD + gcol] = make_float2(x1, y1);
            }
        }
    }
}

// ============================================================================
// Flash attention on mma.sync, 3-term bf16 splits both GEMMs.
// Block: 128 q-rows, 8 warps (warp = 16 rows x full 64 width).
// KV tiles 64 rows, hi+lo for K and V, 2-stage cp.async, pad-72 rows.
// Writes bf16 hi/lo gathered [M][D] directly into out-projection A buffers.
// ============================================================================
#define APAD 72
#define KV_TILE_H (64 * APAD)          // halves per tile
#define AT_STAGE_H (4 * KV_TILE_H)     // Kh | Kl | Vh | Vl
#define AT_SMEM (2 * AT_STAGE_H * 2)   // 73728 B
#define NKT (SS / 64)                  // 32

__global__ __launch_bounds__(256)
void attn_mma(const __nv_bfloat16* __restrict__ Qh, const __nv_bfloat16* __restrict__ Ql,
              const __nv_bfloat16* __restrict__ Kh, const __nv_bfloat16* __restrict__ Kl,
              const __nv_bfloat16* __restrict__ Vh, const __nv_bfloat16* __restrict__ Vl,
              __nv_bfloat16* __restrict__ OutH, __nv_bfloat16* __restrict__ OutL)
{
    extern __shared__ __nv_bfloat16 smb[];
    const uint32_t sb = smem_u32(smb);
    const int t = threadIdx.x, wid = t >> 5, lane = t & 31;
    const int bh = blockIdx.y;
    const int q0 = blockIdx.x * 128;
    const int wm = wid * 16;
    const size_t bhoff = (size_t)bh * SS * DH;

    // ---- stage Q tile (hi at 0, lo at 128*APAD halves) ----
    {
        const __nv_bfloat16* qs[2] = {Qh + bhoff + (size_t)q0 * DH,
                                      Ql + bhoff + (size_t)q0 * DH};
#pragma unroll
        for (int p = 0; p < 8; p++) {
            int j = t + p * 256;          // 2048 chunks
            int tile = j >> 10;
            int row = (j >> 3) & 127;
            int c16 = j & 7;
            uint32_t d = sb + (tile * 128 * APAD + row * APAD + c16 * 8) * 2;
            CP_ASYNC16(d, qs[tile] + (size_t)row * DH + c16 * 8);
        }
        CP_COMMIT();
        CP_WAIT0();
        __syncthreads();
    }

    // ---- Q fragments (persistent) ----
    uint32_t qh[4][4], ql[4][4];
#pragma unroll
    for (int kk = 0; kk < 4; kk++) {
        int row = wm + (lane & 15);
        int col = kk * 16 + (lane >> 4) * 8;
        uint32_t ad = sb + (row * APAD + col) * 2;
        LDSM4(qh[kk][0], qh[kk][1], qh[kk][2], qh[kk][3], ad);
        LDSM4(ql[kk][0], ql[kk][1], ql[kk][2], ql[kk][3], ad + 128 * APAD * 2);
    }
    __syncthreads();   // smem free for KV

    // ---- KV pipeline ----
    const __nv_bfloat16* kvsrc[4] = {Kh + bhoff, Kl + bhoff, Vh + bhoff, Vl + bhoff};
    auto issue_kv = [&](int kt, int buf) {
        uint32_t base = sb + buf * AT_STAGE_H * 2;
#pragma unroll
        for (int p = 0; p < 8; p++) {
            int j = t + p * 256;          // 2048 chunks
            int tile = j >> 9;
            int row = (j >> 3) & 63;
            int c16 = j & 7;
            uint32_t d = base + (tile * KV_TILE_H + row * APAD + c16 * 8) * 2;
            CP_ASYNC16(d, kvsrc[tile] + (size_t)(kt * 64 + row) * DH + c16 * 8);
        }
        CP_COMMIT();
    };

    float o[8][4];
#pragma unroll
    for (int j = 0; j < 8; j++)
#pragma unroll
        for (int r = 0; r < 4; r++) o[j][r] = 0.f;
    float m_i[2] = {-INFINITY, -INFINITY};
    float l_i[2] = {0.f, 0.f};

    issue_kv(0, 0);
    issue_kv(1, 1);

    for (int kt = 0; kt < NKT; kt++) {
        CP_WAIT1();
        __syncthreads();
        const uint32_t base = sb + (kt & 1) * AT_STAGE_H * 2;

        // ---- scores S = Q K^T ----
        float s[8][4];
#pragma unroll
        for (int j = 0; j < 8; j++)
#pragma unroll
            for (int r = 0; r < 4; r++) s[j][r] = 0.f;

#pragma unroll
        for (int kk = 0; kk < 4; kk++) {
            uint32_t kfh[4][4], kfl[4][4];
#pragma unroll
            for (int g = 0; g < 4; g++) {
                int row = g * 16 + ((lane >> 4) & 1) * 8 + (lane & 7);
                int col = kk * 16 + ((lane >> 3) & 1) * 8;
                uint32_t kd = base + (row * APAD + col) * 2;
                LDSM4(kfh[g][0], kfh[g][1], kfh[g][2], kfh[g][3], kd);
                LDSM4(kfl[g][0], kfl[g][1], kfl[g][2], kfl[g][3], kd + KV_TILE_H * 2);
            }
#pragma unroll
            for (int j = 0; j < 8; j++) {
                int g = j >> 1, oo = (j & 1) * 2;
                MMA16816(s[j], qh[kk], kfh[g][oo], kfh[g][oo + 1]);
                MMA16816(s[j], qh[kk], kfl[g][oo], kfl[g][oo + 1]);
                MMA16816(s[j], ql[kk], kfh[g][oo], kfh[g][oo + 1]);
            }
        }

        // ---- online softmax (rows r = lane>>2 and r+8) ----
        float mx[2] = {-INFINITY, -INFINITY};
#pragma unroll
        for (int j = 0; j < 8; j++) {
#pragma unroll
            for (int r = 0; r < 4; r++) s[j][r] *= 0.125f;
            mx[0] = fmaxf(mx[0], fmaxf(s[j][0], s[j][1]));
            mx[1] = fmaxf(mx[1], fmaxf(s[j][2], s[j][3]));
        }
#pragma unroll
        for (int r = 0; r < 2; r++) {
            mx[r] = fmaxf(mx[r], __shfl_xor_sync(0xffffffffu, mx[r], 1));
            mx[r] = fmaxf(mx[r], __shfl_xor_sync(0xffffffffu, mx[r], 2));
        }
        float mn[2], corr[2];
#pragma unroll
        for (int r = 0; r < 2; r++) {
            mn[r] = fmaxf(m_i[r], mx[r]);
            corr[r] = __expf(m_i[r] - mn[r]);
            m_i[r] = mn[r];
        }
        float rs[2] = {0.f, 0.f};
#pragma unroll
        for (int j = 0; j < 8; j++) {
            s[j][0] = __expf(s[j][0] - mn[0]);
            s[j][1] = __expf(s[j][1] - mn[0]);
            s[j][2] = __expf(s[j][2] - mn[1]);
            s[j][3] = __expf(s[j][3] - mn[1]);
            rs[0] += s[j][0] + s[j][1];
            rs[1] += s[j][2] + s[j][3];
        }
#pragma unroll
        for (int r = 0; r < 2; r++) {
            rs[r] += __shfl_xor_sync(0xffffffffu, rs[r], 1);
            rs[r] += __shfl_xor_sync(0xffffffffu, rs[r], 2);
            l_i[r] = l_i[r] * corr[r] + rs[r];
        }
#pragma unroll
        for (int j = 0; j < 8; j++) {
            o[j][0] *= corr[0]; o[j][1] *= corr[0];
            o[j][2] *= corr[1]; o[j][3] *= corr[1];
        }

        // ---- PV: O += P V ----
#pragma unroll
        for (int kk = 0; kk < 4; kk++) {
            uint32_t aph[4], apl[4];
            aph[0] = pack_hi(s[2 * kk][0], s[2 * kk][1]);
            aph[1] = pack_hi(s[2 * kk][2], s[2 * kk][3]);
            aph[2] = pack_hi(s[2 * kk + 1][0], s[2 * kk + 1][1]);
            aph[3] = pack_hi(s[2 * kk + 1][2], s[2 * kk + 1][3]);
            apl[0] = pack_lo(s[2 * kk][0], s[2 * kk][1], aph[0]);
            apl[1] = pack_lo(s[2 * kk][2], s[2 * kk][3], aph[1]);
            apl[2] = pack_lo(s[2 * kk + 1][0], s[2 * kk + 1][1], aph[2]);
            apl[3] = pack_lo(s[2 * kk + 1][2], s[2 * kk + 1][3], aph[3]);

            uint32_t vfh[4][4], vfl[4][4];
#pragma unroll
            for (int g = 0; g < 4; g++) {
                int row = kk * 16 + (lane & 15);          // kv
                int col = g * 16 + (lane >> 4) * 8;       // dh
                uint32_t vd = base + (2 * KV_TILE_H + row * APAD + col) * 2;
                LDSM4T(vfh[g][0], vfh[g][1], vfh[g][2], vfh[g][3], vd);
                LDSM4T(vfl[g][0], vfl[g][1], vfl[g][2], vfl[g][3], vd + KV_TILE_H * 2);
            }
#pragma unroll
            for (int j = 0; j < 8; j++) {
                int g = j >> 1, oo = (j & 1) * 2;
                MMA16816(o[j], aph, vfh[g][oo], vfh[g][oo + 1]);
                MMA16816(o[j], aph, vfl[g][oo], vfl[g][oo + 1]);
                MMA16816(o[j], apl, vfh[g][oo], vfh[g][oo + 1]);
            }
        }
        __syncthreads();                  // all warps done with stage kt
        if (kt + 2 < NKT) issue_kv(kt + 2, kt & 1);
    }

    // ---- epilogue: write bf16 hi/lo gathered [M][D] ----
    const int b = bh >> 4, h = bh & 15;
    const float inv0 = 1.f / l_i[0], inv1 = 1.f / l_i[1];
    const int srow0 = q0 + wm + (lane >> 2);
#pragma unroll
    for (int j = 0; j < 8; j++) {
        int dh = j * 8 + (lane & 3) * 2;
        int kcol = h * 64 + dh;
        size_t o0 = ((size_t)(b * SS + srow0)) * DD + kcol;
        size_t o1 = ((size_t)(b * SS + srow0 + 8)) * DD + kcol;
        float x0 = o[j][0] * inv0, y0 = o[j][1] * inv0;
        float x1 = o[j][2] * inv1, y1 = o[j][3] * inv1;
        uint32_t h0 = pack_hi(x0, y0), h1 = pack_hi(x1, y1);
        *(uint32_t*)&OutH[o0] = h0;
        *(uint32_t*)&OutL[o0] = pack_lo(x0, y0, h0);
        *(uint32_t*)&OutH[o1] = h1;
        *(uint32_t*)&OutL[o1] = pack_lo(x1, y1, h1);
    }
}

// ============================================================================
// launch
// ============================================================================
extern "C" void kernel_launch(void* const* d_in, const int* in_sizes, int n_in,
                              void* d_out, int out_size)
{
    const float* q   = (const float*)d_in[0];
    const float* k   = (const float*)d_in[1];
    const float* v   = (const float*)d_in[2];
    const float* w_q = (const float*)d_in[3];
    const float* b_q = (const float*)d_in[4];
    const float* w_k = (const float*)d_in[5];
    const float* b_k = (const float*)d_in[6];
    const float* w_v = (const float*)d_in[7];
    const float* b_v = (const float*)d_in[8];
    const float* w_o = (const float*)d_in[9];
    const float* b_o = (const float*)d_in[10];
    float* out = (float*)d_out;

    __nv_bfloat16 *pAh, *pAl, *pBh, *pBl, *pQh, *pQl, *pKh, *pKl, *pVh, *pVl;
    cudaGetSymbolAddress((void**)&pAh, g_Ah);
    cudaGetSymbolAddress((void**)&pAl, g_Al);
    cudaGetSymbolAddress((void**)&pBh, g_Bh);
    cudaGetSymbolAddress((void**)&pBl, g_Bl);
    cudaGetSymbolAddress((void**)&pQh, g_Qh);
    cudaGetSymbolAddress((void**)&pQl, g_Ql);
    cudaGetSymbolAddress((void**)&pKh, g_Kh);
    cudaGetSymbolAddress((void**)&pKl, g_Kl);
    cudaGetSymbolAddress((void**)&pVh, g_Vh);
    cudaGetSymbolAddress((void**)&pVl, g_Vl);

    static int attr_set = 0;
    if (!attr_set) {
        cudaFuncSetAttribute(gemm_mma,
                             cudaFuncAttributeMaxDynamicSharedMemorySize, GEMM_SMEM);
        cudaFuncSetAttribute(attn_mma,
                             cudaFuncAttributeMaxDynamicSharedMemorySize, AT_SMEM);
        attr_set = 1;
    }

    const int n4A = MM * DD / 4;
    const dim3 gw(DD / 32, DD / 32);
    const dim3 bw(32, 8);
    const dim3 gg(DD / 128, MM / 128);

    // Q projection -> bf16 hi/lo head-split
    conv_split<<<n4A / 256, 256>>>((const float4*)q, pAh, pAl, n4A);
    conv_wT<<<gw, bw>>>(w_q, pBh, pBl);
    gemm_mma<<<gg, 256, GEMM_SMEM>>>(pAh, pAl, pBh, pBl, b_q, nullptr, pQh, pQl, 1);
    // K projection
    conv_split<<<n4A / 256, 256>>>((const float4*)k, pAh, pAl, n4A);
    conv_wT<<<gw, bw>>>(w_k, pBh, pBl);
    gemm_mma<<<gg, 256, GEMM_SMEM>>>(pAh, pAl, pBh, pBl, b_k, nullptr, pKh, pKl, 1);
    // V projection
    conv_split<<<n4A / 256, 256>>>((const float4*)v, pAh, pAl, n4A);
    conv_wT<<<gw, bw>>>(w_v, pBh, pBl);
    gemm_mma<<<gg, 256, GEMM_SMEM>>>(pAh, pAl, pBh, pBl, b_v, nullptr, pVh, pVl, 1);

    // attention (tensor-core, writes out-projection A operands directly)
    dim3 ga(SS / 128, BB * HH);   // (16, 32)
    attn_mma<<<ga, 256, AT_SMEM>>>(pQh, pQl, pKh, pKl, pVh, pVl, pAh, pAl);

    // output projection -> fp32 natural
    conv_wT<<<gw, bw>>>(w_o, pBh, pBl);
    gemm_mma<<<gg, 256, GEMM_SMEM>>>(pAh, pAl, pBh, pBl, b_o, out, nullptr, nullptr, 0);
}

// round 5
// speedup vs baseline: 2.7022x; 1.0869x over previous
#include <cuda_runtime.h>
#include <cuda_bf16.h>
#include <math.h>
#include <stdint.h>

// Problem constants
#define BB 2
#define SS 2048
#define DD 1024
#define HH 16
#define DH 64
#define MM (BB * SS)   // 4096 rows

// -------------------- scratch (allocation-free rule: __device__ globals) ----
// Per-projection GEMM A operands (A0 reused as attn-output / out-proj A)
__device__ __nv_bfloat16 g_A0h[MM * DD];
__device__ __nv_bfloat16 g_A0l[MM * DD];
__device__ __nv_bfloat16 g_A1h[MM * DD];
__device__ __nv_bfloat16 g_A1l[MM * DD];
__device__ __nv_bfloat16 g_A2h[MM * DD];
__device__ __nv_bfloat16 g_A2l[MM * DD];
// Per-weight GEMM B operands [N][K] (q,k,v,o)
__device__ __nv_bfloat16 g_B0h[DD * DD];
__device__ __nv_bfloat16 g_B0l[DD * DD];
__device__ __nv_bfloat16 g_B1h[DD * DD];
__device__ __nv_bfloat16 g_B1l[DD * DD];
__device__ __nv_bfloat16 g_B2h[DD * DD];
__device__ __nv_bfloat16 g_B2l[DD * DD];
__device__ __nv_bfloat16 g_B3h[DD * DD];
__device__ __nv_bfloat16 g_B3l[DD * DD];
// Projection outputs, head-split [B*H][S][DH]
__device__ __nv_bfloat16 g_Qh[MM * DD];
__device__ __nv_bfloat16 g_Ql[MM * DD];
__device__ __nv_bfloat16 g_Kh[MM * DD];
__device__ __nv_bfloat16 g_Kl[MM * DD];
__device__ __nv_bfloat16 g_Vh[MM * DD];
__device__ __nv_bfloat16 g_Vl[MM * DD];

// ============================================================================
// helpers
// ============================================================================
__device__ __forceinline__ uint32_t smem_u32(const void* p) {
    uint32_t a;
    asm("{ .reg .u64 t; cvta.to.shared.u64 t, %1; cvt.u32.u64 %0, t; }"
        : "=r"(a) : "l"(p));
    return a;
}

#define LDSM4(r0, r1, r2, r3, addr)                                            \
    asm volatile("ldmatrix.sync.aligned.m8n8.x4.shared.b16 {%0,%1,%2,%3}, [%4];" \
                 : "=r"(r0), "=r"(r1), "=r"(r2), "=r"(r3) : "r"(addr))
#define LDSM4T(r0, r1, r2, r3, addr)                                           \
    asm volatile("ldmatrix.sync.aligned.m8n8.x4.trans.shared.b16 {%0,%1,%2,%3}, [%4];" \
                 : "=r"(r0), "=r"(r1), "=r"(r2), "=r"(r3) : "r"(addr))

#define MMA16816(d, a, b0, b1)                                                 \
    asm volatile("mma.sync.aligned.m16n8k16.row.col.f32.bf16.bf16.f32 "        \
                 "{%0,%1,%2,%3}, {%4,%5,%6,%7}, {%8,%9}, {%0,%1,%2,%3};"       \
                 : "+f"((d)[0]), "+f"((d)[1]), "+f"((d)[2]), "+f"((d)[3])      \
                 : "r"((a)[0]), "r"((a)[1]), "r"((a)[2]), "r"((a)[3]),         \
                   "r"(b0), "r"(b1))

#define CP_ASYNC16(dst, src)                                                   \
    asm volatile("cp.async.cg.shared.global [%0], [%1], 16;" :: "r"(dst), "l"(src))
#define CP_COMMIT()  asm volatile("cp.async.commit_group;" ::: "memory")
#define CP_WAIT1()   asm volatile("cp.async.wait_group 1;" ::: "memory")
#define CP_WAIT0()   asm volatile("cp.async.wait_group 0;" ::: "memory")

__device__ __forceinline__ uint32_t pack_hi(float x, float y) {
    __nv_bfloat162 h = __floats2bfloat162_rn(x, y);
    return *(uint32_t*)&h;
}
__device__ __forceinline__ uint32_t pack_lo(float x, float y, uint32_t hbits) {
    __nv_bfloat162 h = *(__nv_bfloat162*)&hbits;
    __nv_bfloat162 l = __floats2bfloat162_rn(x - __bfloat162float(h.x),
                                             y - __bfloat162float(h.y));
    return *(uint32_t*)&l;
}

// ============================================================================
// fused conversion kernels
// ============================================================================
// blockIdx.y picks q/k/v input -> A{0,1,2} hi/lo
__global__ __launch_bounds__(256)
void conv_split3(const float4* __restrict__ q, const float4* __restrict__ k,
                 const float4* __restrict__ v,
                 __nv_bfloat16* __restrict__ a0h, __nv_bfloat16* __restrict__ a0l,
                 __nv_bfloat16* __restrict__ a1h, __nv_bfloat16* __restrict__ a1l,
                 __nv_bfloat16* __restrict__ a2h, __nv_bfloat16* __restrict__ a2l)
{
    const int z = blockIdx.y;
    const float4* src = (z == 0) ? q : (z == 1) ? k : v;
    __nv_bfloat16* hi = (z == 0) ? a0h : (z == 1) ? a1h : a2h;
    __nv_bfloat16* lo = (z == 0) ? a0l : (z == 1) ? a1l : a2l;
    int i = blockIdx.x * 256 + threadIdx.x;
    float4 val = src[i];
    uint32_t h0 = pack_hi(val.x, val.y), h1 = pack_hi(val.z, val.w);
    uint32_t l0 = pack_lo(val.x, val.y, h0), l1 = pack_lo(val.z, val.w, h1);
    ((uint32_t*)hi)[i * 2 + 0] = h0;
    ((uint32_t*)hi)[i * 2 + 1] = h1;
    ((uint32_t*)lo)[i * 2 + 0] = l0;
    ((uint32_t*)lo)[i * 2 + 1] = l1;
}

// blockIdx.z picks which W -> B[n][k] hi/lo (transpose + split)
__global__ __launch_bounds__(256)
void conv_wT4(const float* __restrict__ w0, const float* __restrict__ w1,
              const float* __restrict__ w2, const float* __restrict__ w3,
              __nv_bfloat16* __restrict__ b0h, __nv_bfloat16* __restrict__ b0l,
              __nv_bfloat16* __restrict__ b1h, __nv_bfloat16* __restrict__ b1l,
              __nv_bfloat16* __restrict__ b2h, __nv_bfloat16* __restrict__ b2l,
              __nv_bfloat16* __restrict__ b3h, __nv_bfloat16* __restrict__ b3l)
{
    const int z = blockIdx.z;
    const float* W = (z == 0) ? w0 : (z == 1) ? w1 : (z == 2) ? w2 : w3;
    __nv_bfloat16* hi = (z == 0) ? b0h : (z == 1) ? b1h : (z == 2) ? b2h : b3h;
    __nv_bfloat16* lo = (z == 0) ? b0l : (z == 1) ? b1l : (z == 2) ? b2l : b3l;

    __shared__ float t[32][33];
    int n0 = blockIdx.x * 32, k0 = blockIdx.y * 32;
    int tx = threadIdx.x, ty = threadIdx.y;   // block (32,8)
#pragma unroll
    for (int i = 0; i < 32; i += 8)
        t[ty + i][tx] = W[(size_t)(k0 + ty + i) * DD + n0 + tx];
    __syncthreads();
#pragma unroll
    for (int i = 0; i < 32; i += 8) {
        float v = t[tx][ty + i];
        __nv_bfloat16 h = __float2bfloat16_rn(v);
        size_t o = (size_t)(n0 + ty + i) * DD + k0 + tx;
        hi[o] = h;
        lo[o] = __float2bfloat16_rn(v - __bfloat162float(h));
    }
}

// ============================================================================
// mma.sync GEMM body: C = A B^T + bias, 3-term bf16 split.
// 128x128 tile, BK=32, 2-stage cp.async, target 2 CTAs/SM.
// mode 0: fp32 natural out.  mode 1: bf16 hi/lo head-split out.
// ============================================================================
#define PADK 40
#define TILE_H (128 * PADK)
#define STAGE_H (4 * TILE_H)
#define KSTAGES (DD / 32)
#define GEMM_SMEM (2 * STAGE_H * 2)     // 81920 B

__device__ __forceinline__
void gemm_body(const __nv_bfloat16* __restrict__ Ah, const __nv_bfloat16* __restrict__ Al,
               const __nv_bfloat16* __restrict__ Bh, const __nv_bfloat16* __restrict__ Bl,
               const float* __restrict__ bias, float* __restrict__ OutF,
               __nv_bfloat16* __restrict__ OutH, __nv_bfloat16* __restrict__ OutL,
               int mode)
{
    extern __shared__ __nv_bfloat16 smb[];
    const uint32_t sb = smem_u32(smb);
    const int t = threadIdx.x, wid = t >> 5, lane = t & 31;
    const int m0 = blockIdx.y * 128, n0 = blockIdx.x * 128;
    const int wm = (wid >> 2) * 64, wn = (wid & 3) * 32;

    const __nv_bfloat16* srcs[4] = {
        Ah + (size_t)m0 * DD, Al + (size_t)m0 * DD,
        Bh + (size_t)n0 * DD, Bl + (size_t)n0 * DD };

    auto issue_stage = [&](int s, int buf) {
        uint32_t base = sb + buf * STAGE_H * 2;
#pragma unroll
        for (int p = 0; p < 8; p++) {
            int j = t + p * 256;              // 0..2047 16B chunks
            int tile = j >> 9;
            int c = j & 511;
            int row = c >> 2;
            int c16 = c & 3;
            const __nv_bfloat16* g =
                srcs[tile] + (size_t)row * DD + s * 32 + c16 * 8;
            uint32_t d = base + (tile * TILE_H + row * PADK + c16 * 8) * 2;
            CP_ASYNC16(d, g);
        }
        CP_COMMIT();
    };

    float acc[4][4][4];
#pragma unroll
    for (int i = 0; i < 4; i++)
#pragma unroll
        for (int j = 0; j < 4; j++)
#pragma unroll
            for (int r = 0; r < 4; r++) acc[i][j][r] = 0.f;

    issue_stage(0, 0);
    issue_stage(1, 1);

    for (int s = 0; s < KSTAGES; s++) {
        CP_WAIT1();
        __syncthreads();
        const uint32_t base = sb + (s & 1) * STAGE_H * 2;
#pragma unroll
        for (int kk = 0; kk < 2; kk++) {
            uint32_t ah[4][4], al[4][4], bh[2][4], bl[2][4];
#pragma unroll
            for (int i = 0; i < 4; i++) {
                int row = wm + i * 16 + (lane & 15);
                int col = kk * 16 + (lane >> 4) * 8;
                uint32_t ad = base + (row * PADK + col) * 2;
                LDSM4(ah[i][0], ah[i][1], ah[i][2], ah[i][3], ad);
                LDSM4(al[i][0], al[i][1], al[i][2], al[i][3], ad + TILE_H * 2);
            }
#pragma unroll
            for (int g = 0; g < 2; g++) {
                int row = wn + g * 16 + ((lane >> 4) & 1) * 8 + (lane & 7);
                int col = kk * 16 + ((lane >> 3) & 1) * 8;
                uint32_t bd = base + (2 * TILE_H + row * PADK + col) * 2;
                LDSM4(bh[g][0], bh[g][1], bh[g][2], bh[g][3], bd);
                LDSM4(bl[g][0], bl[g][1], bl[g][2], bl[g][3], bd + TILE_H * 2);
            }
#pragma unroll
            for (int i = 0; i < 4; i++)
#pragma unroll
                for (int j = 0; j < 4; j++) {
                    int g = j >> 1, o = (j & 1) * 2;
                    MMA16816(acc[i][j], ah[i], bh[g][o], bh[g][o + 1]);
                    MMA16816(acc[i][j], ah[i], bl[g][o], bl[g][o + 1]);
                    MMA16816(acc[i][j], al[i], bh[g][o], bh[g][o + 1]);
                }
        }
        __syncthreads();
        if (s + 2 < KSTAGES) issue_stage(s + 2, s & 1);
    }
    CP_WAIT0();

#pragma unroll
    for (int i = 0; i < 4; i++) {
        int grow = m0 + wm + i * 16 + (lane >> 2);
#pragma unroll
        for (int j = 0; j < 4; j++) {
            int gcol = n0 + wn + j * 8 + (lane & 3) * 2;
            float bx = __ldg(&bias[gcol]), by = __ldg(&bias[gcol + 1]);
            float x0 = acc[i][j][0] + bx, y0 = acc[i][j][1] + by;
            float x1 = acc[i][j][2] + bx, y1 = acc[i][j][3] + by;
            if (mode == 1) {
                int h = gcol >> 6, dh = gcol & 63;
                int b0r = grow >> 11, s0 = grow & 2047;
                size_t o0 = (((size_t)(b0r * HH + h) * SS) + s0) * DH + dh;
                int g1 = grow + 8;
                int b1r = g1 >> 11, s1 = g1 & 2047;
                size_t o1 = (((size_t)(b1r * HH + h) * SS) + s1) * DH + dh;
                uint32_t h0 = pack_hi(x0, y0), h1 = pack_hi(x1, y1);
                *(uint32_t*)&OutH[o0] = h0;
                *(uint32_t*)&OutL[o0] = pack_lo(x0, y0, h0);
                *(uint32_t*)&OutH[o1] = h1;
                *(uint32_t*)&OutL[o1] = pack_lo(x1, y1, h1);
            } else {
                *(float2*)&OutF[(size_t)grow * DD + gcol] = make_float2(x0, y0);
                *(float2*)&OutF[(size_t)(grow + 8) * DD + gcol] = make_float2(x1, y1);
            }
        }
    }
}

struct GemmPtrs3 {
    const __nv_bfloat16 *Ah[3], *Al[3], *Bh[3], *Bl[3];
    const float *bias[3];
    __nv_bfloat16 *OH[3], *OL[3];
};

// fused Q/K/V projection: blockIdx.z = which projection
__global__ __launch_bounds__(256, 2)
void gemm_mma3(GemmPtrs3 p)
{
    const int z = blockIdx.z;
    gemm_body(p.Ah[z], p.Al[z], p.Bh[z], p.Bl[z], p.bias[z],
              nullptr, p.OH[z], p.OL[z], 1);
}

// single GEMM, fp32 natural out (output projection)
__global__ __launch_bounds__(256, 2)
void gemm_mma1(const __nv_bfloat16* __restrict__ Ah, const __nv_bfloat16* __restrict__ Al,
               const __nv_bfloat16* __restrict__ Bh, const __nv_bfloat16* __restrict__ Bl,
               const float* __restrict__ bias, float* __restrict__ OutF)
{
    gemm_body(Ah, Al, Bh, Bl, bias, OutF, nullptr, nullptr, 0);
}

// ============================================================================
// Flash attention on mma.sync (R4-proven, unchanged)
// ============================================================================
#define APAD 72
#define KV_TILE_H (64 * APAD)
#define AT_STAGE_H (4 * KV_TILE_H)
#define AT_SMEM (2 * AT_STAGE_H * 2)   // 73728 B
#define NKT (SS / 64)

__global__ __launch_bounds__(256)
void attn_mma(const __nv_bfloat16* __restrict__ Qh, const __nv_bfloat16* __restrict__ Ql,
              const __nv_bfloat16* __restrict__ Kh, const __nv_bfloat16* __restrict__ Kl,
              const __nv_bfloat16* __restrict__ Vh, const __nv_bfloat16* __restrict__ Vl,
              __nv_bfloat16* __restrict__ OutH, __nv_bfloat16* __restrict__ OutL)
{
    extern __shared__ __nv_bfloat16 smb[];
    const uint32_t sb = smem_u32(smb);
    const int t = threadIdx.x, wid = t >> 5, lane = t & 31;
    const int bh = blockIdx.y;
    const int q0 = blockIdx.x * 128;
    const int wm = wid * 16;
    const size_t bhoff = (size_t)bh * SS * DH;

    {
        const __nv_bfloat16* qs[2] = {Qh + bhoff + (size_t)q0 * DH,
                                      Ql + bhoff + (size_t)q0 * DH};
#pragma unroll
        for (int p = 0; p < 8; p++) {
            int j = t + p * 256;
            int tile = j >> 10;
            int row = (j >> 3) & 127;
            int c16 = j & 7;
            uint32_t d = sb + (tile * 128 * APAD + row * APAD + c16 * 8) * 2;
            CP_ASYNC16(d, qs[tile] + (size_t)row * DH + c16 * 8);
        }
        CP_COMMIT();
        CP_WAIT0();
        __syncthreads();
    }

    uint32_t qh[4][4], ql[4][4];
#pragma unroll
    for (int kk = 0; kk < 4; kk++) {
        int row = wm + (lane & 15);
        int col = kk * 16 + (lane >> 4) * 8;
        uint32_t ad = sb + (row * APAD + col) * 2;
        LDSM4(qh[kk][0], qh[kk][1], qh[kk][2], qh[kk][3], ad);
        LDSM4(ql[kk][0], ql[kk][1], ql[kk][2], ql[kk][3], ad + 128 * APAD * 2);
    }
    __syncthreads();

    const __nv_bfloat16* kvsrc[4] = {Kh + bhoff, Kl + bhoff, Vh + bhoff, Vl + bhoff};
    auto issue_kv = [&](int kt, int buf) {
        uint32_t base = sb + buf * AT_STAGE_H * 2;
#pragma unroll
        for (int p = 0; p < 8; p++) {
            int j = t + p * 256;
            int tile = j >> 9;
            int row = (j >> 3) & 63;
            int c16 = j & 7;
            uint32_t d = base + (tile * KV_TILE_H + row * APAD + c16 * 8) * 2;
            CP_ASYNC16(d, kvsrc[tile] + (size_t)(kt * 64 + row) * DH + c16 * 8);
        }
        CP_COMMIT();
    };

    float o[8][4];
#pragma unroll
    for (int j = 0; j < 8; j++)
#pragma unroll
        for (int r = 0; r < 4; r++) o[j][r] = 0.f;
    float m_i[2] = {-INFINITY, -INFINITY};
    float l_i[2] = {0.f, 0.f};

    issue_kv(0, 0);
    issue_kv(1, 1);

    for (int kt = 0; kt < NKT; kt++) {
        CP_WAIT1();
        __syncthreads();
        const uint32_t base = sb + (kt & 1) * AT_STAGE_H * 2;

        float s[8][4];
#pragma unroll
        for (int j = 0; j < 8; j++)
#pragma unroll
            for (int r = 0; r < 4; r++) s[j][r] = 0.f;

#pragma unroll
        for (int kk = 0; kk < 4; kk++) {
            uint32_t kfh[4][4], kfl[4][4];
#pragma unroll
            for (int g = 0; g < 4; g++) {
                int row = g * 16 + ((lane >> 4) & 1) * 8 + (lane & 7);
                int col = kk * 16 + ((lane >> 3) & 1) * 8;
                uint32_t kd = base + (row * APAD + col) * 2;
                LDSM4(kfh[g][0], kfh[g][1], kfh[g][2], kfh[g][3], kd);
                LDSM4(kfl[g][0], kfl[g][1], kfl[g][2], kfl[g][3], kd + KV_TILE_H * 2);
            }
#pragma unroll
            for (int j = 0; j < 8; j++) {
                int g = j >> 1, oo = (j & 1) * 2;
                MMA16816(s[j], qh[kk], kfh[g][oo], kfh[g][oo + 1]);
                MMA16816(s[j], qh[kk], kfl[g][oo], kfl[g][oo + 1]);
                MMA16816(s[j], ql[kk], kfh[g][oo], kfh[g][oo + 1]);
            }
        }

        float mx[2] = {-INFINITY, -INFINITY};
#pragma unroll
        for (int j = 0; j < 8; j++) {
#pragma unroll
            for (int r = 0; r < 4; r++) s[j][r] *= 0.125f;
            mx[0] = fmaxf(mx[0], fmaxf(s[j][0], s[j][1]));
            mx[1] = fmaxf(mx[1], fmaxf(s[j][2], s[j][3]));
        }
#pragma unroll
        for (int r = 0; r < 2; r++) {
            mx[r] = fmaxf(mx[r], __shfl_xor_sync(0xffffffffu, mx[r], 1));
            mx[r] = fmaxf(mx[r], __shfl_xor_sync(0xffffffffu, mx[r], 2));
        }
        float mn[2], corr[2];
#pragma unroll
        for (int r = 0; r < 2; r++) {
            mn[r] = fmaxf(m_i[r], mx[r]);
            corr[r] = __expf(m_i[r] - mn[r]);
            m_i[r] = mn[r];
        }
        float rs[2] = {0.f, 0.f};
#pragma unroll
        for (int j = 0; j < 8; j++) {
            s[j][0] = __expf(s[j][0] - mn[0]);
            s[j][1] = __expf(s[j][1] - mn[0]);
            s[j][2] = __expf(s[j][2] - mn[1]);
            s[j][3] = __expf(s[j][3] - mn[1]);
            rs[0] += s[j][0] + s[j][1];
            rs[1] += s[j][2] + s[j][3];
        }
#pragma unroll
        for (int r = 0; r < 2; r++) {
            rs[r] += __shfl_xor_sync(0xffffffffu, rs[r], 1);
            rs[r] += __shfl_xor_sync(0xffffffffu, rs[r], 2);
            l_i[r] = l_i[r] * corr[r] + rs[r];
        }
#pragma unroll
        for (int j = 0; j < 8; j++) {
            o[j][0] *= corr[0]; o[j][1] *= corr[0];
            o[j][2] *= corr[1]; o[j][3] *= corr[1];
        }

#pragma unroll
        for (int kk = 0; kk < 4; kk++) {
            uint32_t aph[4], apl[4];
            aph[0] = pack_hi(s[2 * kk][0], s[2 * kk][1]);
            aph[1] = pack_hi(s[2 * kk][2], s[2 * kk][3]);
            aph[2] = pack_hi(s[2 * kk + 1][0], s[2 * kk + 1][1]);
            aph[3] = pack_hi(s[2 * kk + 1][2], s[2 * kk + 1][3]);
            apl[0] = pack_lo(s[2 * kk][0], s[2 * kk][1], aph[0]);
            apl[1] = pack_lo(s[2 * kk][2], s[2 * kk][3], aph[1]);
            apl[2] = pack_lo(s[2 * kk + 1][0], s[2 * kk + 1][1], aph[2]);
            apl[3] = pack_lo(s[2 * kk + 1][2], s[2 * kk + 1][3], aph[3]);

            uint32_t vfh[4][4], vfl[4][4];
#pragma unroll
            for (int g = 0; g < 4; g++) {
                int row = kk * 16 + (lane & 15);
                int col = g * 16 + (lane >> 4) * 8;
                uint32_t vd = base + (2 * KV_TILE_H + row * APAD + col) * 2;
                LDSM4T(vfh[g][0], vfh[g][1], vfh[g][2], vfh[g][3], vd);
                LDSM4T(vfl[g][0], vfl[g][1], vfl[g][2], vfl[g][3], vd + KV_TILE_H * 2);
            }
#pragma unroll
            for (int j = 0; j < 8; j++) {
                int g = j >> 1, oo = (j & 1) * 2;
                MMA16816(o[j], aph, vfh[g][oo], vfh[g][oo + 1]);
                MMA16816(o[j], aph, vfl[g][oo], vfl[g][oo + 1]);
                MMA16816(o[j], apl, vfh[g][oo], vfh[g][oo + 1]);
            }
        }
        __syncthreads();
        if (kt + 2 < NKT) issue_kv(kt + 2, kt & 1);
    }

    const int b = bh >> 4, h = bh & 15;
    const float inv0 = 1.f / l_i[0], inv1 = 1.f / l_i[1];
    const int srow0 = q0 + wm + (lane >> 2);
#pragma unroll
    for (int j = 0; j < 8; j++) {
        int dh = j * 8 + (lane & 3) * 2;
        int kcol = h * 64 + dh;
        size_t o0 = ((size_t)(b * SS + srow0)) * DD + kcol;
        size_t o1 = ((size_t)(b * SS + srow0 + 8)) * DD + kcol;
        float x0 = o[j][0] * inv0, y0 = o[j][1] * inv0;
        float x1 = o[j][2] * inv1, y1 = o[j][3] * inv1;
        uint32_t h0 = pack_hi(x0, y0), h1 = pack_hi(x1, y1);
        *(uint32_t*)&OutH[o0] = h0;
        *(uint32_t*)&OutL[o0] = pack_lo(x0, y0, h0);
        *(uint32_t*)&OutH[o1] = h1;
        *(uint32_t*)&OutL[o1] = pack_lo(x1, y1, h1);
    }
}

// ============================================================================
// launch
// ============================================================================
extern "C" void kernel_launch(void* const* d_in, const int* in_sizes, int n_in,
                              void* d_out, int out_size)
{
    const float* q   = (const float*)d_in[0];
    const float* k   = (const float*)d_in[1];
    const float* v   = (const float*)d_in[2];
    const float* w_q = (const float*)d_in[3];
    const float* b_q = (const float*)d_in[4];
    const float* w_k = (const float*)d_in[5];
    const float* b_k = (const float*)d_in[6];
    const float* w_v = (const float*)d_in[7];
    const float* b_v = (const float*)d_in[8];
    const float* w_o = (const float*)d_in[9];
    const float* b_o = (const float*)d_in[10];
    float* out = (float*)d_out;

    __nv_bfloat16 *pA0h, *pA0l, *pA1h, *pA1l, *pA2h, *pA2l;
    __nv_bfloat16 *pB0h, *pB0l, *pB1h, *pB1l, *pB2h, *pB2l, *pB3h, *pB3l;
    __nv_bfloat16 *pQh, *pQl, *pKh, *pKl, *pVh, *pVl;
    cudaGetSymbolAddress((void**)&pA0h, g_A0h);
    cudaGetSymbolAddress((void**)&pA0l, g_A0l);
    cudaGetSymbolAddress((void**)&pA1h, g_A1h);
    cudaGetSymbolAddress((void**)&pA1l, g_A1l);
    cudaGetSymbolAddress((void**)&pA2h, g_A2h);
    cudaGetSymbolAddress((void**)&pA2l, g_A2l);
    cudaGetSymbolAddress((void**)&pB0h, g_B0h);
    cudaGetSymbolAddress((void**)&pB0l, g_B0l);
    cudaGetSymbolAddress((void**)&pB1h, g_B1h);
    cudaGetSymbolAddress((void**)&pB1l, g_B1l);
    cudaGetSymbolAddress((void**)&pB2h, g_B2h);
    cudaGetSymbolAddress((void**)&pB2l, g_B2l);
    cudaGetSymbolAddress((void**)&pB3h, g_B3h);
    cudaGetSymbolAddress((void**)&pB3l, g_B3l);
    cudaGetSymbolAddress((void**)&pQh, g_Qh);
    cudaGetSymbolAddress((void**)&pQl, g_Ql);
    cudaGetSymbolAddress((void**)&pKh, g_Kh);
    cudaGetSymbolAddress((void**)&pKl, g_Kl);
    cudaGetSymbolAddress((void**)&pVh, g_Vh);
    cudaGetSymbolAddress((void**)&pVl, g_Vl);

    static int attr_set = 0;
    if (!attr_set) {
        cudaFuncSetAttribute(gemm_mma3,
                             cudaFuncAttributeMaxDynamicSharedMemorySize, GEMM_SMEM);
        cudaFuncSetAttribute(gemm_mma1,
                             cudaFuncAttributeMaxDynamicSharedMemorySize, GEMM_SMEM);
        cudaFuncSetAttribute(attn_mma,
                             cudaFuncAttributeMaxDynamicSharedMemorySize, AT_SMEM);
        attr_set = 1;
    }

    // 1. all input splits (q,k,v) in one launch
    dim3 gs(MM * DD / 4 / 256, 3);
    conv_split3<<<gs, 256>>>((const float4*)q, (const float4*)k, (const float4*)v,
                             pA0h, pA0l, pA1h, pA1l, pA2h, pA2l);
    // 2. all weight transposes in one launch
    dim3 gw(DD / 32, DD / 32, 4);
    conv_wT4<<<gw, dim3(32, 8)>>>(w_q, w_k, w_v, w_o,
                                  pB0h, pB0l, pB1h, pB1l,
                                  pB2h, pB2l, pB3h, pB3l);
    // 3. fused Q/K/V projections
    GemmPtrs3 gp;
    gp.Ah[0] = pA0h; gp.Al[0] = pA0l; gp.Bh[0] = pB0h; gp.Bl[0] = pB0l;
    gp.bias[0] = b_q; gp.OH[0] = pQh; gp.OL[0] = pQl;
    gp.Ah[1] = pA1h; gp.Al[1] = pA1l; gp.Bh[1] = pB1h; gp.Bl[1] = pB1l;
    gp.bias[1] = b_k; gp.OH[1] = pKh; gp.OL[1] = pKl;
    gp.Ah[2] = pA2h; gp.Al[2] = pA2l; gp.Bh[2] = pB2h; gp.Bl[2] = pB2l;
    gp.bias[2] = b_v; gp.OH[2] = pVh; gp.OL[2] = pVl;
    dim3 gg(DD / 128, MM / 128, 3);   // (8, 32, 3) = 768 CTAs
    gemm_mma3<<<gg, 256, GEMM_SMEM>>>(gp);

    // 4. attention -> writes out-proj A operands (A0)
    dim3 ga(SS / 128, BB * HH);       // (16, 32)
    attn_mma<<<ga, 256, AT_SMEM>>>(pQh, pQl, pKh, pKl, pVh, pVl, pA0h, pA0l);

    // 5. output projection -> fp32 natural
    dim3 g1(DD / 128, MM / 128);
    gemm_mma1<<<g1, 256, GEMM_SMEM>>>(pA0h, pA0l, pB3h, pB3l, b_o, out);
}

// round 6
// speedup vs baseline: 2.9156x; 1.0790x over previous
#include <cuda_runtime.h>
#include <cuda_bf16.h>
#include <math.h>
#include <stdint.h>

// Problem constants
#define BB 2
#define SS 2048
#define DD 1024
#define HH 16
#define DH 64
#define MM (BB * SS)   // 4096 rows

// -------------------- scratch (allocation-free rule: __device__ globals) ----
__device__ __nv_bfloat16 g_A0h[MM * DD];
__device__ __nv_bfloat16 g_A0l[MM * DD];
__device__ __nv_bfloat16 g_A1h[MM * DD];
__device__ __nv_bfloat16 g_A1l[MM * DD];
__device__ __nv_bfloat16 g_A2h[MM * DD];
__device__ __nv_bfloat16 g_A2l[MM * DD];
__device__ __nv_bfloat16 g_B0h[DD * DD];
__device__ __nv_bfloat16 g_B0l[DD * DD];
__device__ __nv_bfloat16 g_B1h[DD * DD];
__device__ __nv_bfloat16 g_B1l[DD * DD];
__device__ __nv_bfloat16 g_B2h[DD * DD];
__device__ __nv_bfloat16 g_B2l[DD * DD];
__device__ __nv_bfloat16 g_B3h[DD * DD];
__device__ __nv_bfloat16 g_B3l[DD * DD];
__device__ __nv_bfloat16 g_Qh[MM * DD];
__device__ __nv_bfloat16 g_Ql[MM * DD];
__device__ __nv_bfloat16 g_Kh[MM * DD];
__device__ __nv_bfloat16 g_Kl[MM * DD];
__device__ __nv_bfloat16 g_Vh[MM * DD];
__device__ __nv_bfloat16 g_Vl[MM * DD];

// ============================================================================
// helpers
// ============================================================================
__device__ __forceinline__ uint32_t smem_u32(const void* p) {
    uint32_t a;
    asm("{ .reg .u64 t; cvta.to.shared.u64 t, %1; cvt.u32.u64 %0, t; }"
        : "=r"(a) : "l"(p));
    return a;
}

#define LDSM4(r0, r1, r2, r3, addr)                                            \
    asm volatile("ldmatrix.sync.aligned.m8n8.x4.shared.b16 {%0,%1,%2,%3}, [%4];" \
                 : "=r"(r0), "=r"(r1), "=r"(r2), "=r"(r3) : "r"(addr))
#define LDSM4T(r0, r1, r2, r3, addr)                                           \
    asm volatile("ldmatrix.sync.aligned.m8n8.x4.trans.shared.b16 {%0,%1,%2,%3}, [%4];" \
                 : "=r"(r0), "=r"(r1), "=r"(r2), "=r"(r3) : "r"(addr))

#define MMA16816(d, a, b0, b1)                                                 \
    asm volatile("mma.sync.aligned.m16n8k16.row.col.f32.bf16.bf16.f32 "        \
                 "{%0,%1,%2,%3}, {%4,%5,%6,%7}, {%8,%9}, {%0,%1,%2,%3};"       \
                 : "+f"((d)[0]), "+f"((d)[1]), "+f"((d)[2]), "+f"((d)[3])      \
                 : "r"((a)[0]), "r"((a)[1]), "r"((a)[2]), "r"((a)[3]),         \
                   "r"(b0), "r"(b1))

#define CP_ASYNC16(dst, src)                                                   \
    asm volatile("cp.async.cg.shared.global [%0], [%1], 16;" :: "r"(dst), "l"(src))
#define CP_COMMIT()  asm volatile("cp.async.commit_group;" ::: "memory")
#define CP_WAIT1()   asm volatile("cp.async.wait_group 1;" ::: "memory")
#define CP_WAIT0()   asm volatile("cp.async.wait_group 0;" ::: "memory")

__device__ __forceinline__ uint32_t pack_hi(float x, float y) {
    __nv_bfloat162 h = __floats2bfloat162_rn(x, y);
    return *(uint32_t*)&h;
}
__device__ __forceinline__ uint32_t pack_lo(float x, float y, uint32_t hbits) {
    __nv_bfloat162 h = *(__nv_bfloat162*)&hbits;
    __nv_bfloat162 l = __floats2bfloat162_rn(x - __bfloat162float(h.x),
                                             y - __bfloat162float(h.y));
    return *(uint32_t*)&l;
}

// ============================================================================
// fused conversion kernels
// ============================================================================
__global__ __launch_bounds__(256)
void conv_split3(const float4* __restrict__ q, const float4* __restrict__ k,
                 const float4* __restrict__ v,
                 __nv_bfloat16* __restrict__ a0h, __nv_bfloat16* __restrict__ a0l,
                 __nv_bfloat16* __restrict__ a1h, __nv_bfloat16* __restrict__ a1l,
                 __nv_bfloat16* __restrict__ a2h, __nv_bfloat16* __restrict__ a2l)
{
    const int z = blockIdx.y;
    const float4* src = (z == 0) ? q : (z == 1) ? k : v;
    __nv_bfloat16* hi = (z == 0) ? a0h : (z == 1) ? a1h : a2h;
    __nv_bfloat16* lo = (z == 0) ? a0l : (z == 1) ? a1l : a2l;
    int i = blockIdx.x * 256 + threadIdx.x;
    float4 val = src[i];
    uint32_t h0 = pack_hi(val.x, val.y), h1 = pack_hi(val.z, val.w);
    uint32_t l0 = pack_lo(val.x, val.y, h0), l1 = pack_lo(val.z, val.w, h1);
    ((uint32_t*)hi)[i * 2 + 0] = h0;
    ((uint32_t*)hi)[i * 2 + 1] = h1;
    ((uint32_t*)lo)[i * 2 + 0] = l0;
    ((uint32_t*)lo)[i * 2 + 1] = l1;
}

__global__ __launch_bounds__(256)
void conv_wT4(const float* __restrict__ w0, const float* __restrict__ w1,
              const float* __restrict__ w2, const float* __restrict__ w3,
              __nv_bfloat16* __restrict__ b0h, __nv_bfloat16* __restrict__ b0l,
              __nv_bfloat16* __restrict__ b1h, __nv_bfloat16* __restrict__ b1l,
              __nv_bfloat16* __restrict__ b2h, __nv_bfloat16* __restrict__ b2l,
              __nv_bfloat16* __restrict__ b3h, __nv_bfloat16* __restrict__ b3l)
{
    const int z = blockIdx.z;
    const float* W = (z == 0) ? w0 : (z == 1) ? w1 : (z == 2) ? w2 : w3;
    __nv_bfloat16* hi = (z == 0) ? b0h : (z == 1) ? b1h : (z == 2) ? b2h : b3h;
    __nv_bfloat16* lo = (z == 0) ? b0l : (z == 1) ? b1l : (z == 2) ? b2l : b3l;

    __shared__ float t[32][33];
    int n0 = blockIdx.x * 32, k0 = blockIdx.y * 32;
    int tx = threadIdx.x, ty = threadIdx.y;   // block (32,8)
#pragma unroll
    for (int i = 0; i < 32; i += 8)
        t[ty + i][tx] = W[(size_t)(k0 + ty + i) * DD + n0 + tx];
    __syncthreads();
#pragma unroll
    for (int i = 0; i < 32; i += 8) {
        float v = t[tx][ty + i];
        __nv_bfloat16 h = __float2bfloat16_rn(v);
        size_t o = (size_t)(n0 + ty + i) * DD + k0 + tx;
        hi[o] = h;
        lo[o] = __float2bfloat16_rn(v - __bfloat162float(h));
    }
}

// ============================================================================
// mma.sync GEMM body (R5-proven, unchanged)
// ============================================================================
#define PADK 40
#define TILE_H (128 * PADK)
#define STAGE_H (4 * TILE_H)
#define KSTAGES (DD / 32)
#define GEMM_SMEM (2 * STAGE_H * 2)     // 81920 B

__device__ __forceinline__
void gemm_body(const __nv_bfloat16* __restrict__ Ah, const __nv_bfloat16* __restrict__ Al,
               const __nv_bfloat16* __restrict__ Bh, const __nv_bfloat16* __restrict__ Bl,
               const float* __restrict__ bias, float* __restrict__ OutF,
               __nv_bfloat16* __restrict__ OutH, __nv_bfloat16* __restrict__ OutL,
               int mode)
{
    extern __shared__ __nv_bfloat16 smb[];
    const uint32_t sb = smem_u32(smb);
    const int t = threadIdx.x, wid = t >> 5, lane = t & 31;
    const int m0 = blockIdx.y * 128, n0 = blockIdx.x * 128;
    const int wm = (wid >> 2) * 64, wn = (wid & 3) * 32;

    const __nv_bfloat16* srcs[4] = {
        Ah + (size_t)m0 * DD, Al + (size_t)m0 * DD,
        Bh + (size_t)n0 * DD, Bl + (size_t)n0 * DD };

    auto issue_stage = [&](int s, int buf) {
        uint32_t base = sb + buf * STAGE_H * 2;
#pragma unroll
        for (int p = 0; p < 8; p++) {
            int j = t + p * 256;
            int tile = j >> 9;
            int c = j & 511;
            int row = c >> 2;
            int c16 = c & 3;
            const __nv_bfloat16* g =
                srcs[tile] + (size_t)row * DD + s * 32 + c16 * 8;
            uint32_t d = base + (tile * TILE_H + row * PADK + c16 * 8) * 2;
            CP_ASYNC16(d, g);
        }
        CP_COMMIT();
    };

    float acc[4][4][4];
#pragma unroll
    for (int i = 0; i < 4; i++)
#pragma unroll
        for (int j = 0; j < 4; j++)
#pragma unroll
            for (int r = 0; r < 4; r++) acc[i][j][r] = 0.f;

    issue_stage(0, 0);
    issue_stage(1, 1);

    for (int s = 0; s < KSTAGES; s++) {
        CP_WAIT1();
        __syncthreads();
        const uint32_t base = sb + (s & 1) * STAGE_H * 2;
#pragma unroll
        for (int kk = 0; kk < 2; kk++) {
            uint32_t ah[4][4], al[4][4], bh[2][4], bl[2][4];
#pragma unroll
            for (int i = 0; i < 4; i++) {
                int row = wm + i * 16 + (lane & 15);
                int col = kk * 16 + (lane >> 4) * 8;
                uint32_t ad = base + (row * PADK + col) * 2;
                LDSM4(ah[i][0], ah[i][1], ah[i][2], ah[i][3], ad);
                LDSM4(al[i][0], al[i][1], al[i][2], al[i][3], ad + TILE_H * 2);
            }
#pragma unroll
            for (int g = 0; g < 2; g++) {
                int row = wn + g * 16 + ((lane >> 4) & 1) * 8 + (lane & 7);
                int col = kk * 16 + ((lane >> 3) & 1) * 8;
                uint32_t bd = base + (2 * TILE_H + row * PADK + col) * 2;
                LDSM4(bh[g][0], bh[g][1], bh[g][2], bh[g][3], bd);
                LDSM4(bl[g][0], bl[g][1], bl[g][2], bl[g][3], bd + TILE_H * 2);
            }
#pragma unroll
            for (int i = 0; i < 4; i++)
#pragma unroll
                for (int j = 0; j < 4; j++) {
                    int g = j >> 1, o = (j & 1) * 2;
                    MMA16816(acc[i][j], ah[i], bh[g][o], bh[g][o + 1]);
                    MMA16816(acc[i][j], ah[i], bl[g][o], bl[g][o + 1]);
                    MMA16816(acc[i][j], al[i], bh[g][o], bh[g][o + 1]);
                }
        }
        __syncthreads();
        if (s + 2 < KSTAGES) issue_stage(s + 2, s & 1);
    }
    CP_WAIT0();

#pragma unroll
    for (int i = 0; i < 4; i++) {
        int grow = m0 + wm + i * 16 + (lane >> 2);
#pragma unroll
        for (int j = 0; j < 4; j++) {
            int gcol = n0 + wn + j * 8 + (lane & 3) * 2;
            float bx = __ldg(&bias[gcol]), by = __ldg(&bias[gcol + 1]);
            float x0 = acc[i][j][0] + bx, y0 = acc[i][j][1] + by;
            float x1 = acc[i][j][2] + bx, y1 = acc[i][j][3] + by;
            if (mode == 1) {
                int h = gcol >> 6, dh = gcol & 63;
                int b0r = grow >> 11, s0 = grow & 2047;
                size_t o0 = (((size_t)(b0r * HH + h) * SS) + s0) * DH + dh;
                int g1 = grow + 8;
                int b1r = g1 >> 11, s1 = g1 & 2047;
                size_t o1 = (((size_t)(b1r * HH + h) * SS) + s1) * DH + dh;
                uint32_t h0 = pack_hi(x0, y0), h1 = pack_hi(x1, y1);
                *(uint32_t*)&OutH[o0] = h0;
                *(uint32_t*)&OutL[o0] = pack_lo(x0, y0, h0);
                *(uint32_t*)&OutH[o1] = h1;
                *(uint32_t*)&OutL[o1] = pack_lo(x1, y1, h1);
            } else {
                *(float2*)&OutF[(size_t)grow * DD + gcol] = make_float2(x0, y0);
                *(float2*)&OutF[(size_t)(grow + 8) * DD + gcol] = make_float2(x1, y1);
            }
        }
    }
}

struct GemmPtrs3 {
    const __nv_bfloat16 *Ah[3], *Al[3], *Bh[3], *Bl[3];
    const float *bias[3];
    __nv_bfloat16 *OH[3], *OL[3];
};

__global__ __launch_bounds__(256, 2)
void gemm_mma3(GemmPtrs3 p)
{
    const int z = blockIdx.z;
    gemm_body(p.Ah[z], p.Al[z], p.Bh[z], p.Bl[z], p.bias[z],
              nullptr, p.OH[z], p.OL[z], 1);
}

__global__ __launch_bounds__(256, 2)
void gemm_mma1(const __nv_bfloat16* __restrict__ Ah, const __nv_bfloat16* __restrict__ Al,
               const __nv_bfloat16* __restrict__ Bh, const __nv_bfloat16* __restrict__ Bl,
               const float* __restrict__ bias, float* __restrict__ OutF)
{
    gemm_body(Ah, Al, Bh, Bl, bias, OutF, nullptr, nullptr, 0);
}

// ============================================================================
// Flash attention on mma.sync.
// NEW: 128 threads (4 warps), q-tile 64, target 3 CTAs/SM (12 warps).
// Per-warp layout unchanged from R4/R5 (16 rows x full 64-wide tile).
// ============================================================================
#define APAD 72
#define KV_TILE_H (64 * APAD)
#define AT_STAGE_H (4 * KV_TILE_H)
#define AT_SMEM (2 * AT_STAGE_H * 2)   // 73728 B
#define NKT (SS / 64)

__global__ __launch_bounds__(128, 3)
void attn_mma(const __nv_bfloat16* __restrict__ Qh, const __nv_bfloat16* __restrict__ Ql,
              const __nv_bfloat16* __restrict__ Kh, const __nv_bfloat16* __restrict__ Kl,
              const __nv_bfloat16* __restrict__ Vh, const __nv_bfloat16* __restrict__ Vl,
              __nv_bfloat16* __restrict__ OutH, __nv_bfloat16* __restrict__ OutL)
{
    extern __shared__ __nv_bfloat16 smb[];
    const uint32_t sb = smem_u32(smb);
    const int t = threadIdx.x, wid = t >> 5, lane = t & 31;
    const int bh = blockIdx.y;
    const int q0 = blockIdx.x * 64;
    const int wm = wid * 16;
    const size_t bhoff = (size_t)bh * SS * DH;

    // ---- stage Q tile: 2 x (64 rows x 8 chunks) = 1024 chunks ----
    {
        const __nv_bfloat16* qs[2] = {Qh + bhoff + (size_t)q0 * DH,
                                      Ql + bhoff + (size_t)q0 * DH};
#pragma unroll
        for (int p = 0; p < 8; p++) {
            int j = t + p * 128;
            int tile = j >> 9;
            int row = (j >> 3) & 63;
            int c16 = j & 7;
            uint32_t d = sb + (tile * 64 * APAD + row * APAD + c16 * 8) * 2;
            CP_ASYNC16(d, qs[tile] + (size_t)row * DH + c16 * 8);
        }
        CP_COMMIT();
        CP_WAIT0();
        __syncthreads();
    }

    uint32_t qh[4][4], ql[4][4];
#pragma unroll
    for (int kk = 0; kk < 4; kk++) {
        int row = wm + (lane & 15);
        int col = kk * 16 + (lane >> 4) * 8;
        uint32_t ad = sb + (row * APAD + col) * 2;
        LDSM4(qh[kk][0], qh[kk][1], qh[kk][2], qh[kk][3], ad);
        LDSM4(ql[kk][0], ql[kk][1], ql[kk][2], ql[kk][3], ad + 64 * APAD * 2);
    }
    __syncthreads();

    const __nv_bfloat16* kvsrc[4] = {Kh + bhoff, Kl + bhoff, Vh + bhoff, Vl + bhoff};
    auto issue_kv = [&](int kt, int buf) {
        uint32_t base = sb + buf * AT_STAGE_H * 2;
#pragma unroll
        for (int p = 0; p < 16; p++) {
            int j = t + p * 128;          // 0..2047
            int tile = j >> 9;
            int row = (j >> 3) & 63;
            int c16 = j & 7;
            uint32_t d = base + (tile * KV_TILE_H + row * APAD + c16 * 8) * 2;
            CP_ASYNC16(d, kvsrc[tile] + (size_t)(kt * 64 + row) * DH + c16 * 8);
        }
        CP_COMMIT();
    };

    float o[8][4];
#pragma unroll
    for (int j = 0; j < 8; j++)
#pragma unroll
        for (int r = 0; r < 4; r++) o[j][r] = 0.f;
    float m_i[2] = {-INFINITY, -INFINITY};
    float l_i[2] = {0.f, 0.f};

    issue_kv(0, 0);
    issue_kv(1, 1);

    for (int kt = 0; kt < NKT; kt++) {
        CP_WAIT1();
        __syncthreads();
        const uint32_t base = sb + (kt & 1) * AT_STAGE_H * 2;

        float s[8][4];
#pragma unroll
        for (int j = 0; j < 8; j++)
#pragma unroll
            for (int r = 0; r < 4; r++) s[j][r] = 0.f;

#pragma unroll
        for (int kk = 0; kk < 4; kk++) {
            uint32_t kfh[4][4], kfl[4][4];
#pragma unroll
            for (int g = 0; g < 4; g++) {
                int row = g * 16 + ((lane >> 4) & 1) * 8 + (lane & 7);
                int col = kk * 16 + ((lane >> 3) & 1) * 8;
                uint32_t kd = base + (row * APAD + col) * 2;
                LDSM4(kfh[g][0], kfh[g][1], kfh[g][2], kfh[g][3], kd);
                LDSM4(kfl[g][0], kfl[g][1], kfl[g][2], kfl[g][3], kd + KV_TILE_H * 2);
            }
#pragma unroll
            for (int j = 0; j < 8; j++) {
                int g = j >> 1, oo = (j & 1) * 2;
                MMA16816(s[j], qh[kk], kfh[g][oo], kfh[g][oo + 1]);
                MMA16816(s[j], qh[kk], kfl[g][oo], kfl[g][oo + 1]);
                MMA16816(s[j], ql[kk], kfh[g][oo], kfh[g][oo + 1]);
            }
        }

        float mx[2] = {-INFINITY, -INFINITY};
#pragma unroll
        for (int j = 0; j < 8; j++) {
#pragma unroll
            for (int r = 0; r < 4; r++) s[j][r] *= 0.125f;
            mx[0] = fmaxf(mx[0], fmaxf(s[j][0], s[j][1]));
            mx[1] = fmaxf(mx[1], fmaxf(s[j][2], s[j][3]));
        }
#pragma unroll
        for (int r = 0; r < 2; r++) {
            mx[r] = fmaxf(mx[r], __shfl_xor_sync(0xffffffffu, mx[r], 1));
            mx[r] = fmaxf(mx[r], __shfl_xor_sync(0xffffffffu, mx[r], 2));
        }
        float mn[2], corr[2];
#pragma unroll
        for (int r = 0; r < 2; r++) {
            mn[r] = fmaxf(m_i[r], mx[r]);
            corr[r] = __expf(m_i[r] - mn[r]);
            m_i[r] = mn[r];
        }
        float rs[2] = {0.f, 0.f};
#pragma unroll
        for (int j = 0; j < 8; j++) {
            s[j][0] = __expf(s[j][0] - mn[0]);
            s[j][1] = __expf(s[j][1] - mn[0]);
            s[j][2] = __expf(s[j][2] - mn[1]);
            s[j][3] = __expf(s[j][3] - mn[1]);
            rs[0] += s[j][0] + s[j][1];
            rs[1] += s[j][2] + s[j][3];
        }
#pragma unroll
        for (int r = 0; r < 2; r++) {
            rs[r] += __shfl_xor_sync(0xffffffffu, rs[r], 1);
            rs[r] += __shfl_xor_sync(0xffffffffu, rs[r], 2);
            l_i[r] = l_i[r] * corr[r] + rs[r];
        }
#pragma unroll
        for (int j = 0; j < 8; j++) {
            o[j][0] *= corr[0]; o[j][1] *= corr[0];
            o[j][2] *= corr[1]; o[j][3] *= corr[1];
        }

#pragma unroll
        for (int kk = 0; kk < 4; kk++) {
            uint32_t aph[4], apl[4];
            aph[0] = pack_hi(s[2 * kk][0], s[2 * kk][1]);
            aph[1] = pack_hi(s[2 * kk][2], s[2 * kk][3]);
            aph[2] = pack_hi(s[2 * kk + 1][0], s[2 * kk + 1][1]);
            aph[3] = pack_hi(s[2 * kk + 1][2], s[2 * kk + 1][3]);
            apl[0] = pack_lo(s[2 * kk][0], s[2 * kk][1], aph[0]);
            apl[1] = pack_lo(s[2 * kk][2], s[2 * kk][3], aph[1]);
            apl[2] = pack_lo(s[2 * kk + 1][0], s[2 * kk + 1][1], aph[2]);
            apl[3] = pack_lo(s[2 * kk + 1][2], s[2 * kk + 1][3], aph[3]);

            uint32_t vfh[4][4], vfl[4][4];
#pragma unroll
            for (int g = 0; g < 4; g++) {
                int row = kk * 16 + (lane & 15);
                int col = g * 16 + (lane >> 4) * 8;
                uint32_t vd = base + (2 * KV_TILE_H + row * APAD + col) * 2;
                LDSM4T(vfh[g][0], vfh[g][1], vfh[g][2], vfh[g][3], vd);
                LDSM4T(vfl[g][0], vfl[g][1], vfl[g][2], vfl[g][3], vd + KV_TILE_H * 2);
            }
#pragma unroll
            for (int j = 0; j < 8; j++) {
                int g = j >> 1, oo = (j & 1) * 2;
                MMA16816(o[j], aph, vfh[g][oo], vfh[g][oo + 1]);
                MMA16816(o[j], aph, vfl[g][oo], vfl[g][oo + 1]);
                MMA16816(o[j], apl, vfh[g][oo], vfh[g][oo + 1]);
            }
        }
        __syncthreads();
        if (kt + 2 < NKT) issue_kv(kt + 2, kt & 1);
    }

    const int b = bh >> 4, h = bh & 15;
    const float inv0 = 1.f / l_i[0], inv1 = 1.f / l_i[1];
    const int srow0 = q0 + wm + (lane >> 2);
#pragma unroll
    for (int j = 0; j < 8; j++) {
        int dh = j * 8 + (lane & 3) * 2;
        int kcol = h * 64 + dh;
        size_t o0 = ((size_t)(b * SS + srow0)) * DD + kcol;
        size_t o1 = ((size_t)(b * SS + srow0 + 8)) * DD + kcol;
        float x0 = o[j][0] * inv0, y0 = o[j][1] * inv0;
        float x1 = o[j][2] * inv1, y1 = o[j][3] * inv1;
        uint32_t h0 = pack_hi(x0, y0), h1 = pack_hi(x1, y1);
        *(uint32_t*)&OutH[o0] = h0;
        *(uint32_t*)&OutL[o0] = pack_lo(x0, y0, h0);
        *(uint32_t*)&OutH[o1] = h1;
        *(uint32_t*)&OutL[o1] = pack_lo(x1, y1, h1);
    }
}

// ============================================================================
// launch
// ============================================================================
extern "C" void kernel_launch(void* const* d_in, const int* in_sizes, int n_in,
                              void* d_out, int out_size)
{
    const float* q   = (const float*)d_in[0];
    const float* k   = (const float*)d_in[1];
    const float* v   = (const float*)d_in[2];
    const float* w_q = (const float*)d_in[3];
    const float* b_q = (const float*)d_in[4];
    const float* w_k = (const float*)d_in[5];
    const float* b_k = (const float*)d_in[6];
    const float* w_v = (const float*)d_in[7];
    const float* b_v = (const float*)d_in[8];
    const float* w_o = (const float*)d_in[9];
    const float* b_o = (const float*)d_in[10];
    float* out = (float*)d_out;

    __nv_bfloat16 *pA0h, *pA0l, *pA1h, *pA1l, *pA2h, *pA2l;
    __nv_bfloat16 *pB0h, *pB0l, *pB1h, *pB1l, *pB2h, *pB2l, *pB3h, *pB3l;
    __nv_bfloat16 *pQh, *pQl, *pKh, *pKl, *pVh, *pVl;
    cudaGetSymbolAddress((void**)&pA0h, g_A0h);
    cudaGetSymbolAddress((void**)&pA0l, g_A0l);
    cudaGetSymbolAddress((void**)&pA1h, g_A1h);
    cudaGetSymbolAddress((void**)&pA1l, g_A1l);
    cudaGetSymbolAddress((void**)&pA2h, g_A2h);
    cudaGetSymbolAddress((void**)&pA2l, g_A2l);
    cudaGetSymbolAddress((void**)&pB0h, g_B0h);
    cudaGetSymbolAddress((void**)&pB0l, g_B0l);
    cudaGetSymbolAddress((void**)&pB1h, g_B1h);
    cudaGetSymbolAddress((void**)&pB1l, g_B1l);
    cudaGetSymbolAddress((void**)&pB2h, g_B2h);
    cudaGetSymbolAddress((void**)&pB2l, g_B2l);
    cudaGetSymbolAddress((void**)&pB3h, g_B3h);
    cudaGetSymbolAddress((void**)&pB3l, g_B3l);
    cudaGetSymbolAddress((void**)&pQh, g_Qh);
    cudaGetSymbolAddress((void**)&pQl, g_Ql);
    cudaGetSymbolAddress((void**)&pKh, g_Kh);
    cudaGetSymbolAddress((void**)&pKl, g_Kl);
    cudaGetSymbolAddress((void**)&pVh, g_Vh);
    cudaGetSymbolAddress((void**)&pVl, g_Vl);

    static int attr_set = 0;
    if (!attr_set) {
        cudaFuncSetAttribute(gemm_mma3,
                             cudaFuncAttributeMaxDynamicSharedMemorySize, GEMM_SMEM);
        cudaFuncSetAttribute(gemm_mma1,
                             cudaFuncAttributeMaxDynamicSharedMemorySize, GEMM_SMEM);
        cudaFuncSetAttribute(attn_mma,
                             cudaFuncAttributeMaxDynamicSharedMemorySize, AT_SMEM);
        attr_set = 1;
    }

    dim3 gs(MM * DD / 4 / 256, 3);
    conv_split3<<<gs, 256>>>((const float4*)q, (const float4*)k, (const float4*)v,
                             pA0h, pA0l, pA1h, pA1l, pA2h, pA2l);
    dim3 gw(DD / 32, DD / 32, 4);
    conv_wT4<<<gw, dim3(32, 8)>>>(w_q, w_k, w_v, w_o,
                                  pB0h, pB0l, pB1h, pB1l,
                                  pB2h, pB2l, pB3h, pB3l);
    GemmPtrs3 gp;
    gp.Ah[0] = pA0h; gp.Al[0] = pA0l; gp.Bh[0] = pB0h; gp.Bl[0] = pB0l;
    gp.bias[0] = b_q; gp.OH[0] = pQh; gp.OL[0] = pQl;
    gp.Ah[1] = pA1h; gp.Al[1] = pA1l; gp.Bh[1] = pB1h; gp.Bl[1] = pB1l;
    gp.bias[1] = b_k; gp.OH[1] = pKh; gp.OL[1] = pKl;
    gp.Ah[2] = pA2h; gp.Al[2] = pA2l; gp.Bh[2] = pB2h; gp.Bl[2] = pB2l;
    gp.bias[2] = b_v; gp.OH[2] = pVh; gp.OL[2] = pVl;
    dim3 gg(DD / 128, MM / 128, 3);   // (8, 32, 3)
    gemm_mma3<<<gg, 256, GEMM_SMEM>>>(gp);

    // attention: 64-row q-tiles, 128-thread CTAs, 3 CTAs/SM target
    dim3 ga(SS / 64, BB * HH);        // (32, 32) = 1024 CTAs
    attn_mma<<<ga, 128, AT_SMEM>>>(pQh, pQl, pKh, pKl, pVh, pVl, pA0h, pA0l);

    dim3 g1(DD / 128, MM / 128);
    gemm_mma1<<<g1, 256, GEMM_SMEM>>>(pA0h, pA0l, pB3h, pB3l, b_o, out);
}

// round 7
// speedup vs baseline: 3.6078x; 1.2374x over previous
#include <cuda_runtime.h>
#include <cuda_bf16.h>
#include <cuda_fp16.h>
#include <math.h>
#include <stdint.h>

// Problem constants
#define BB 2
#define SS 2048
#define DD 1024
#define HH 16
#define DH 64
#define MM (BB * SS)   // 4096 rows

// -------------------- scratch (allocation-free rule: __device__ globals) ----
__device__ __nv_bfloat16 g_A0h[MM * DD];
__device__ __nv_bfloat16 g_A0l[MM * DD];
__device__ __nv_bfloat16 g_A1h[MM * DD];
__device__ __nv_bfloat16 g_A1l[MM * DD];
__device__ __nv_bfloat16 g_A2h[MM * DD];
__device__ __nv_bfloat16 g_A2l[MM * DD];
__device__ __nv_bfloat16 g_B0h[DD * DD];
__device__ __nv_bfloat16 g_B0l[DD * DD];
__device__ __nv_bfloat16 g_B1h[DD * DD];
__device__ __nv_bfloat16 g_B1l[DD * DD];
__device__ __nv_bfloat16 g_B2h[DD * DD];
__device__ __nv_bfloat16 g_B2l[DD * DD];
__device__ __nv_bfloat16 g_B3h[DD * DD];
__device__ __nv_bfloat16 g_B3l[DD * DD];
// attention operands, head-split [B*H][S][DH], fp16
__device__ __half g_Qf[MM * DD];
__device__ __half g_Kf[MM * DD];
__device__ __half g_Vhf[MM * DD];
__device__ __half g_Vlf[MM * DD];

// ============================================================================
// helpers
// ============================================================================
__device__ __forceinline__ uint32_t smem_u32(const void* p) {
    uint32_t a;
    asm("{ .reg .u64 t; cvta.to.shared.u64 t, %1; cvt.u32.u64 %0, t; }"
        : "=r"(a) : "l"(p));
    return a;
}

#define LDSM4(r0, r1, r2, r3, addr)                                            \
    asm volatile("ldmatrix.sync.aligned.m8n8.x4.shared.b16 {%0,%1,%2,%3}, [%4];" \
                 : "=r"(r0), "=r"(r1), "=r"(r2), "=r"(r3) : "r"(addr))
#define LDSM4T(r0, r1, r2, r3, addr)                                           \
    asm volatile("ldmatrix.sync.aligned.m8n8.x4.trans.shared.b16 {%0,%1,%2,%3}, [%4];" \
                 : "=r"(r0), "=r"(r1), "=r"(r2), "=r"(r3) : "r"(addr))

#define MMA16816(d, a, b0, b1)                                                 \
    asm volatile("mma.sync.aligned.m16n8k16.row.col.f32.bf16.bf16.f32 "        \
                 "{%0,%1,%2,%3}, {%4,%5,%6,%7}, {%8,%9}, {%0,%1,%2,%3};"       \
                 : "+f"((d)[0]), "+f"((d)[1]), "+f"((d)[2]), "+f"((d)[3])      \
                 : "r"((a)[0]), "r"((a)[1]), "r"((a)[2]), "r"((a)[3]),         \
                   "r"(b0), "r"(b1))

#define MMAF16(d, a, b0, b1)                                                   \
    asm volatile("mma.sync.aligned.m16n8k16.row.col.f32.f16.f16.f32 "          \
                 "{%0,%1,%2,%3}, {%4,%5,%6,%7}, {%8,%9}, {%0,%1,%2,%3};"       \
                 : "+f"((d)[0]), "+f"((d)[1]), "+f"((d)[2]), "+f"((d)[3])      \
                 : "r"((a)[0]), "r"((a)[1]), "r"((a)[2]), "r"((a)[3]),         \
                   "r"(b0), "r"(b1))

#define CP_ASYNC16(dst, src)                                                   \
    asm volatile("cp.async.cg.shared.global [%0], [%1], 16;" :: "r"(dst), "l"(src))
#define CP_COMMIT()  asm volatile("cp.async.commit_group;" ::: "memory")
#define CP_WAIT1()   asm volatile("cp.async.wait_group 1;" ::: "memory")
#define CP_WAIT0()   asm volatile("cp.async.wait_group 0;" ::: "memory")

__device__ __forceinline__ uint32_t pack_hi(float x, float y) {
    __nv_bfloat162 h = __floats2bfloat162_rn(x, y);
    return *(uint32_t*)&h;
}
__device__ __forceinline__ uint32_t pack_lo(float x, float y, uint32_t hbits) {
    __nv_bfloat162 h = *(__nv_bfloat162*)&hbits;
    __nv_bfloat162 l = __floats2bfloat162_rn(x - __bfloat162float(h.x),
                                             y - __bfloat162float(h.y));
    return *(uint32_t*)&l;
}
__device__ __forceinline__ uint32_t pack_h2(float x, float y) {
    __half2 h = __floats2half2_rn(x, y);
    return *(uint32_t*)&h;
}
__device__ __forceinline__ uint32_t pack_h2lo(float x, float y, uint32_t hbits) {
    __half2 h = *(__half2*)&hbits;
    __half2 l = __floats2half2_rn(x - __half2float(h.x),
                                  y - __half2float(h.y));
    return *(uint32_t*)&l;
}

// ============================================================================
// fused conversion kernels (A/B operands for bf16 3-term GEMMs)
// ============================================================================
__global__ __launch_bounds__(256)
void conv_split3(const float4* __restrict__ q, const float4* __restrict__ k,
                 const float4* __restrict__ v,
                 __nv_bfloat16* __restrict__ a0h, __nv_bfloat16* __restrict__ a0l,
                 __nv_bfloat16* __restrict__ a1h, __nv_bfloat16* __restrict__ a1l,
                 __nv_bfloat16* __restrict__ a2h, __nv_bfloat16* __restrict__ a2l)
{
    const int z = blockIdx.y;
    const float4* src = (z == 0) ? q : (z == 1) ? k : v;
    __nv_bfloat16* hi = (z == 0) ? a0h : (z == 1) ? a1h : a2h;
    __nv_bfloat16* lo = (z == 0) ? a0l : (z == 1) ? a1l : a2l;
    int i = blockIdx.x * 256 + threadIdx.x;
    float4 val = src[i];
    uint32_t h0 = pack_hi(val.x, val.y), h1 = pack_hi(val.z, val.w);
    uint32_t l0 = pack_lo(val.x, val.y, h0), l1 = pack_lo(val.z, val.w, h1);
    ((uint32_t*)hi)[i * 2 + 0] = h0;
    ((uint32_t*)hi)[i * 2 + 1] = h1;
    ((uint32_t*)lo)[i * 2 + 0] = l0;
    ((uint32_t*)lo)[i * 2 + 1] = l1;
}

__global__ __launch_bounds__(256)
void conv_wT4(const float* __restrict__ w0, const float* __restrict__ w1,
              const float* __restrict__ w2, const float* __restrict__ w3,
              __nv_bfloat16* __restrict__ b0h, __nv_bfloat16* __restrict__ b0l,
              __nv_bfloat16* __restrict__ b1h, __nv_bfloat16* __restrict__ b1l,
              __nv_bfloat16* __restrict__ b2h, __nv_bfloat16* __restrict__ b2l,
              __nv_bfloat16* __restrict__ b3h, __nv_bfloat16* __restrict__ b3l)
{
    const int z = blockIdx.z;
    const float* W = (z == 0) ? w0 : (z == 1) ? w1 : (z == 2) ? w2 : w3;
    __nv_bfloat16* hi = (z == 0) ? b0h : (z == 1) ? b1h : (z == 2) ? b2h : b3h;
    __nv_bfloat16* lo = (z == 0) ? b0l : (z == 1) ? b1l : (z == 2) ? b2l : b3l;

    __shared__ float t[32][33];
    int n0 = blockIdx.x * 32, k0 = blockIdx.y * 32;
    int tx = threadIdx.x, ty = threadIdx.y;   // block (32,8)
#pragma unroll
    for (int i = 0; i < 32; i += 8)
        t[ty + i][tx] = W[(size_t)(k0 + ty + i) * DD + n0 + tx];
    __syncthreads();
#pragma unroll
    for (int i = 0; i < 32; i += 8) {
        float v = t[tx][ty + i];
        __nv_bfloat16 h = __float2bfloat16_rn(v);
        size_t o = (size_t)(n0 + ty + i) * DD + k0 + tx;
        hi[o] = h;
        lo[o] = __float2bfloat16_rn(v - __bfloat162float(h));
    }
}

// ============================================================================
// mma.sync GEMM body (bf16 3-term, R5-proven core).
// mode 0: fp32 natural out.
// mode 1: fp16 single head-split out  (Q, K attention operands)
// mode 2: fp16 hi/lo head-split out   (V attention operand)
// ============================================================================
#define PADK 40
#define TILE_H (128 * PADK)
#define STAGE_H (4 * TILE_H)
#define KSTAGES (DD / 32)
#define GEMM_SMEM (2 * STAGE_H * 2)     // 81920 B

__device__ __forceinline__
void gemm_body(const __nv_bfloat16* __restrict__ Ah, const __nv_bfloat16* __restrict__ Al,
               const __nv_bfloat16* __restrict__ Bh, const __nv_bfloat16* __restrict__ Bl,
               const float* __restrict__ bias, float* __restrict__ OutF,
               void* __restrict__ O1, void* __restrict__ O2, int mode)
{
    extern __shared__ __nv_bfloat16 smb[];
    const uint32_t sb = smem_u32(smb);
    const int t = threadIdx.x, wid = t >> 5, lane = t & 31;
    const int m0 = blockIdx.y * 128, n0 = blockIdx.x * 128;
    const int wm = (wid >> 2) * 64, wn = (wid & 3) * 32;

    const __nv_bfloat16* srcs[4] = {
        Ah + (size_t)m0 * DD, Al + (size_t)m0 * DD,
        Bh + (size_t)n0 * DD, Bl + (size_t)n0 * DD };

    auto issue_stage = [&](int s, int buf) {
        uint32_t base = sb + buf * STAGE_H * 2;
#pragma unroll
        for (int p = 0; p < 8; p++) {
            int j = t + p * 256;
            int tile = j >> 9;
            int c = j & 511;
            int row = c >> 2;
            int c16 = c & 3;
            const __nv_bfloat16* g =
                srcs[tile] + (size_t)row * DD + s * 32 + c16 * 8;
            uint32_t d = base + (tile * TILE_H + row * PADK + c16 * 8) * 2;
            CP_ASYNC16(d, g);
        }
        CP_COMMIT();
    };

    float acc[4][4][4];
#pragma unroll
    for (int i = 0; i < 4; i++)
#pragma unroll
        for (int j = 0; j < 4; j++)
#pragma unroll
            for (int r = 0; r < 4; r++) acc[i][j][r] = 0.f;

    issue_stage(0, 0);
    issue_stage(1, 1);

    for (int s = 0; s < KSTAGES; s++) {
        CP_WAIT1();
        __syncthreads();
        const uint32_t base = sb + (s & 1) * STAGE_H * 2;
#pragma unroll
        for (int kk = 0; kk < 2; kk++) {
            uint32_t ah[4][4], al[4][4], bh[2][4], bl[2][4];
#pragma unroll
            for (int i = 0; i < 4; i++) {
                int row = wm + i * 16 + (lane & 15);
                int col = kk * 16 + (lane >> 4) * 8;
                uint32_t ad = base + (row * PADK + col) * 2;
                LDSM4(ah[i][0], ah[i][1], ah[i][2], ah[i][3], ad);
                LDSM4(al[i][0], al[i][1], al[i][2], al[i][3], ad + TILE_H * 2);
            }
#pragma unroll
            for (int g = 0; g < 2; g++) {
                int row = wn + g * 16 + ((lane >> 4) & 1) * 8 + (lane & 7);
                int col = kk * 16 + ((lane >> 3) & 1) * 8;
                uint32_t bd = base + (2 * TILE_H + row * PADK + col) * 2;
                LDSM4(bh[g][0], bh[g][1], bh[g][2], bh[g][3], bd);
                LDSM4(bl[g][0], bl[g][1], bl[g][2], bl[g][3], bd + TILE_H * 2);
            }
#pragma unroll
            for (int i = 0; i < 4; i++)
#pragma unroll
                for (int j = 0; j < 4; j++) {
                    int g = j >> 1, o = (j & 1) * 2;
                    MMA16816(acc[i][j], ah[i], bh[g][o], bh[g][o + 1]);
                    MMA16816(acc[i][j], ah[i], bl[g][o], bl[g][o + 1]);
                    MMA16816(acc[i][j], al[i], bh[g][o], bh[g][o + 1]);
                }
        }
        __syncthreads();
        if (s + 2 < KSTAGES) issue_stage(s + 2, s & 1);
    }
    CP_WAIT0();

#pragma unroll
    for (int i = 0; i < 4; i++) {
        int grow = m0 + wm + i * 16 + (lane >> 2);
#pragma unroll
        for (int j = 0; j < 4; j++) {
            int gcol = n0 + wn + j * 8 + (lane & 3) * 2;
            float bx = __ldg(&bias[gcol]), by = __ldg(&bias[gcol + 1]);
            float x0 = acc[i][j][0] + bx, y0 = acc[i][j][1] + by;
            float x1 = acc[i][j][2] + bx, y1 = acc[i][j][3] + by;
            if (mode == 0) {
                *(float2*)&OutF[(size_t)grow * DD + gcol] = make_float2(x0, y0);
                *(float2*)&OutF[(size_t)(grow + 8) * DD + gcol] = make_float2(x1, y1);
            } else {
                int h = gcol >> 6, dh = gcol & 63;
                int b0r = grow >> 11, s0 = grow & 2047;
                size_t o0 = (((size_t)(b0r * HH + h) * SS) + s0) * DH + dh;
                int g1 = grow + 8;
                int b1r = g1 >> 11, s1 = g1 & 2047;
                size_t o1 = (((size_t)(b1r * HH + h) * SS) + s1) * DH + dh;
                uint32_t h0 = pack_h2(x0, y0), h1 = pack_h2(x1, y1);
                ((uint32_t*)((__half*)O1 + o0))[0] = h0;
                ((uint32_t*)((__half*)O1 + o1))[0] = h1;
                if (mode == 2) {
                    ((uint32_t*)((__half*)O2 + o0))[0] = pack_h2lo(x0, y0, h0);
                    ((uint32_t*)((__half*)O2 + o1))[0] = pack_h2lo(x1, y1, h1);
                }
            }
        }
    }
}

struct GemmPtrs3 {
    const __nv_bfloat16 *Ah[3], *Al[3], *Bh[3], *Bl[3];
    const float *bias[3];
    void *O1[3], *O2[3];
    int mode[3];
};

__global__ __launch_bounds__(256, 2)
void gemm_mma3(GemmPtrs3 p)
{
    const int z = blockIdx.z;
    gemm_body(p.Ah[z], p.Al[z], p.Bh[z], p.Bl[z], p.bias[z],
              nullptr, p.O1[z], p.O2[z], p.mode[z]);
}

__global__ __launch_bounds__(256, 2)
void gemm_mma1(const __nv_bfloat16* __restrict__ Ah, const __nv_bfloat16* __restrict__ Al,
               const __nv_bfloat16* __restrict__ Bh, const __nv_bfloat16* __restrict__ Bl,
               const float* __restrict__ bias, float* __restrict__ OutF)
{
    gemm_body(Ah, Al, Bh, Bl, bias, OutF, nullptr, nullptr, 0);
}

// ============================================================================
// Flash attention, fp16 operands.
// scores: single fp16 Q*K (1 MMA); PV: fp16 P * (Vh + Vl) (2 MMAs).
// 128 threads (4 warps), q-tile 64, KV tiles: K | Vh | Vl (3 tiles/stage).
// ============================================================================
#define APAD 72
#define KV_TILE_H (64 * APAD)
#define AT_STAGE_H (3 * KV_TILE_H)
#define AT_SMEM (2 * AT_STAGE_H * 2)   // 55296 B
#define NKT (SS / 64)

__global__ __launch_bounds__(128, 3)
void attn_mma(const __half* __restrict__ Qf, const __half* __restrict__ Kf,
              const __half* __restrict__ Vhf, const __half* __restrict__ Vlf,
              __nv_bfloat16* __restrict__ OutH, __nv_bfloat16* __restrict__ OutL)
{
    extern __shared__ __nv_bfloat16 smb[];
    const uint32_t sb = smem_u32(smb);
    const int t = threadIdx.x, wid = t >> 5, lane = t & 31;
    const int bh = blockIdx.y;
    const int q0 = blockIdx.x * 64;
    const int wm = wid * 16;
    const size_t bhoff = (size_t)bh * SS * DH;

    // ---- stage Q tile: 64 rows x 8 chunks = 512 chunks ----
    {
        const __half* qs = Qf + bhoff + (size_t)q0 * DH;
#pragma unroll
        for (int p = 0; p < 4; p++) {
            int j = t + p * 128;
            int row = j >> 3;
            int c16 = j & 7;
            uint32_t d = sb + (row * APAD + c16 * 8) * 2;
            CP_ASYNC16(d, qs + (size_t)row * DH + c16 * 8);
        }
        CP_COMMIT();
        CP_WAIT0();
        __syncthreads();
    }

    uint32_t qh[4][4];
#pragma unroll
    for (int kk = 0; kk < 4; kk++) {
        int row = wm + (lane & 15);
        int col = kk * 16 + (lane >> 4) * 8;
        uint32_t ad = sb + (row * APAD + col) * 2;
        LDSM4(qh[kk][0], qh[kk][1], qh[kk][2], qh[kk][3], ad);
    }
    __syncthreads();

    const __half* kvsrc[3] = {Kf + bhoff, Vhf + bhoff, Vlf + bhoff};
    auto issue_kv = [&](int kt, int buf) {
        uint32_t base = sb + buf * AT_STAGE_H * 2;
#pragma unroll
        for (int p = 0; p < 12; p++) {
            int j = t + p * 128;          // 0..1535
            int tile = j >> 9;
            int row = (j >> 3) & 63;
            int c16 = j & 7;
            uint32_t d = base + (tile * KV_TILE_H + row * APAD + c16 * 8) * 2;
            CP_ASYNC16(d, kvsrc[tile] + (size_t)(kt * 64 + row) * DH + c16 * 8);
        }
        CP_COMMIT();
    };

    float o[8][4];
#pragma unroll
    for (int j = 0; j < 8; j++)
#pragma unroll
        for (int r = 0; r < 4; r++) o[j][r] = 0.f;
    float m_i[2] = {-INFINITY, -INFINITY};
    float l_i[2] = {0.f, 0.f};

    issue_kv(0, 0);
    issue_kv(1, 1);

    for (int kt = 0; kt < NKT; kt++) {
        CP_WAIT1();
        __syncthreads();
        const uint32_t base = sb + (kt & 1) * AT_STAGE_H * 2;

        // ---- scores: S = Q K^T (single fp16 term) ----
        float s[8][4];
#pragma unroll
        for (int j = 0; j < 8; j++)
#pragma unroll
            for (int r = 0; r < 4; r++) s[j][r] = 0.f;

#pragma unroll
        for (int kk = 0; kk < 4; kk++) {
            uint32_t kf[4][4];
#pragma unroll
            for (int g = 0; g < 4; g++) {
                int row = g * 16 + ((lane >> 4) & 1) * 8 + (lane & 7);
                int col = kk * 16 + ((lane >> 3) & 1) * 8;
                uint32_t kd = base + (row * APAD + col) * 2;
                LDSM4(kf[g][0], kf[g][1], kf[g][2], kf[g][3], kd);
            }
#pragma unroll
            for (int j = 0; j < 8; j++) {
                int g = j >> 1, oo = (j & 1) * 2;
                MMAF16(s[j], qh[kk], kf[g][oo], kf[g][oo + 1]);
            }
        }

        // ---- online softmax ----
        float mx[2] = {-INFINITY, -INFINITY};
#pragma unroll
        for (int j = 0; j < 8; j++) {
#pragma unroll
            for (int r = 0; r < 4; r++) s[j][r] *= 0.125f;
            mx[0] = fmaxf(mx[0], fmaxf(s[j][0], s[j][1]));
            mx[1] = fmaxf(mx[1], fmaxf(s[j][2], s[j][3]));
        }
#pragma unroll
        for (int r = 0; r < 2; r++) {
            mx[r] = fmaxf(mx[r], __shfl_xor_sync(0xffffffffu, mx[r], 1));
            mx[r] = fmaxf(mx[r], __shfl_xor_sync(0xffffffffu, mx[r], 2));
        }
        float mn[2], corr[2];
#pragma unroll
        for (int r = 0; r < 2; r++) {
            mn[r] = fmaxf(m_i[r], mx[r]);
            corr[r] = __expf(m_i[r] - mn[r]);
            m_i[r] = mn[r];
        }
        float rs[2] = {0.f, 0.f};
#pragma unroll
        for (int j = 0; j < 8; j++) {
            s[j][0] = __expf(s[j][0] - mn[0]);
            s[j][1] = __expf(s[j][1] - mn[0]);
            s[j][2] = __expf(s[j][2] - mn[1]);
            s[j][3] = __expf(s[j][3] - mn[1]);
            rs[0] += s[j][0] + s[j][1];
            rs[1] += s[j][2] + s[j][3];
        }
#pragma unroll
        for (int r = 0; r < 2; r++) {
            rs[r] += __shfl_xor_sync(0xffffffffu, rs[r], 1);
            rs[r] += __shfl_xor_sync(0xffffffffu, rs[r], 2);
            l_i[r] = l_i[r] * corr[r] + rs[r];
        }
#pragma unroll
        for (int j = 0; j < 8; j++) {
            o[j][0] *= corr[0]; o[j][1] *= corr[0];
            o[j][2] *= corr[1]; o[j][3] *= corr[1];
        }

        // ---- PV: O += P (Vh + Vl), P single fp16 ----
#pragma unroll
        for (int kk = 0; kk < 4; kk++) {
            uint32_t ap[4];
            ap[0] = pack_h2(s[2 * kk][0], s[2 * kk][1]);
            ap[1] = pack_h2(s[2 * kk][2], s[2 * kk][3]);
            ap[2] = pack_h2(s[2 * kk + 1][0], s[2 * kk + 1][1]);
            ap[3] = pack_h2(s[2 * kk + 1][2], s[2 * kk + 1][3]);

            uint32_t vfh[4][4], vfl[4][4];
#pragma unroll
            for (int g = 0; g < 4; g++) {
                int row = kk * 16 + (lane & 15);
                int col = g * 16 + (lane >> 4) * 8;
                uint32_t vd = base + (KV_TILE_H + row * APAD + col) * 2;
                LDSM4T(vfh[g][0], vfh[g][1], vfh[g][2], vfh[g][3], vd);
                LDSM4T(vfl[g][0], vfl[g][1], vfl[g][2], vfl[g][3], vd + KV_TILE_H * 2);
            }
#pragma unroll
            for (int j = 0; j < 8; j++) {
                int g = j >> 1, oo = (j & 1) * 2;
                MMAF16(o[j], ap, vfh[g][oo], vfh[g][oo + 1]);
                MMAF16(o[j], ap, vfl[g][oo], vfl[g][oo + 1]);
            }
        }
        __syncthreads();
        if (kt + 2 < NKT) issue_kv(kt + 2, kt & 1);
    }

    // ---- epilogue: bf16 hi/lo gathered [M][D] for out-projection ----
    const int b = bh >> 4, h = bh & 15;
    const float inv0 = 1.f / l_i[0], inv1 = 1.f / l_i[1];
    const int srow0 = q0 + wm + (lane >> 2);
#pragma unroll
    for (int j = 0; j < 8; j++) {
        int dh = j * 8 + (lane & 3) * 2;
        int kcol = h * 64 + dh;
        size_t o0 = ((size_t)(b * SS + srow0)) * DD + kcol;
        size_t o1 = ((size_t)(b * SS + srow0 + 8)) * DD + kcol;
        float x0 = o[j][0] * inv0, y0 = o[j][1] * inv0;
        float x1 = o[j][2] * inv1, y1 = o[j][3] * inv1;
        uint32_t h0 = pack_hi(x0, y0), h1 = pack_hi(x1, y1);
        *(uint32_t*)&OutH[o0] = h0;
        *(uint32_t*)&OutL[o0] = pack_lo(x0, y0, h0);
        *(uint32_t*)&OutH[o1] = h1;
        *(uint32_t*)&OutL[o1] = pack_lo(x1, y1, h1);
    }
}

// ============================================================================
// launch
// ============================================================================
extern "C" void kernel_launch(void* const* d_in, const int* in_sizes, int n_in,
                              void* d_out, int out_size)
{
    const float* q   = (const float*)d_in[0];
    const float* k   = (const float*)d_in[1];
    const float* v   = (const float*)d_in[2];
    const float* w_q = (const float*)d_in[3];
    const float* b_q = (const float*)d_in[4];
    const float* w_k = (const float*)d_in[5];
    const float* b_k = (const float*)d_in[6];
    const float* w_v = (const float*)d_in[7];
    const float* b_v = (const float*)d_in[8];
    const float* w_o = (const float*)d_in[9];
    const float* b_o = (const float*)d_in[10];
    float* out = (float*)d_out;

    __nv_bfloat16 *pA0h, *pA0l, *pA1h, *pA1l, *pA2h, *pA2l;
    __nv_bfloat16 *pB0h, *pB0l, *pB1h, *pB1l, *pB2h, *pB2l, *pB3h, *pB3l;
    __half *pQf, *pKf, *pVhf, *pVlf;
    cudaGetSymbolAddress((void**)&pA0h, g_A0h);
    cudaGetSymbolAddress((void**)&pA0l, g_A0l);
    cudaGetSymbolAddress((void**)&pA1h, g_A1h);
    cudaGetSymbolAddress((void**)&pA1l, g_A1l);
    cudaGetSymbolAddress((void**)&pA2h, g_A2h);
    cudaGetSymbolAddress((void**)&pA2l, g_A2l);
    cudaGetSymbolAddress((void**)&pB0h, g_B0h);
    cudaGetSymbolAddress((void**)&pB0l, g_B0l);
    cudaGetSymbolAddress((void**)&pB1h, g_B1h);
    cudaGetSymbolAddress((void**)&pB1l, g_B1l);
    cudaGetSymbolAddress((void**)&pB2h, g_B2h);
    cudaGetSymbolAddress((void**)&pB2l, g_B2l);
    cudaGetSymbolAddress((void**)&pB3h, g_B3h);
    cudaGetSymbolAddress((void**)&pB3l, g_B3l);
    cudaGetSymbolAddress((void**)&pQf, g_Qf);
    cudaGetSymbolAddress((void**)&pKf, g_Kf);
    cudaGetSymbolAddress((void**)&pVhf, g_Vhf);
    cudaGetSymbolAddress((void**)&pVlf, g_Vlf);

    static int attr_set = 0;
    if (!attr_set) {
        cudaFuncSetAttribute(gemm_mma3,
                             cudaFuncAttributeMaxDynamicSharedMemorySize, GEMM_SMEM);
        cudaFuncSetAttribute(gemm_mma1,
                             cudaFuncAttributeMaxDynamicSharedMemorySize, GEMM_SMEM);
        cudaFuncSetAttribute(attn_mma,
                             cudaFuncAttributeMaxDynamicSharedMemorySize, AT_SMEM);
        attr_set = 1;
    }

    dim3 gs(MM * DD / 4 / 256, 3);
    conv_split3<<<gs, 256>>>((const float4*)q, (const float4*)k, (const float4*)v,
                             pA0h, pA0l, pA1h, pA1l, pA2h, pA2l);
    dim3 gw(DD / 32, DD / 32, 4);
    conv_wT4<<<gw, dim3(32, 8)>>>(w_q, w_k, w_v, w_o,
                                  pB0h, pB0l, pB1h, pB1l,
                                  pB2h, pB2l, pB3h, pB3l);

    GemmPtrs3 gp;
    gp.Ah[0] = pA0h; gp.Al[0] = pA0l; gp.Bh[0] = pB0h; gp.Bl[0] = pB0l;
    gp.bias[0] = b_q; gp.O1[0] = pQf;  gp.O2[0] = nullptr; gp.mode[0] = 1;
    gp.Ah[1] = pA1h; gp.Al[1] = pA1l; gp.Bh[1] = pB1h; gp.Bl[1] = pB1l;
    gp.bias[1] = b_k; gp.O1[1] = pKf;  gp.O2[1] = nullptr; gp.mode[1] = 1;
    gp.Ah[2] = pA2h; gp.Al[2] = pA2l; gp.Bh[2] = pB2h; gp.Bl[2] = pB2l;
    gp.bias[2] = b_v; gp.O1[2] = pVhf; gp.O2[2] = pVlf;   gp.mode[2] = 2;
    dim3 gg(DD / 128, MM / 128, 3);   // (8, 32, 3)
    gemm_mma3<<<gg, 256, GEMM_SMEM>>>(gp);

    // attention: fp16 operands, 64-row q-tiles, 128-thread CTAs
    dim3 ga(SS / 64, BB * HH);        // (32, 32) = 1024 CTAs
    attn_mma<<<ga, 128, AT_SMEM>>>(pQf, pKf, pVhf, pVlf, pA0h, pA0l);

    dim3 g1(DD / 128, MM / 128);
    gemm_mma1<<<g1, 256, GEMM_SMEM>>>(pA0h, pA0l, pB3h, pB3l, b_o, out);
}

// round 8
// speedup vs baseline: 5.0372x; 1.3962x over previous
#include <cuda_runtime.h>
#include <cuda_bf16.h>
#include <cuda_fp16.h>
#include <math.h>
#include <stdint.h>

// Problem constants
#define BB 2
#define SS 2048
#define DD 1024
#define HH 16
#define DH 64
#define MM (BB * SS)   // 4096 rows

// -------------------- scratch (allocation-free rule: __device__ globals) ----
// GEMM A operands: fp16 hi/lo.  A0 reused as attn-output / out-proj A.
__device__ __half g_A0h[MM * DD];
__device__ __half g_A0l[MM * DD];
__device__ __half g_A1h[MM * DD];
__device__ __half g_A1l[MM * DD];
__device__ __half g_A2h[MM * DD];
__device__ __half g_A2l[MM * DD];
// GEMM B operands: single fp16 [N][K] (q,k,v,o weights transposed)
__device__ __half g_B0[DD * DD];
__device__ __half g_B1[DD * DD];
__device__ __half g_B2[DD * DD];
__device__ __half g_B3[DD * DD];
// attention operands, head-split [B*H][S][DH], single fp16
__device__ __half g_Qf[MM * DD];
__device__ __half g_Kf[MM * DD];
__device__ __half g_Vf[MM * DD];

// ============================================================================
// helpers
// ============================================================================
__device__ __forceinline__ uint32_t smem_u32(const void* p) {
    uint32_t a;
    asm("{ .reg .u64 t; cvta.to.shared.u64 t, %1; cvt.u32.u64 %0, t; }"
        : "=r"(a) : "l"(p));
    return a;
}

#define LDSM4(r0, r1, r2, r3, addr)                                            \
    asm volatile("ldmatrix.sync.aligned.m8n8.x4.shared.b16 {%0,%1,%2,%3}, [%4];" \
                 : "=r"(r0), "=r"(r1), "=r"(r2), "=r"(r3) : "r"(addr))
#define LDSM4T(r0, r1, r2, r3, addr)                                           \
    asm volatile("ldmatrix.sync.aligned.m8n8.x4.trans.shared.b16 {%0,%1,%2,%3}, [%4];" \
                 : "=r"(r0), "=r"(r1), "=r"(r2), "=r"(r3) : "r"(addr))

#define MMAF16(d, a, b0, b1)                                                   \
    asm volatile("mma.sync.aligned.m16n8k16.row.col.f32.f16.f16.f32 "          \
                 "{%0,%1,%2,%3}, {%4,%5,%6,%7}, {%8,%9}, {%0,%1,%2,%3};"       \
                 : "+f"((d)[0]), "+f"((d)[1]), "+f"((d)[2]), "+f"((d)[3])      \
                 : "r"((a)[0]), "r"((a)[1]), "r"((a)[2]), "r"((a)[3]),         \
                   "r"(b0), "r"(b1))

#define CP_ASYNC16(dst, src)                                                   \
    asm volatile("cp.async.cg.shared.global [%0], [%1], 16;" :: "r"(dst), "l"(src))
#define CP_COMMIT()  asm volatile("cp.async.commit_group;" ::: "memory")
#define CP_WAIT1()   asm volatile("cp.async.wait_group 1;" ::: "memory")
#define CP_WAIT0()   asm volatile("cp.async.wait_group 0;" ::: "memory")

__device__ __forceinline__ uint32_t pack_h2(float x, float y) {
    __half2 h = __floats2half2_rn(x, y);
    return *(uint32_t*)&h;
}
__device__ __forceinline__ uint32_t pack_h2lo(float x, float y, uint32_t hbits) {
    __half2 h = *(__half2*)&hbits;
    __half2 l = __floats2half2_rn(x - __half2float(h.x),
                                  y - __half2float(h.y));
    return *(uint32_t*)&l;
}

// ============================================================================
// fused conversion kernels
// ============================================================================
// q/k/v inputs -> fp16 hi/lo A operands
__global__ __launch_bounds__(256)
void conv_split3(const float4* __restrict__ q, const float4* __restrict__ k,
                 const float4* __restrict__ v,
                 __half* __restrict__ a0h, __half* __restrict__ a0l,
                 __half* __restrict__ a1h, __half* __restrict__ a1l,
                 __half* __restrict__ a2h, __half* __restrict__ a2l)
{
    const int z = blockIdx.y;
    const float4* src = (z == 0) ? q : (z == 1) ? k : v;
    __half* hi = (z == 0) ? a0h : (z == 1) ? a1h : a2h;
    __half* lo = (z == 0) ? a0l : (z == 1) ? a1l : a2l;
    int i = blockIdx.x * 256 + threadIdx.x;
    float4 val = src[i];
    uint32_t h0 = pack_h2(val.x, val.y), h1 = pack_h2(val.z, val.w);
    uint32_t l0 = pack_h2lo(val.x, val.y, h0), l1 = pack_h2lo(val.z, val.w, h1);
    ((uint32_t*)hi)[i * 2 + 0] = h0;
    ((uint32_t*)hi)[i * 2 + 1] = h1;
    ((uint32_t*)lo)[i * 2 + 0] = l0;
    ((uint32_t*)lo)[i * 2 + 1] = l1;
}

// W [K][N] -> B[n][k] single fp16 (transpose)
__global__ __launch_bounds__(256)
void conv_wT4(const float* __restrict__ w0, const float* __restrict__ w1,
              const float* __restrict__ w2, const float* __restrict__ w3,
              __half* __restrict__ b0, __half* __restrict__ b1,
              __half* __restrict__ b2, __half* __restrict__ b3)
{
    const int z = blockIdx.z;
    const float* W = (z == 0) ? w0 : (z == 1) ? w1 : (z == 2) ? w2 : w3;
    __half* dst = (z == 0) ? b0 : (z == 1) ? b1 : (z == 2) ? b2 : b3;

    __shared__ float t[32][33];
    int n0 = blockIdx.x * 32, k0 = blockIdx.y * 32;
    int tx = threadIdx.x, ty = threadIdx.y;   // block (32,8)
#pragma unroll
    for (int i = 0; i < 32; i += 8)
        t[ty + i][tx] = W[(size_t)(k0 + ty + i) * DD + n0 + tx];
    __syncthreads();
#pragma unroll
    for (int i = 0; i < 32; i += 8)
        dst[(size_t)(n0 + ty + i) * DD + k0 + tx] = __float2half_rn(t[tx][ty + i]);
}

// ============================================================================
// mma.sync GEMM: C = A B^T + bias, fp16 2-term (Ah*B + Al*B).
// 128x128 tile, BK=32, 2-stage cp.async.  Stage = Ah | Al | B (3 tiles).
// mode 0: fp32 natural out.  mode 1: fp16 single head-split out.
// ============================================================================
#define PADK 40
#define TILE_H (128 * PADK)
#define STAGE_H (3 * TILE_H)
#define KSTAGES (DD / 32)
#define GEMM_SMEM (2 * STAGE_H * 2)     // 61440 B

__device__ __forceinline__
void gemm_body(const __half* __restrict__ Ah, const __half* __restrict__ Al,
               const __half* __restrict__ Bs,
               const float* __restrict__ bias, float* __restrict__ OutF,
               __half* __restrict__ O1, int mode)
{
    extern __shared__ __half smb[];
    const uint32_t sb = smem_u32(smb);
    const int t = threadIdx.x, wid = t >> 5, lane = t & 31;
    const int m0 = blockIdx.y * 128, n0 = blockIdx.x * 128;
    const int wm = (wid >> 2) * 64, wn = (wid & 3) * 32;

    const __half* srcs[3] = {
        Ah + (size_t)m0 * DD, Al + (size_t)m0 * DD, Bs + (size_t)n0 * DD };

    auto issue_stage = [&](int s, int buf) {
        uint32_t base = sb + buf * STAGE_H * 2;
#pragma unroll
        for (int p = 0; p < 6; p++) {
            int j = t + p * 256;              // 0..1535 16B chunks
            int tile = j >> 9;
            int c = j & 511;
            int row = c >> 2;
            int c16 = c & 3;
            const __half* g = srcs[tile] + (size_t)row * DD + s * 32 + c16 * 8;
            uint32_t d = base + (tile * TILE_H + row * PADK + c16 * 8) * 2;
            CP_ASYNC16(d, g);
        }
        CP_COMMIT();
    };

    float acc[4][4][4];
#pragma unroll
    for (int i = 0; i < 4; i++)
#pragma unroll
        for (int j = 0; j < 4; j++)
#pragma unroll
            for (int r = 0; r < 4; r++) acc[i][j][r] = 0.f;

    issue_stage(0, 0);
    issue_stage(1, 1);

    for (int s = 0; s < KSTAGES; s++) {
        CP_WAIT1();
        __syncthreads();
        const uint32_t base = sb + (s & 1) * STAGE_H * 2;
#pragma unroll
        for (int kk = 0; kk < 2; kk++) {
            uint32_t ah[4][4], al[4][4], bf[2][4];
#pragma unroll
            for (int i = 0; i < 4; i++) {
                int row = wm + i * 16 + (lane & 15);
                int col = kk * 16 + (lane >> 4) * 8;
                uint32_t ad = base + (row * PADK + col) * 2;
                LDSM4(ah[i][0], ah[i][1], ah[i][2], ah[i][3], ad);
                LDSM4(al[i][0], al[i][1], al[i][2], al[i][3], ad + TILE_H * 2);
            }
#pragma unroll
            for (int g = 0; g < 2; g++) {
                int row = wn + g * 16 + ((lane >> 4) & 1) * 8 + (lane & 7);
                int col = kk * 16 + ((lane >> 3) & 1) * 8;
                uint32_t bd = base + (2 * TILE_H + row * PADK + col) * 2;
                LDSM4(bf[g][0], bf[g][1], bf[g][2], bf[g][3], bd);
            }
#pragma unroll
            for (int i = 0; i < 4; i++)
#pragma unroll
                for (int j = 0; j < 4; j++) {
                    int g = j >> 1, o = (j & 1) * 2;
                    MMAF16(acc[i][j], ah[i], bf[g][o], bf[g][o + 1]);
                    MMAF16(acc[i][j], al[i], bf[g][o], bf[g][o + 1]);
                }
        }
        __syncthreads();
        if (s + 2 < KSTAGES) issue_stage(s + 2, s & 1);
    }
    CP_WAIT0();

#pragma unroll
    for (int i = 0; i < 4; i++) {
        int grow = m0 + wm + i * 16 + (lane >> 2);
#pragma unroll
        for (int j = 0; j < 4; j++) {
            int gcol = n0 + wn + j * 8 + (lane & 3) * 2;
            float bx = __ldg(&bias[gcol]), by = __ldg(&bias[gcol + 1]);
            float x0 = acc[i][j][0] + bx, y0 = acc[i][j][1] + by;
            float x1 = acc[i][j][2] + bx, y1 = acc[i][j][3] + by;
            if (mode == 0) {
                *(float2*)&OutF[(size_t)grow * DD + gcol] = make_float2(x0, y0);
                *(float2*)&OutF[(size_t)(grow + 8) * DD + gcol] = make_float2(x1, y1);
            } else {
                int h = gcol >> 6, dh = gcol & 63;
                int b0r = grow >> 11, s0 = grow & 2047;
                size_t o0 = (((size_t)(b0r * HH + h) * SS) + s0) * DH + dh;
                int g1 = grow + 8;
                int b1r = g1 >> 11, s1 = g1 & 2047;
                size_t o1 = (((size_t)(b1r * HH + h) * SS) + s1) * DH + dh;
                *(uint32_t*)&O1[o0] = pack_h2(x0, y0);
                *(uint32_t*)&O1[o1] = pack_h2(x1, y1);
            }
        }
    }
}

struct GemmPtrs3 {
    const __half *Ah[3], *Al[3], *Bs[3];
    const float *bias[3];
    __half *O1[3];
};

__global__ __launch_bounds__(256, 2)
void gemm_mma3(GemmPtrs3 p)
{
    const int z = blockIdx.z;
    gemm_body(p.Ah[z], p.Al[z], p.Bs[z], p.bias[z], nullptr, p.O1[z], 1);
}

__global__ __launch_bounds__(256, 2)
void gemm_mma1(const __half* __restrict__ Ah, const __half* __restrict__ Al,
               const __half* __restrict__ Bs,
               const float* __restrict__ bias, float* __restrict__ OutF)
{
    gemm_body(Ah, Al, Bs, bias, OutF, nullptr, 0);
}

// ============================================================================
// Flash attention, all-fp16 operands.
// scores: 1 MMA (Q*K); PV: 1 MMA (P*V).  KV stage = K | V (2 tiles).
// 128 threads (4 warps), q-tile 64, 3 CTAs/SM target.
// ============================================================================
#define APAD 72
#define KV_TILE_H (64 * APAD)
#define AT_STAGE_H (2 * KV_TILE_H)
#define AT_SMEM (2 * AT_STAGE_H * 2)   // 36864 B
#define NKT (SS / 64)

__global__ __launch_bounds__(128, 3)
void attn_mma(const __half* __restrict__ Qf, const __half* __restrict__ Kf,
              const __half* __restrict__ Vf,
              __half* __restrict__ OutH, __half* __restrict__ OutL)
{
    extern __shared__ __half smb[];
    const uint32_t sb = smem_u32(smb);
    const int t = threadIdx.x, wid = t >> 5, lane = t & 31;
    const int bh = blockIdx.y;
    const int q0 = blockIdx.x * 64;
    const int wm = wid * 16;
    const size_t bhoff = (size_t)bh * SS * DH;

    // ---- stage Q tile ----
    {
        const __half* qs = Qf + bhoff + (size_t)q0 * DH;
#pragma unroll
        for (int p = 0; p < 4; p++) {
            int j = t + p * 128;
            int row = j >> 3;
            int c16 = j & 7;
            uint32_t d = sb + (row * APAD + c16 * 8) * 2;
            CP_ASYNC16(d, qs + (size_t)row * DH + c16 * 8);
        }
        CP_COMMIT();
        CP_WAIT0();
        __syncthreads();
    }

    uint32_t qh[4][4];
#pragma unroll
    for (int kk = 0; kk < 4; kk++) {
        int row = wm + (lane & 15);
        int col = kk * 16 + (lane >> 4) * 8;
        uint32_t ad = sb + (row * APAD + col) * 2;
        LDSM4(qh[kk][0], qh[kk][1], qh[kk][2], qh[kk][3], ad);
    }
    __syncthreads();

    const __half* kvsrc[2] = {Kf + bhoff, Vf + bhoff};
    auto issue_kv = [&](int kt, int buf) {
        uint32_t base = sb + buf * AT_STAGE_H * 2;
#pragma unroll
        for (int p = 0; p < 8; p++) {
            int j = t + p * 128;          // 0..1023
            int tile = j >> 9;
            int row = (j >> 3) & 63;
            int c16 = j & 7;
            uint32_t d = base + (tile * KV_TILE_H + row * APAD + c16 * 8) * 2;
            CP_ASYNC16(d, kvsrc[tile] + (size_t)(kt * 64 + row) * DH + c16 * 8);
        }
        CP_COMMIT();
    };

    float o[8][4];
#pragma unroll
    for (int j = 0; j < 8; j++)
#pragma unroll
        for (int r = 0; r < 4; r++) o[j][r] = 0.f;
    float m_i[2] = {-INFINITY, -INFINITY};
    float l_i[2] = {0.f, 0.f};

    issue_kv(0, 0);
    issue_kv(1, 1);

    for (int kt = 0; kt < NKT; kt++) {
        CP_WAIT1();
        __syncthreads();
        const uint32_t base = sb + (kt & 1) * AT_STAGE_H * 2;

        float s[8][4];
#pragma unroll
        for (int j = 0; j < 8; j++)
#pragma unroll
            for (int r = 0; r < 4; r++) s[j][r] = 0.f;

#pragma unroll
        for (int kk = 0; kk < 4; kk++) {
            uint32_t kf[4][4];
#pragma unroll
            for (int g = 0; g < 4; g++) {
                int row = g * 16 + ((lane >> 4) & 1) * 8 + (lane & 7);
                int col = kk * 16 + ((lane >> 3) & 1) * 8;
                uint32_t kd = base + (row * APAD + col) * 2;
                LDSM4(kf[g][0], kf[g][1], kf[g][2], kf[g][3], kd);
            }
#pragma unroll
            for (int j = 0; j < 8; j++) {
                int g = j >> 1, oo = (j & 1) * 2;
                MMAF16(s[j], qh[kk], kf[g][oo], kf[g][oo + 1]);
            }
        }

        float mx[2] = {-INFINITY, -INFINITY};
#pragma unroll
        for (int j = 0; j < 8; j++) {
#pragma unroll
            for (int r = 0; r < 4; r++) s[j][r] *= 0.125f;
            mx[0] = fmaxf(mx[0], fmaxf(s[j][0], s[j][1]));
            mx[1] = fmaxf(mx[1], fmaxf(s[j][2], s[j][3]));
        }
#pragma unroll
        for (int r = 0; r < 2; r++) {
            mx[r] = fmaxf(mx[r], __shfl_xor_sync(0xffffffffu, mx[r], 1));
            mx[r] = fmaxf(mx[r], __shfl_xor_sync(0xffffffffu, mx[r], 2));
        }
        float mn[2], corr[2];
#pragma unroll
        for (int r = 0; r < 2; r++) {
            mn[r] = fmaxf(m_i[r], mx[r]);
            corr[r] = __expf(m_i[r] - mn[r]);
            m_i[r] = mn[r];
        }
        float rs[2] = {0.f, 0.f};
#pragma unroll
        for (int j = 0; j < 8; j++) {
            s[j][0] = __expf(s[j][0] - mn[0]);
            s[j][1] = __expf(s[j][1] - mn[0]);
            s[j][2] = __expf(s[j][2] - mn[1]);
            s[j][3] = __expf(s[j][3] - mn[1]);
            rs[0] += s[j][0] + s[j][1];
            rs[1] += s[j][2] + s[j][3];
        }
#pragma unroll
        for (int r = 0; r < 2; r++) {
            rs[r] += __shfl_xor_sync(0xffffffffu, rs[r], 1);
            rs[r] += __shfl_xor_sync(0xffffffffu, rs[r], 2);
            l_i[r] = l_i[r] * corr[r] + rs[r];
        }
#pragma unroll
        for (int j = 0; j < 8; j++) {
            o[j][0] *= corr[0]; o[j][1] *= corr[0];
            o[j][2] *= corr[1]; o[j][3] *= corr[1];
        }

        // ---- PV: O += P V (single fp16 each) ----
#pragma unroll
        for (int kk = 0; kk < 4; kk++) {
            uint32_t ap[4];
            ap[0] = pack_h2(s[2 * kk][0], s[2 * kk][1]);
            ap[1] = pack_h2(s[2 * kk][2], s[2 * kk][3]);
            ap[2] = pack_h2(s[2 * kk + 1][0], s[2 * kk + 1][1]);
            ap[3] = pack_h2(s[2 * kk + 1][2], s[2 * kk + 1][3]);

            uint32_t vf[4][4];
#pragma unroll
            for (int g = 0; g < 4; g++) {
                int row = kk * 16 + (lane & 15);
                int col = g * 16 + (lane >> 4) * 8;
                uint32_t vd = base + (KV_TILE_H + row * APAD + col) * 2;
                LDSM4T(vf[g][0], vf[g][1], vf[g][2], vf[g][3], vd);
            }
#pragma unroll
            for (int j = 0; j < 8; j++) {
                int g = j >> 1, oo = (j & 1) * 2;
                MMAF16(o[j], ap, vf[g][oo], vf[g][oo + 1]);
            }
        }
        __syncthreads();
        if (kt + 2 < NKT) issue_kv(kt + 2, kt & 1);
    }

    // ---- epilogue: fp16 hi/lo gathered [M][D] for out-projection ----
    const int b = bh >> 4, h = bh & 15;
    const float inv0 = 1.f / l_i[0], inv1 = 1.f / l_i[1];
    const int srow0 = q0 + wm + (lane >> 2);
#pragma unroll
    for (int j = 0; j < 8; j++) {
        int dh = j * 8 + (lane & 3) * 2;
        int kcol = h * 64 + dh;
        size_t o0 = ((size_t)(b * SS + srow0)) * DD + kcol;
        size_t o1 = ((size_t)(b * SS + srow0 + 8)) * DD + kcol;
        float x0 = o[j][0] * inv0, y0 = o[j][1] * inv0;
        float x1 = o[j][2] * inv1, y1 = o[j][3] * inv1;
        uint32_t h0 = pack_h2(x0, y0), h1 = pack_h2(x1, y1);
        *(uint32_t*)&OutH[o0] = h0;
        *(uint32_t*)&OutL[o0] = pack_h2lo(x0, y0, h0);
        *(uint32_t*)&OutH[o1] = h1;
        *(uint32_t*)&OutL[o1] = pack_h2lo(x1, y1, h1);
    }
}

// ============================================================================
// launch
// ============================================================================
extern "C" void kernel_launch(void* const* d_in, const int* in_sizes, int n_in,
                              void* d_out, int out_size)
{
    const float* q   = (const float*)d_in[0];
    const float* k   = (const float*)d_in[1];
    const float* v   = (const float*)d_in[2];
    const float* w_q = (const float*)d_in[3];
    const float* b_q = (const float*)d_in[4];
    const float* w_k = (const float*)d_in[5];
    const float* b_k = (const float*)d_in[6];
    const float* w_v = (const float*)d_in[7];
    const float* b_v = (const float*)d_in[8];
    const float* w_o = (const float*)d_in[9];
    const float* b_o = (const float*)d_in[10];
    float* out = (float*)d_out;

    __half *pA0h, *pA0l, *pA1h, *pA1l, *pA2h, *pA2l;
    __half *pB0, *pB1, *pB2, *pB3, *pQf, *pKf, *pVf;
    cudaGetSymbolAddress((void**)&pA0h, g_A0h);
    cudaGetSymbolAddress((void**)&pA0l, g_A0l);
    cudaGetSymbolAddress((void**)&pA1h, g_A1h);
    cudaGetSymbolAddress((void**)&pA1l, g_A1l);
    cudaGetSymbolAddress((void**)&pA2h, g_A2h);
    cudaGetSymbolAddress((void**)&pA2l, g_A2l);
    cudaGetSymbolAddress((void**)&pB0, g_B0);
    cudaGetSymbolAddress((void**)&pB1, g_B1);
    cudaGetSymbolAddress((void**)&pB2, g_B2);
    cudaGetSymbolAddress((void**)&pB3, g_B3);
    cudaGetSymbolAddress((void**)&pQf, g_Qf);
    cudaGetSymbolAddress((void**)&pKf, g_Kf);
    cudaGetSymbolAddress((void**)&pVf, g_Vf);

    static int attr_set = 0;
    if (!attr_set) {
        cudaFuncSetAttribute(gemm_mma3,
                             cudaFuncAttributeMaxDynamicSharedMemorySize, GEMM_SMEM);
        cudaFuncSetAttribute(gemm_mma1,
                             cudaFuncAttributeMaxDynamicSharedMemorySize, GEMM_SMEM);
        cudaFuncSetAttribute(attn_mma,
                             cudaFuncAttributeMaxDynamicSharedMemorySize, AT_SMEM);
        attr_set = 1;
    }

    dim3 gs(MM * DD / 4 / 256, 3);
    conv_split3<<<gs, 256>>>((const float4*)q, (const float4*)k, (const float4*)v,
                             pA0h, pA0l, pA1h, pA1l, pA2h, pA2l);
    dim3 gw(DD / 32, DD / 32, 4);
    conv_wT4<<<gw, dim3(32, 8)>>>(w_q, w_k, w_v, w_o, pB0, pB1, pB2, pB3);

    GemmPtrs3 gp;
    gp.Ah[0] = pA0h; gp.Al[0] = pA0l; gp.Bs[0] = pB0;
    gp.bias[0] = b_q; gp.O1[0] = pQf;
    gp.Ah[1] = pA1h; gp.Al[1] = pA1l; gp.Bs[1] = pB1;
    gp.bias[1] = b_k; gp.O1[1] = pKf;
    gp.Ah[2] = pA2h; gp.Al[2] = pA2l; gp.Bs[2] = pB2;
    gp.bias[2] = b_v; gp.O1[2] = pVf;
    dim3 gg(DD / 128, MM / 128, 3);   // (8, 32, 3)
    gemm_mma3<<<gg, 256, GEMM_SMEM>>>(gp);

    dim3 ga(SS / 64, BB * HH);        // (32, 32) = 1024 CTAs
    attn_mma<<<ga, 128, AT_SMEM>>>(pQf, pKf, pVf, pA0h, pA0l);

    dim3 g1(DD / 128, MM / 128);
    gemm_mma1<<<g1, 256, GEMM_SMEM>>>(pA0h, pA0l, pB3, b_o, out);
}

// round 9
// speedup vs baseline: 6.3290x; 1.2564x over previous
#include <cuda_runtime.h>
#include <cuda_bf16.h>
#include <cuda_fp16.h>
#include <math.h>
#include <stdint.h>

// Problem constants
#define BB 2
#define SS 2048
#define DD 1024
#define HH 16
#define DH 64
#define MM (BB * SS)   // 4096 rows

// softmax scale folded into Q projection: 1/sqrt(64) * log2(e)
#define QSCALE 0.18033688011112042f

// -------------------- scratch (allocation-free rule: __device__ globals) ----
// attn-output / out-proj A operand (fp16 hi/lo, 2-term)
__device__ __half g_A0h[MM * DD];
__device__ __half g_A0l[MM * DD];
// q/k/v inputs as single fp16 A operands
__device__ __half g_Ain0[MM * DD];
__device__ __half g_Ain1[MM * DD];
__device__ __half g_Ain2[MM * DD];
// GEMM B operands: single fp16 [N][K]
__device__ __half g_B0[DD * DD];
__device__ __half g_B1[DD * DD];
__device__ __half g_B2[DD * DD];
__device__ __half g_B3[DD * DD];
// attention operands, head-split [B*H][S][DH], single fp16
__device__ __half g_Qf[MM * DD];
__device__ __half g_Kf[MM * DD];
__device__ __half g_Vf[MM * DD];

// ============================================================================
// helpers
// ============================================================================
__device__ __forceinline__ uint32_t smem_u32(const void* p) {
    uint32_t a;
    asm("{ .reg .u64 t; cvta.to.shared.u64 t, %1; cvt.u32.u64 %0, t; }"
        : "=r"(a) : "l"(p));
    return a;
}
__device__ __forceinline__ float ex2f(float x) {
    float y;
    asm("ex2.approx.f32 %0, %1;" : "=f"(y) : "f"(x));
    return y;
}

#define LDSM4(r0, r1, r2, r3, addr)                                            \
    asm volatile("ldmatrix.sync.aligned.m8n8.x4.shared.b16 {%0,%1,%2,%3}, [%4];" \
                 : "=r"(r0), "=r"(r1), "=r"(r2), "=r"(r3) : "r"(addr))
#define LDSM4T(r0, r1, r2, r3, addr)                                           \
    asm volatile("ldmatrix.sync.aligned.m8n8.x4.trans.shared.b16 {%0,%1,%2,%3}, [%4];" \
                 : "=r"(r0), "=r"(r1), "=r"(r2), "=r"(r3) : "r"(addr))

#define MMAF16(d, a, b0, b1)                                                   \
    asm volatile("mma.sync.aligned.m16n8k16.row.col.f32.f16.f16.f32 "          \
                 "{%0,%1,%2,%3}, {%4,%5,%6,%7}, {%8,%9}, {%0,%1,%2,%3};"       \
                 : "+f"((d)[0]), "+f"((d)[1]), "+f"((d)[2]), "+f"((d)[3])      \
                 : "r"((a)[0]), "r"((a)[1]), "r"((a)[2]), "r"((a)[3]),         \
                   "r"(b0), "r"(b1))

#define CP_ASYNC16(dst, src)                                                   \
    asm volatile("cp.async.cg.shared.global [%0], [%1], 16;" :: "r"(dst), "l"(src))
#define CP_COMMIT()  asm volatile("cp.async.commit_group;" ::: "memory")
#define CP_WAIT1()   asm volatile("cp.async.wait_group 1;" ::: "memory")
#define CP_WAIT0()   asm volatile("cp.async.wait_group 0;" ::: "memory")

__device__ __forceinline__ uint32_t pack_h2(float x, float y) {
    __half2 h = __floats2half2_rn(x, y);
    return *(uint32_t*)&h;
}
__device__ __forceinline__ uint32_t pack_h2lo(float x, float y, uint32_t hbits) {
    __half2 h = *(__half2*)&hbits;
    __half2 l = __floats2half2_rn(x - __half2float(h.x),
                                  y - __half2float(h.y));
    return *(uint32_t*)&l;
}

// ============================================================================
// conversion kernels
// ============================================================================
// q/k/v -> single fp16 A operands
__global__ __launch_bounds__(256)
void conv_h3(const float4* __restrict__ q, const float4* __restrict__ k,
             const float4* __restrict__ v,
             __half* __restrict__ a0, __half* __restrict__ a1,
             __half* __restrict__ a2)
{
    const int z = blockIdx.y;
    const float4* src = (z == 0) ? q : (z == 1) ? k : v;
    __half* dst = (z == 0) ? a0 : (z == 1) ? a1 : a2;
    int i = blockIdx.x * 256 + threadIdx.x;
    float4 val = src[i];
    ((uint32_t*)dst)[i * 2 + 0] = pack_h2(val.x, val.y);
    ((uint32_t*)dst)[i * 2 + 1] = pack_h2(val.z, val.w);
}

// W [K][N] -> B[n][k] single fp16 (transpose)
__global__ __launch_bounds__(256)
void conv_wT4(const float* __restrict__ w0, const float* __restrict__ w1,
              const float* __restrict__ w2, const float* __restrict__ w3,
              __half* __restrict__ b0, __half* __restrict__ b1,
              __half* __restrict__ b2, __half* __restrict__ b3)
{
    const int z = blockIdx.z;
    const float* W = (z == 0) ? w0 : (z == 1) ? w1 : (z == 2) ? w2 : w3;
    __half* dst = (z == 0) ? b0 : (z == 1) ? b1 : (z == 2) ? b2 : b3;

    __shared__ float t[32][33];
    int n0 = blockIdx.x * 32, k0 = blockIdx.y * 32;
    int tx = threadIdx.x, ty = threadIdx.y;   // block (32,8)
#pragma unroll
    for (int i = 0; i < 32; i += 8)
        t[ty + i][tx] = W[(size_t)(k0 + ty + i) * DD + n0 + tx];
    __syncthreads();
#pragma unroll
    for (int i = 0; i < 32; i += 8)
        dst[(size_t)(n0 + ty + i) * DD + k0 + tx] = __float2half_rn(t[tx][ty + i]);
}

// ============================================================================
// mma.sync GEMM, templated on #A-terms.
// NT=1: stage = A|B.   NT=2: stage = Ah|Al|B.
// MODE 0: fp32 natural out.  MODE 1: fp16 head-split out, scaled.
// ============================================================================
#define PADK 40
#define TILE_H (128 * PADK)
#define KSTAGES (DD / 32)
#define GEMM_SMEM1 (2 * 2 * TILE_H * 2)   // 40960 B
#define GEMM_SMEM2 (2 * 3 * TILE_H * 2)   // 61440 B

template <int NT, int MODE>
__device__ __forceinline__
void gemm_body(const __half* __restrict__ Ah, const __half* __restrict__ Al,
               const __half* __restrict__ Bs,
               const float* __restrict__ bias, float scale,
               float* __restrict__ OutF, __half* __restrict__ O1)
{
    constexpr int NTILES = NT + 1;
    constexpr int STG_H = NTILES * TILE_H;
    extern __shared__ __half smb[];
    const uint32_t sb = smem_u32(smb);
    const int t = threadIdx.x, wid = t >> 5, lane = t & 31;
    const int m0 = blockIdx.y * 128, n0 = blockIdx.x * 128;
    const int wm = (wid >> 2) * 64, wn = (wid & 3) * 32;

    const __half* srcs[NTILES];
    srcs[0] = Ah + (size_t)m0 * DD;
    if (NT == 2) srcs[1] = Al + (size_t)m0 * DD;
    srcs[NT] = Bs + (size_t)n0 * DD;

    auto issue_stage = [&](int s, int buf) {
        uint32_t base = sb + buf * STG_H * 2;
#pragma unroll
        for (int p = 0; p < NTILES * 2; p++) {
            int j = t + p * 256;              // 16B chunks
            int tile = j >> 9;
            int c = j & 511;
            int row = c >> 2;
            int c16 = c & 3;
            const __half* g = srcs[tile] + (size_t)row * DD + s * 32 + c16 * 8;
            uint32_t d = base + (tile * TILE_H + row * PADK + c16 * 8) * 2;
            CP_ASYNC16(d, g);
        }
        CP_COMMIT();
    };

    float acc[4][4][4];
#pragma unroll
    for (int i = 0; i < 4; i++)
#pragma unroll
        for (int j = 0; j < 4; j++)
#pragma unroll
            for (int r = 0; r < 4; r++) acc[i][j][r] = 0.f;

    issue_stage(0, 0);
    issue_stage(1, 1);

    for (int s = 0; s < KSTAGES; s++) {
        CP_WAIT1();
        __syncthreads();
        const uint32_t base = sb + (s & 1) * STG_H * 2;
#pragma unroll
        for (int kk = 0; kk < 2; kk++) {
            uint32_t ah[4][4], al[4][4], bf[2][4];
#pragma unroll
            for (int i = 0; i < 4; i++) {
                int row = wm + i * 16 + (lane & 15);
                int col = kk * 16 + (lane >> 4) * 8;
                uint32_t ad = base + (row * PADK + col) * 2;
                LDSM4(ah[i][0], ah[i][1], ah[i][2], ah[i][3], ad);
                if (NT == 2)
                    LDSM4(al[i][0], al[i][1], al[i][2], al[i][3], ad + TILE_H * 2);
            }
#pragma unroll
            for (int g = 0; g < 2; g++) {
                int row = wn + g * 16 + ((lane >> 4) & 1) * 8 + (lane & 7);
                int col = kk * 16 + ((lane >> 3) & 1) * 8;
                uint32_t bd = base + (NT * TILE_H + row * PADK + col) * 2;
                LDSM4(bf[g][0], bf[g][1], bf[g][2], bf[g][3], bd);
            }
#pragma unroll
            for (int i = 0; i < 4; i++)
#pragma unroll
                for (int j = 0; j < 4; j++) {
                    int g = j >> 1, o = (j & 1) * 2;
                    MMAF16(acc[i][j], ah[i], bf[g][o], bf[g][o + 1]);
                    if (NT == 2)
                        MMAF16(acc[i][j], al[i], bf[g][o], bf[g][o + 1]);
                }
        }
        __syncthreads();
        if (s + 2 < KSTAGES) issue_stage(s + 2, s & 1);
    }
    CP_WAIT0();

#pragma unroll
    for (int i = 0; i < 4; i++) {
        int grow = m0 + wm + i * 16 + (lane >> 2);
#pragma unroll
        for (int j = 0; j < 4; j++) {
            int gcol = n0 + wn + j * 8 + (lane & 3) * 2;
            float bx = __ldg(&bias[gcol]), by = __ldg(&bias[gcol + 1]);
            float x0 = (acc[i][j][0] + bx) * scale, y0 = (acc[i][j][1] + by) * scale;
            float x1 = (acc[i][j][2] + bx) * scale, y1 = (acc[i][j][3] + by) * scale;
            if (MODE == 0) {
                *(float2*)&OutF[(size_t)grow * DD + gcol] = make_float2(x0, y0);
                *(float2*)&OutF[(size_t)(grow + 8) * DD + gcol] = make_float2(x1, y1);
            } else {
                int h = gcol >> 6, dh = gcol & 63;
                int b0r = grow >> 11, s0 = grow & 2047;
                size_t o0 = (((size_t)(b0r * HH + h) * SS) + s0) * DH + dh;
                int g1 = grow + 8;
                int b1r = g1 >> 11, s1 = g1 & 2047;
                size_t o1 = (((size_t)(b1r * HH + h) * SS) + s1) * DH + dh;
                *(uint32_t*)&O1[o0] = pack_h2(x0, y0);
                *(uint32_t*)&O1[o1] = pack_h2(x1, y1);
            }
        }
    }
}

struct GemmPtrs3 {
    const __half *A[3], *Bs[3];
    const float *bias[3];
    float scale[3];
    __half *O1[3];
};

// fused Q/K/V projections, single-term fp16 A
__global__ __launch_bounds__(256, 2)
void gemm_mma3(GemmPtrs3 p)
{
    const int z = blockIdx.z;
    gemm_body<1, 1>(p.A[z], nullptr, p.Bs[z], p.bias[z], p.scale[z],
                    nullptr, p.O1[z]);
}

// output projection, 2-term fp16 A, fp32 out
__global__ __launch_bounds__(256, 2)
void gemm_mma1(const __half* __restrict__ Ah, const __half* __restrict__ Al,
               const __half* __restrict__ Bs,
               const float* __restrict__ bias, float* __restrict__ OutF)
{
    gemm_body<2, 0>(Ah, Al, Bs, bias, 1.0f, OutF, nullptr);
}

// ============================================================================
// Flash attention, all-fp16, exp2-domain softmax (scale pre-folded into Q).
// ============================================================================
#define APAD 72
#define KV_TILE_H (64 * APAD)
#define AT_STAGE_H (2 * KV_TILE_H)
#define AT_SMEM (2 * AT_STAGE_H * 2)   // 36864 B
#define NKT (SS / 64)

__global__ __launch_bounds__(128, 3)
void attn_mma(const __half* __restrict__ Qf, const __half* __restrict__ Kf,
              const __half* __restrict__ Vf,
              __half* __restrict__ OutH, __half* __restrict__ OutL)
{
    extern __shared__ __half smb[];
    const uint32_t sb = smem_u32(smb);
    const int t = threadIdx.x, wid = t >> 5, lane = t & 31;
    const int bh = blockIdx.y;
    const int q0 = blockIdx.x * 64;
    const int wm = wid * 16;
    const size_t bhoff = (size_t)bh * SS * DH;

    // ---- stage Q tile ----
    {
        const __half* qs = Qf + bhoff + (size_t)q0 * DH;
#pragma unroll
        for (int p = 0; p < 4; p++) {
            int j = t + p * 128;
            int row = j >> 3;
            int c16 = j & 7;
            uint32_t d = sb + (row * APAD + c16 * 8) * 2;
            CP_ASYNC16(d, qs + (size_t)row * DH + c16 * 8);
        }
        CP_COMMIT();
        CP_WAIT0();
        __syncthreads();
    }

    uint32_t qh[4][4];
#pragma unroll
    for (int kk = 0; kk < 4; kk++) {
        int row = wm + (lane & 15);
        int col = kk * 16 + (lane >> 4) * 8;
        uint32_t ad = sb + (row * APAD + col) * 2;
        LDSM4(qh[kk][0], qh[kk][1], qh[kk][2], qh[kk][3], ad);
    }
    __syncthreads();

    const __half* kvsrc[2] = {Kf + bhoff, Vf + bhoff};
    auto issue_kv = [&](int kt, int buf) {
        uint32_t base = sb + buf * AT_STAGE_H * 2;
#pragma unroll
        for (int p = 0; p < 8; p++) {
            int j = t + p * 128;          // 0..1023
            int tile = j >> 9;
            int row = (j >> 3) & 63;
            int c16 = j & 7;
            uint32_t d = base + (tile * KV_TILE_H + row * APAD + c16 * 8) * 2;
            CP_ASYNC16(d, kvsrc[tile] + (size_t)(kt * 64 + row) * DH + c16 * 8);
        }
        CP_COMMIT();
    };

    float o[8][4];
#pragma unroll
    for (int j = 0; j < 8; j++)
#pragma unroll
        for (int r = 0; r < 4; r++) o[j][r] = 0.f;
    float m_i[2] = {-INFINITY, -INFINITY};
    float l_i[2] = {0.f, 0.f};

    issue_kv(0, 0);
    issue_kv(1, 1);

    for (int kt = 0; kt < NKT; kt++) {
        CP_WAIT1();
        __syncthreads();
        const uint32_t base = sb + (kt & 1) * AT_STAGE_H * 2;

        // ---- scores (already in log2 domain: Q pre-scaled) ----
        float s[8][4];
#pragma unroll
        for (int j = 0; j < 8; j++)
#pragma unroll
            for (int r = 0; r < 4; r++) s[j][r] = 0.f;

#pragma unroll
        for (int kk = 0; kk < 4; kk++) {
            uint32_t kf[4][4];
#pragma unroll
            for (int g = 0; g < 4; g++) {
                int row = g * 16 + ((lane >> 4) & 1) * 8 + (lane & 7);
                int col = kk * 16 + ((lane >> 3) & 1) * 8;
                uint32_t kd = base + (row * APAD + col) * 2;
                LDSM4(kf[g][0], kf[g][1], kf[g][2], kf[g][3], kd);
            }
#pragma unroll
            for (int j = 0; j < 8; j++) {
                int g = j >> 1, oo = (j & 1) * 2;
                MMAF16(s[j], qh[kk], kf[g][oo], kf[g][oo + 1]);
            }
        }

        // ---- online softmax, base-2 ----
        float mx[2] = {-INFINITY, -INFINITY};
#pragma unroll
        for (int j = 0; j < 8; j++) {
            mx[0] = fmaxf(mx[0], fmaxf(s[j][0], s[j][1]));
            mx[1] = fmaxf(mx[1], fmaxf(s[j][2], s[j][3]));
        }
#pragma unroll
        for (int r = 0; r < 2; r++) {
            mx[r] = fmaxf(mx[r], __shfl_xor_sync(0xffffffffu, mx[r], 1));
            mx[r] = fmaxf(mx[r], __shfl_xor_sync(0xffffffffu, mx[r], 2));
        }
        float mn[2], corr[2];
#pragma unroll
        for (int r = 0; r < 2; r++) {
            mn[r] = fmaxf(m_i[r], mx[r]);
            corr[r] = ex2f(m_i[r] - mn[r]);
            m_i[r] = mn[r];
        }
        float rs[2] = {0.f, 0.f};
#pragma unroll
        for (int j = 0; j < 8; j++) {
            s[j][0] = ex2f(s[j][0] - mn[0]);
            s[j][1] = ex2f(s[j][1] - mn[0]);
            s[j][2] = ex2f(s[j][2] - mn[1]);
            s[j][3] = ex2f(s[j][3] - mn[1]);
            rs[0] += s[j][0] + s[j][1];
            rs[1] += s[j][2] + s[j][3];
        }
#pragma unroll
        for (int r = 0; r < 2; r++) {
            rs[r] += __shfl_xor_sync(0xffffffffu, rs[r], 1);
            rs[r] += __shfl_xor_sync(0xffffffffu, rs[r], 2);
            l_i[r] = l_i[r] * corr[r] + rs[r];
        }
#pragma unroll
        for (int j = 0; j < 8; j++) {
            o[j][0] *= corr[0]; o[j][1] *= corr[0];
            o[j][2] *= corr[1]; o[j][3] *= corr[1];
        }

        // ---- PV ----
#pragma unroll
        for (int kk = 0; kk < 4; kk++) {
            uint32_t ap[4];
            ap[0] = pack_h2(s[2 * kk][0], s[2 * kk][1]);
            ap[1] = pack_h2(s[2 * kk][2], s[2 * kk][3]);
            ap[2] = pack_h2(s[2 * kk + 1][0], s[2 * kk + 1][1]);
            ap[3] = pack_h2(s[2 * kk + 1][2], s[2 * kk + 1][3]);

            uint32_t vf[4][4];
#pragma unroll
            for (int g = 0; g < 4; g++) {
                int row = kk * 16 + (lane & 15);
                int col = g * 16 + (lane >> 4) * 8;
                uint32_t vd = base + (KV_TILE_H + row * APAD + col) * 2;
                LDSM4T(vf[g][0], vf[g][1], vf[g][2], vf[g][3], vd);
            }
#pragma unroll
            for (int j = 0; j < 8; j++) {
                int g = j >> 1, oo = (j & 1) * 2;
                MMAF16(o[j], ap, vf[g][oo], vf[g][oo + 1]);
            }
        }
        __syncthreads();
        if (kt + 2 < NKT) issue_kv(kt + 2, kt & 1);
    }

    // ---- epilogue: fp16 hi/lo gathered [M][D] for out-projection ----
    const int b = bh >> 4, h = bh & 15;
    const float inv0 = 1.f / l_i[0], inv1 = 1.f / l_i[1];
    const int srow0 = q0 + wm + (lane >> 2);
#pragma unroll
    for (int j = 0; j < 8; j++) {
        int dh = j * 8 + (lane & 3) * 2;
        int kcol = h * 64 + dh;
        size_t o0 = ((size_t)(b * SS + srow0)) * DD + kcol;
        size_t o1 = ((size_t)(b * SS + srow0 + 8)) * DD + kcol;
        float x0 = o[j][0] * inv0, y0 = o[j][1] * inv0;
        float x1 = o[j][2] * inv1, y1 = o[j][3] * inv1;
        uint32_t h0 = pack_h2(x0, y0), h1 = pack_h2(x1, y1);
        *(uint32_t*)&OutH[o0] = h0;
        *(uint32_t*)&OutL[o0] = pack_h2lo(x0, y0, h0);
        *(uint32_t*)&OutH[o1] = h1;
        *(uint32_t*)&OutL[o1] = pack_h2lo(x1, y1, h1);
    }
}

// ============================================================================
// launch
// ============================================================================
extern "C" void kernel_launch(void* const* d_in, const int* in_sizes, int n_in,
                              void* d_out, int out_size)
{
    const float* q   = (const float*)d_in[0];
    const float* k   = (const float*)d_in[1];
    const float* v   = (const float*)d_in[2];
    const float* w_q = (const float*)d_in[3];
    const float* b_q = (const float*)d_in[4];
    const float* w_k = (const float*)d_in[5];
    const float* b_k = (const float*)d_in[6];
    const float* w_v = (const float*)d_in[7];
    const float* b_v = (const float*)d_in[8];
    const float* w_o = (const float*)d_in[9];
    const float* b_o = (const float*)d_in[10];
    float* out = (float*)d_out;

    __half *pA0h, *pA0l, *pAin0, *pAin1, *pAin2;
    __half *pB0, *pB1, *pB2, *pB3, *pQf, *pKf, *pVf;
    cudaGetSymbolAddress((void**)&pA0h, g_A0h);
    cudaGetSymbolAddress((void**)&pA0l, g_A0l);
    cudaGetSymbolAddress((void**)&pAin0, g_Ain0);
    cudaGetSymbolAddress((void**)&pAin1, g_Ain1);
    cudaGetSymbolAddress((void**)&pAin2, g_Ain2);
    cudaGetSymbolAddress((void**)&pB0, g_B0);
    cudaGetSymbolAddress((void**)&pB1, g_B1);
    cudaGetSymbolAddress((void**)&pB2, g_B2);
    cudaGetSymbolAddress((void**)&pB3, g_B3);
    cudaGetSymbolAddress((void**)&pQf, g_Qf);
    cudaGetSymbolAddress((void**)&pKf, g_Kf);
    cudaGetSymbolAddress((void**)&pVf, g_Vf);

    static int attr_set = 0;
    if (!attr_set) {
        cudaFuncSetAttribute(gemm_mma3,
                             cudaFuncAttributeMaxDynamicSharedMemorySize, GEMM_SMEM1);
        cudaFuncSetAttribute(gemm_mma1,
                             cudaFuncAttributeMaxDynamicSharedMemorySize, GEMM_SMEM2);
        cudaFuncSetAttribute(attn_mma,
                             cudaFuncAttributeMaxDynamicSharedMemorySize, AT_SMEM);
        attr_set = 1;
    }

    dim3 gs(MM * DD / 4 / 256, 3);
    conv_h3<<<gs, 256>>>((const float4*)q, (const float4*)k, (const float4*)v,
                         pAin0, pAin1, pAin2);
    dim3 gw(DD / 32, DD / 32, 4);
    conv_wT4<<<gw, dim3(32, 8)>>>(w_q, w_k, w_v, w_o, pB0, pB1, pB2, pB3);

    GemmPtrs3 gp;
    gp.A[0] = pAin0; gp.Bs[0] = pB0; gp.bias[0] = b_q;
    gp.scale[0] = QSCALE; gp.O1[0] = pQf;
    gp.A[1] = pAin1; gp.Bs[1] = pB1; gp.bias[1] = b_k;
    gp.scale[1] = 1.0f; gp.O1[1] = pKf;
    gp.A[2] = pAin2; gp.Bs[2] = pB2; gp.bias[2] = b_v;
    gp.scale[2] = 1.0f; gp.O1[2] = pVf;
    dim3 gg(DD / 128, MM / 128, 3);   // (8, 32, 3)
    gemm_mma3<<<gg, 256, GEMM_SMEM1>>>(gp);

    dim3 ga(SS / 64, BB * HH);        // (32, 32) = 1024 CTAs
    attn_mma<<<ga, 128, AT_SMEM>>>(pQf, pKf, pVf, pA0h, pA0l);

    dim3 g1(DD / 128, MM / 128);
    gemm_mma1<<<g1, 256, GEMM_SMEM2>>>(pA0h, pA0l, pB3, b_o, out);
}

// round 10
// speedup vs baseline: 7.0235x; 1.1097x over previous
#include <cuda_runtime.h>
#include <cuda_bf16.h>
#include <cuda_fp16.h>
#include <math.h>
#include <stdint.h>

// Problem constants
#define BB 2
#define SS 2048
#define DD 1024
#define HH 16
#define DH 64
#define MM (BB * SS)   // 4096 rows

// softmax scale folded into Q projection: 1/sqrt(64) * log2(e)
#define QSCALE 0.18033688011112042f

// -------------------- scratch (allocation-free rule: __device__ globals) ----
// attn-output / out-proj A operand (single fp16)
__device__ __half g_A0[MM * DD];
// q/k/v inputs as single fp16 A operands
__device__ __half g_Ain0[MM * DD];
__device__ __half g_Ain1[MM * DD];
__device__ __half g_Ain2[MM * DD];
// GEMM B operands: single fp16 [N][K]
__device__ __half g_B0[DD * DD];
__device__ __half g_B1[DD * DD];
__device__ __half g_B2[DD * DD];
__device__ __half g_B3[DD * DD];
// attention operands, head-split [B*H][S][DH], single fp16
__device__ __half g_Qf[MM * DD];
__device__ __half g_Kf[MM * DD];
__device__ __half g_Vf[MM * DD];

// ============================================================================
// helpers
// ============================================================================
__device__ __forceinline__ uint32_t smem_u32(const void* p) {
    uint32_t a;
    asm("{ .reg .u64 t; cvta.to.shared.u64 t, %1; cvt.u32.u64 %0, t; }"
        : "=r"(a) : "l"(p));
    return a;
}
__device__ __forceinline__ float ex2f(float x) {
    float y;
    asm("ex2.approx.f32 %0, %1;" : "=f"(y) : "f"(x));
    return y;
}
__device__ __forceinline__ uint32_t ex2_h2(uint32_t a) {
    uint32_t d;
    asm("ex2.approx.f16x2 %0, %1;" : "=r"(d) : "r"(a));
    return d;
}

#define LDSM4(r0, r1, r2, r3, addr)                                            \
    asm volatile("ldmatrix.sync.aligned.m8n8.x4.shared.b16 {%0,%1,%2,%3}, [%4];" \
                 : "=r"(r0), "=r"(r1), "=r"(r2), "=r"(r3) : "r"(addr))
#define LDSM4T(r0, r1, r2, r3, addr)                                           \
    asm volatile("ldmatrix.sync.aligned.m8n8.x4.trans.shared.b16 {%0,%1,%2,%3}, [%4];" \
                 : "=r"(r0), "=r"(r1), "=r"(r2), "=r"(r3) : "r"(addr))

#define MMAF16(d, a, b0, b1)                                                   \
    asm volatile("mma.sync.aligned.m16n8k16.row.col.f32.f16.f16.f32 "          \
                 "{%0,%1,%2,%3}, {%4,%5,%6,%7}, {%8,%9}, {%0,%1,%2,%3};"       \
                 : "+f"((d)[0]), "+f"((d)[1]), "+f"((d)[2]), "+f"((d)[3])      \
                 : "r"((a)[0]), "r"((a)[1]), "r"((a)[2]), "r"((a)[3]),         \
                   "r"(b0), "r"(b1))

#define CP_ASYNC16(dst, src)                                                   \
    asm volatile("cp.async.cg.shared.global [%0], [%1], 16;" :: "r"(dst), "l"(src))
#define CP_COMMIT()  asm volatile("cp.async.commit_group;" ::: "memory")
#define CP_WAIT1()   asm volatile("cp.async.wait_group 1;" ::: "memory")
#define CP_WAIT0()   asm volatile("cp.async.wait_group 0;" ::: "memory")

__device__ __forceinline__ uint32_t pack_h2(float x, float y) {
    __half2 h = __floats2half2_rn(x, y);
    return *(uint32_t*)&h;
}

// ============================================================================
// conversion kernels
// ============================================================================
// q/k/v -> single fp16 A operands
__global__ __launch_bounds__(256)
void conv_h3(const float4* __restrict__ q, const float4* __restrict__ k,
             const float4* __restrict__ v,
             __half* __restrict__ a0, __half* __restrict__ a1,
             __half* __restrict__ a2)
{
    const int z = blockIdx.y;
    const float4* src = (z == 0) ? q : (z == 1) ? k : v;
    __half* dst = (z == 0) ? a0 : (z == 1) ? a1 : a2;
    int i = blockIdx.x * 256 + threadIdx.x;
    float4 val = src[i];
    ((uint32_t*)dst)[i * 2 + 0] = pack_h2(val.x, val.y);
    ((uint32_t*)dst)[i * 2 + 1] = pack_h2(val.z, val.w);
}

// W [K][N] -> B[n][k] single fp16 (transpose)
__global__ __launch_bounds__(256)
void conv_wT4(const float* __restrict__ w0, const float* __restrict__ w1,
              const float* __restrict__ w2, const float* __restrict__ w3,
              __half* __restrict__ b0, __half* __restrict__ b1,
              __half* __restrict__ b2, __half* __restrict__ b3)
{
    const int z = blockIdx.z;
    const float* W = (z == 0) ? w0 : (z == 1) ? w1 : (z == 2) ? w2 : w3;
    __half* dst = (z == 0) ? b0 : (z == 1) ? b1 : (z == 2) ? b2 : b3;

    __shared__ float t[32][33];
    int n0 = blockIdx.x * 32, k0 = blockIdx.y * 32;
    int tx = threadIdx.x, ty = threadIdx.y;   // block (32,8)
#pragma unroll
    for (int i = 0; i < 32; i += 8)
        t[ty + i][tx] = W[(size_t)(k0 + ty + i) * DD + n0 + tx];
    __syncthreads();
#pragma unroll
    for (int i = 0; i < 32; i += 8)
        dst[(size_t)(n0 + ty + i) * DD + k0 + tx] = __float2half_rn(t[tx][ty + i]);
}

// ============================================================================
// mma.sync GEMM, single-term fp16 A.  Stage = A|B.
// MODE 0: fp32 natural out.  MODE 1: fp16 head-split out, scaled.
// ============================================================================
#define PADK 40
#define TILE_H (128 * PADK)
#define KSTAGES (DD / 32)
#define GEMM_SMEM1 (2 * 2 * TILE_H * 2)   // 40960 B

template <int MODE>
__device__ __forceinline__
void gemm_body(const __half* __restrict__ Ah, const __half* __restrict__ Bs,
               const float* __restrict__ bias, float scale,
               float* __restrict__ OutF, __half* __restrict__ O1)
{
    constexpr int STG_H = 2 * TILE_H;
    extern __shared__ __half smb[];
    const uint32_t sb = smem_u32(smb);
    const int t = threadIdx.x, wid = t >> 5, lane = t & 31;
    const int m0 = blockIdx.y * 128, n0 = blockIdx.x * 128;
    const int wm = (wid >> 2) * 64, wn = (wid & 3) * 32;

    const __half* srcs[2] = {Ah + (size_t)m0 * DD, Bs + (size_t)n0 * DD};

    auto issue_stage = [&](int s, int buf) {
        uint32_t base = sb + buf * STG_H * 2;
#pragma unroll
        for (int p = 0; p < 4; p++) {
            int j = t + p * 256;              // 16B chunks
            int tile = j >> 9;
            int c = j & 511;
            int row = c >> 2;
            int c16 = c & 3;
            const __half* g = srcs[tile] + (size_t)row * DD + s * 32 + c16 * 8;
            uint32_t d = base + (tile * TILE_H + row * PADK + c16 * 8) * 2;
            CP_ASYNC16(d, g);
        }
        CP_COMMIT();
    };

    float acc[4][4][4];
#pragma unroll
    for (int i = 0; i < 4; i++)
#pragma unroll
        for (int j = 0; j < 4; j++)
#pragma unroll
            for (int r = 0; r < 4; r++) acc[i][j][r] = 0.f;

    issue_stage(0, 0);
    issue_stage(1, 1);

    for (int s = 0; s < KSTAGES; s++) {
        CP_WAIT1();
        __syncthreads();
        const uint32_t base = sb + (s & 1) * STG_H * 2;
#pragma unroll
        for (int kk = 0; kk < 2; kk++) {
            uint32_t ah[4][4], bf[2][4];
#pragma unroll
            for (int i = 0; i < 4; i++) {
                int row = wm + i * 16 + (lane & 15);
                int col = kk * 16 + (lane >> 4) * 8;
                uint32_t ad = base + (row * PADK + col) * 2;
                LDSM4(ah[i][0], ah[i][1], ah[i][2], ah[i][3], ad);
            }
#pragma unroll
            for (int g = 0; g < 2; g++) {
                int row = wn + g * 16 + ((lane >> 4) & 1) * 8 + (lane & 7);
                int col = kk * 16 + ((lane >> 3) & 1) * 8;
                uint32_t bd = base + (TILE_H + row * PADK + col) * 2;
                LDSM4(bf[g][0], bf[g][1], bf[g][2], bf[g][3], bd);
            }
#pragma unroll
            for (int i = 0; i < 4; i++)
#pragma unroll
                for (int j = 0; j < 4; j++) {
                    int g = j >> 1, o = (j & 1) * 2;
                    MMAF16(acc[i][j], ah[i], bf[g][o], bf[g][o + 1]);
                }
        }
        __syncthreads();
        if (s + 2 < KSTAGES) issue_stage(s + 2, s & 1);
    }
    CP_WAIT0();

#pragma unroll
    for (int i = 0; i < 4; i++) {
        int grow = m0 + wm + i * 16 + (lane >> 2);
#pragma unroll
        for (int j = 0; j < 4; j++) {
            int gcol = n0 + wn + j * 8 + (lane & 3) * 2;
            float bx = __ldg(&bias[gcol]), by = __ldg(&bias[gcol + 1]);
            float x0 = (acc[i][j][0] + bx) * scale, y0 = (acc[i][j][1] + by) * scale;
            float x1 = (acc[i][j][2] + bx) * scale, y1 = (acc[i][j][3] + by) * scale;
            if (MODE == 0) {
                *(float2*)&OutF[(size_t)grow * DD + gcol] = make_float2(x0, y0);
                *(float2*)&OutF[(size_t)(grow + 8) * DD + gcol] = make_float2(x1, y1);
            } else {
                int h = gcol >> 6, dh = gcol & 63;
                int b0r = grow >> 11, s0 = grow & 2047;
                size_t o0 = (((size_t)(b0r * HH + h) * SS) + s0) * DH + dh;
                int g1 = grow + 8;
                int b1r = g1 >> 11, s1 = g1 & 2047;
                size_t o1 = (((size_t)(b1r * HH + h) * SS) + s1) * DH + dh;
                *(uint32_t*)&O1[o0] = pack_h2(x0, y0);
                *(uint32_t*)&O1[o1] = pack_h2(x1, y1);
            }
        }
    }
}

struct GemmPtrs3 {
    const __half *A[3], *Bs[3];
    const float *bias[3];
    float scale[3];
    __half *O1[3];
};

// fused Q/K/V projections
__global__ __launch_bounds__(256, 2)
void gemm_mma3(GemmPtrs3 p)
{
    const int z = blockIdx.z;
    gemm_body<1>(p.A[z], p.Bs[z], p.bias[z], p.scale[z], nullptr, p.O1[z]);
}

// output projection, fp32 out
__global__ __launch_bounds__(256, 2)
void gemm_mma1(const __half* __restrict__ Ah, const __half* __restrict__ Bs,
               const float* __restrict__ bias, float* __restrict__ OutF)
{
    gemm_body<0>(Ah, Bs, bias, 1.0f, OutF, nullptr);
}

// ============================================================================
// Flash attention, all-fp16, exp2-domain softmax.
// NEW: f16x2 exponent (packed P direct), row-sum via ones-MMA.
// ============================================================================
#define APAD 72
#define KV_TILE_H (64 * APAD)
#define AT_STAGE_H (2 * KV_TILE_H)
#define AT_SMEM (2 * AT_STAGE_H * 2)   // 36864 B
#define NKT (SS / 64)
#define ONES_H2 0x3C003C00u

__global__ __launch_bounds__(128, 3)
void attn_mma(const __half* __restrict__ Qf, const __half* __restrict__ Kf,
              const __half* __restrict__ Vf, __half* __restrict__ OutH)
{
    extern __shared__ __half smb[];
    const uint32_t sb = smem_u32(smb);
    const int t = threadIdx.x, wid = t >> 5, lane = t & 31;
    const int bh = blockIdx.y;
    const int q0 = blockIdx.x * 64;
    const int wm = wid * 16;
    const size_t bhoff = (size_t)bh * SS * DH;

    // ---- stage Q tile ----
    {
        const __half* qs = Qf + bhoff + (size_t)q0 * DH;
#pragma unroll
        for (int p = 0; p < 4; p++) {
            int j = t + p * 128;
            int row = j >> 3;
            int c16 = j & 7;
            uint32_t d = sb + (row * APAD + c16 * 8) * 2;
            CP_ASYNC16(d, qs + (size_t)row * DH + c16 * 8);
        }
        CP_COMMIT();
        CP_WAIT0();
        __syncthreads();
    }

    uint32_t qh[4][4];
#pragma unroll
    for (int kk = 0; kk < 4; kk++) {
        int row = wm + (lane & 15);
        int col = kk * 16 + (lane >> 4) * 8;
        uint32_t ad = sb + (row * APAD + col) * 2;
        LDSM4(qh[kk][0], qh[kk][1], qh[kk][2], qh[kk][3], ad);
    }
    __syncthreads();

    const __half* kvsrc[2] = {Kf + bhoff, Vf + bhoff};
    auto issue_kv = [&](int kt, int buf) {
        uint32_t base = sb + buf * AT_STAGE_H * 2;
#pragma unroll
        for (int p = 0; p < 8; p++) {
            int j = t + p * 128;          // 0..1023
            int tile = j >> 9;
            int row = (j >> 3) & 63;
            int c16 = j & 7;
            uint32_t d = base + (tile * KV_TILE_H + row * APAD + c16 * 8) * 2;
            CP_ASYNC16(d, kvsrc[tile] + (size_t)(kt * 64 + row) * DH + c16 * 8);
        }
        CP_COMMIT();
    };

    float o[8][4];
#pragma unroll
    for (int j = 0; j < 8; j++)
#pragma unroll
        for (int r = 0; r < 4; r++) o[j][r] = 0.f;
    float m_i[2] = {-INFINITY, -INFINITY};
    float l_i[2] = {0.f, 0.f};

    issue_kv(0, 0);
    issue_kv(1, 1);

    for (int kt = 0; kt < NKT; kt++) {
        CP_WAIT1();
        __syncthreads();
        const uint32_t base = sb + (kt & 1) * AT_STAGE_H * 2;

        // ---- scores (log2 domain: scale folded into Q projection) ----
        float s[8][4];
#pragma unroll
        for (int j = 0; j < 8; j++)
#pragma unroll
            for (int r = 0; r < 4; r++) s[j][r] = 0.f;

#pragma unroll
        for (int kk = 0; kk < 4; kk++) {
            uint32_t kf[4][4];
#pragma unroll
            for (int g = 0; g < 4; g++) {
                int row = g * 16 + ((lane >> 4) & 1) * 8 + (lane & 7);
                int col = kk * 16 + ((lane >> 3) & 1) * 8;
                uint32_t kd = base + (row * APAD + col) * 2;
                LDSM4(kf[g][0], kf[g][1], kf[g][2], kf[g][3], kd);
            }
#pragma unroll
            for (int j = 0; j < 8; j++) {
                int g = j >> 1, oo = (j & 1) * 2;
                MMAF16(s[j], qh[kk], kf[g][oo], kf[g][oo + 1]);
            }
        }

        // ---- online softmax, base-2, f16x2 exponent ----
        float mx[2] = {-INFINITY, -INFINITY};
#pragma unroll
        for (int j = 0; j < 8; j++) {
            mx[0] = fmaxf(mx[0], fmaxf(s[j][0], s[j][1]));
            mx[1] = fmaxf(mx[1], fmaxf(s[j][2], s[j][3]));
        }
#pragma unroll
        for (int r = 0; r < 2; r++) {
            mx[r] = fmaxf(mx[r], __shfl_xor_sync(0xffffffffu, mx[r], 1));
            mx[r] = fmaxf(mx[r], __shfl_xor_sync(0xffffffffu, mx[r], 2));
        }
        float mn[2], corr[2];
#pragma unroll
        for (int r = 0; r < 2; r++) {
            mn[r] = fmaxf(m_i[r], mx[r]);
            corr[r] = ex2f(m_i[r] - mn[r]);
            m_i[r] = mn[r];
        }
        // P packed: subtract max in f32, pack, exp2 in f16x2
        uint32_t p2[16];
#pragma unroll
        for (int j = 0; j < 8; j++) {
            p2[j * 2 + 0] = ex2_h2(pack_h2(s[j][0] - mn[0], s[j][1] - mn[0]));
            p2[j * 2 + 1] = ex2_h2(pack_h2(s[j][2] - mn[1], s[j][3] - mn[1]));
        }
#pragma unroll
        for (int j = 0; j < 8; j++) {
            o[j][0] *= corr[0]; o[j][1] *= corr[0];
            o[j][2] *= corr[1]; o[j][3] *= corr[1];
        }

        // ---- PV + row-sum via ones-MMA ----
        float dsum[4] = {0.f, 0.f, 0.f, 0.f};
#pragma unroll
        for (int kk = 0; kk < 4; kk++) {
            uint32_t ap[4];
            ap[0] = p2[(2 * kk) * 2 + 0];
            ap[1] = p2[(2 * kk) * 2 + 1];
            ap[2] = p2[(2 * kk + 1) * 2 + 0];
            ap[3] = p2[(2 * kk + 1) * 2 + 1];

            uint32_t vf[4][4];
#pragma unroll
            for (int g = 0; g < 4; g++) {
                int row = kk * 16 + (lane & 15);
                int col = g * 16 + (lane >> 4) * 8;
                uint32_t vd = base + (KV_TILE_H + row * APAD + col) * 2;
                LDSM4T(vf[g][0], vf[g][1], vf[g][2], vf[g][3], vd);
            }
#pragma unroll
            for (int j = 0; j < 8; j++) {
                int g = j >> 1, oo = (j & 1) * 2;
                MMAF16(o[j], ap, vf[g][oo], vf[g][oo + 1]);
            }
            MMAF16(dsum, ap, ONES_H2, ONES_H2);
        }
        l_i[0] = l_i[0] * corr[0] + dsum[0];
        l_i[1] = l_i[1] * corr[1] + dsum[2];

        __syncthreads();
        if (kt + 2 < NKT) issue_kv(kt + 2, kt & 1);
    }

    // ---- epilogue: single fp16 gathered [M][D] for out-projection ----
    const int b = bh >> 4, h = bh & 15;
    const float inv0 = 1.f / l_i[0], inv1 = 1.f / l_i[1];
    const int srow0 = q0 + wm + (lane >> 2);
#pragma unroll
    for (int j = 0; j < 8; j++) {
        int dh = j * 8 + (lane & 3) * 2;
        int kcol = h * 64 + dh;
        size_t o0 = ((size_t)(b * SS + srow0)) * DD + kcol;
        size_t o1 = ((size_t)(b * SS + srow0 + 8)) * DD + kcol;
        *(uint32_t*)&OutH[o0] = pack_h2(o[j][0] * inv0, o[j][1] * inv0);
        *(uint32_t*)&OutH[o1] = pack_h2(o[j][2] * inv1, o[j][3] * inv1);
    }
}

// ============================================================================
// launch
// ============================================================================
extern "C" void kernel_launch(void* const* d_in, const int* in_sizes, int n_in,
                              void* d_out, int out_size)
{
    const float* q   = (const float*)d_in[0];
    const float* k   = (const float*)d_in[1];
    const float* v   = (const float*)d_in[2];
    const float* w_q = (const float*)d_in[3];
    const float* b_q = (const float*)d_in[4];
    const float* w_k = (const float*)d_in[5];
    const float* b_k = (const float*)d_in[6];
    const float* w_v = (const float*)d_in[7];
    const float* b_v = (const float*)d_in[8];
    const float* w_o = (const float*)d_in[9];
    const float* b_o = (const float*)d_in[10];
    float* out = (float*)d_out;

    __half *pA0, *pAin0, *pAin1, *pAin2;
    __half *pB0, *pB1, *pB2, *pB3, *pQf, *pKf, *pVf;
    cudaGetSymbolAddress((void**)&pA0, g_A0);
    cudaGetSymbolAddress((void**)&pAin0, g_Ain0);
    cudaGetSymbolAddress((void**)&pAin1, g_Ain1);
    cudaGetSymbolAddress((void**)&pAin2, g_Ain2);
    cudaGetSymbolAddress((void**)&pB0, g_B0);
    cudaGetSymbolAddress((void**)&pB1, g_B1);
    cudaGetSymbolAddress((void**)&pB2, g_B2);
    cudaGetSymbolAddress((void**)&pB3, g_B3);
    cudaGetSymbolAddress((void**)&pQf, g_Qf);
    cudaGetSymbolAddress((void**)&pKf, g_Kf);
    cudaGetSymbolAddress((void**)&pVf, g_Vf);

    static int attr_set = 0;
    if (!attr_set) {
        cudaFuncSetAttribute(gemm_mma3,
                             cudaFuncAttributeMaxDynamicSharedMemorySize, GEMM_SMEM1);
        cudaFuncSetAttribute(gemm_mma1,
                             cudaFuncAttributeMaxDynamicSharedMemorySize, GEMM_SMEM1);
        cudaFuncSetAttribute(attn_mma,
                             cudaFuncAttributeMaxDynamicSharedMemorySize, AT_SMEM);
        attr_set = 1;
    }

    dim3 gs(MM * DD / 4 / 256, 3);
    conv_h3<<<gs, 256>>>((const float4*)q, (const float4*)k, (const float4*)v,
                         pAin0, pAin1, pAin2);
    dim3 gw(DD / 32, DD / 32, 4);
    conv_wT4<<<gw, dim3(32, 8)>>>(w_q, w_k, w_v, w_o, pB0, pB1, pB2, pB3);

    GemmPtrs3 gp;
    gp.A[0] = pAin0; gp.Bs[0] = pB0; gp.bias[0] = b_q;
    gp.scale[0] = QSCALE; gp.O1[0] = pQf;
    gp.A[1] = pAin1; gp.Bs[1] = pB1; gp.bias[1] = b_k;
    gp.scale[1] = 1.0f; gp.O1[1] = pKf;
    gp.A[2] = pAin2; gp.Bs[2] = pB2; gp.bias[2] = b_v;
    gp.scale[2] = 1.0f; gp.O1[2] = pVf;
    dim3 gg(DD / 128, MM / 128, 3);   // (8, 32, 3)
    gemm_mma3<<<gg, 256, GEMM_SMEM1>>>(gp);

    dim3 ga(SS / 64, BB * HH);        // (32, 32) = 1024 CTAs
    attn_mma<<<ga, 128, AT_SMEM>>>(pQf, pKf, pVf, pA0);

    dim3 g1(DD / 128, MM / 128);
    gemm_mma1<<<g1, 256, GEMM_SMEM1>>>(pA0, pB3, b_o, out);
}